// round 8
// baseline (speedup 1.0000x reference)
#include <cuda_runtime.h>
#include <cstdint>
#include <math.h>

#define NN 4
#define CC 512
#define DD 768
#define HH 12
#define EE 20
#define MMENT 4
#define PP 380
#define NP 1520
#define LL 97
#define DIM2 1536
#define DIM3 2304
#define DIM4 3072
#define KBIL 49152
#define NEGV (-1e30f)

// ---------------- static device scratch ----------------
__device__ float g_eemb[NN*EE*MMENT*DD];
__device__ float g_eatt[NN*EE*MMENT*CC];
__device__ float g_glob[NN*EE*DD];
__device__ float g_A[NN*EE*DD];
__device__ float g_B[NN*EE*DD];
__device__ float g_edge[NN*EE*EE*DD];
__device__ float g_q[NP*DIM2];
__device__ float g_pa[NP*CC];
__device__ float g_hcat[NP*DIM3];
__device__ float g_tcat[NP*DIM3];
__device__ float g_qW[NP*DIM4];
__device__ float g_pathraw[NP*DIM4];
__device__ float g_hs[NP*DD];
__device__ float g_ts[NP*DD];
__device__ float g_part[4*NP*DD];
// transposed (K-major) weights for mma B operand
__device__ float g_wT_att[DIM4*DIM2];
__device__ float g_wT_path[DD*DIM4];
__device__ float g_wT_head[DD*DIM3];
__device__ float g_wT_tail[DD*DIM3];
__device__ float g_wT_bil[128*KBIL];   // rows 97..127 zero

// ---------------- helpers ----------------
__device__ __forceinline__ uint32_t f2tf32(float f) {
    uint32_t r;
    asm("cvt.rna.tf32.f32 %0, %1;" : "=r"(r) : "f"(f));
    return r;
}
__device__ __forceinline__ void mma_tf32(float* d, uint32_t a0, uint32_t a1,
                                         uint32_t a2, uint32_t a3,
                                         uint32_t b0, uint32_t b1)
{
    asm volatile(
        "mma.sync.aligned.m16n8k8.row.col.f32.tf32.tf32.f32 "
        "{%0,%1,%2,%3}, {%4,%5,%6,%7}, {%8,%9}, {%0,%1,%2,%3};"
        : "+f"(d[0]), "+f"(d[1]), "+f"(d[2]), "+f"(d[3])
        : "r"(a0), "r"(a1), "r"(a2), "r"(a3), "r"(b0), "r"(b1));
}

// gather one 128x32 A chunk + 128x32 B chunk into mma-fragment order (registers)
__device__ __forceinline__ void gatherAB(
    const float* __restrict__ A, int lda, int M, int m0,
    const float* __restrict__ BT, int ldbt, int n0,
    int k0, int tid, float (&av)[4][4], float (&bv)[8][2])
{
    #pragma unroll
    for (int t = 0; t < 4; t++) {
        int combo = tid + t*256;            // mt(3b) ks(2b) lane(5b)
        int mt = combo >> 7, ks = (combo >> 5) & 3, ln = combo & 31;
        int gg = ln >> 2, cc = ln & 3;
        int r0 = m0 + mt*16 + gg, r1 = r0 + 8;
        int c0 = k0 + ks*8 + cc;
        const float* Ar0 = A + (size_t)r0*lda + c0;
        const float* Ar1 = A + (size_t)r1*lda + c0;
        av[t][0] = (r0 < M) ? Ar0[0] : 0.f;
        av[t][1] = (r1 < M) ? Ar1[0] : 0.f;
        av[t][2] = (r0 < M) ? Ar0[4] : 0.f;
        av[t][3] = (r1 < M) ? Ar1[4] : 0.f;
    }
    #pragma unroll
    for (int t = 0; t < 8; t++) {
        int combo = tid + t*256;            // nt(4b) ks(2b) lane(5b)
        int nt = combo >> 7, ks = (combo >> 5) & 3, ln = combo & 31;
        int gg = ln >> 2, cc = ln & 3;
        int n = n0 + nt*8 + gg;
        const float* Br = BT + (size_t)n*ldbt + k0 + ks*8 + cc;
        bv[t][0] = Br[0];
        bv[t][1] = Br[4];
    }
}

__device__ __forceinline__ void storeAB(uint32_t* sA, uint32_t* sB, int tid,
                                        const float (&av)[4][4], const float (&bv)[8][2])
{
    #pragma unroll
    for (int t = 0; t < 4; t++) {
        int combo = tid + t*256;
        uint4 v = make_uint4(f2tf32(av[t][0]), f2tf32(av[t][1]),
                             f2tf32(av[t][2]), f2tf32(av[t][3]));
        *(uint4*)(sA + combo*4) = v;
    }
    #pragma unroll
    for (int t = 0; t < 8; t++) {
        int combo = tid + t*256;
        uint2 v = make_uint2(f2tf32(bv[t][0]), f2tf32(bv[t][1]));
        *(uint2*)(sB + combo*2) = v;
    }
}

__device__ __forceinline__ void computeChunk(const uint32_t* sA, const uint32_t* sB,
                                             int wm, int wn, int lane,
                                             float (&acc)[4][4][4])
{
    #pragma unroll
    for (int ks = 0; ks < 4; ks++) {
        uint32_t b[4][2];
        #pragma unroll
        for (int nt = 0; nt < 4; nt++) {
            uint2 bb = *(const uint2*)(sB + (((wn*4 + nt)*4 + ks)*32 + lane)*2);
            b[nt][0] = bb.x; b[nt][1] = bb.y;
        }
        #pragma unroll
        for (int mt = 0; mt < 4; mt++) {
            uint4 aa = *(const uint4*)(sA + (((wm*4 + mt)*4 + ks)*32 + lane)*4);
            #pragma unroll
            for (int nt = 0; nt < 4; nt++)
                mma_tf32(acc[mt][nt], aa.x, aa.y, aa.z, aa.w, b[nt][0], b[nt][1]);
        }
    }
}

// ================ tf32 warp-mma GEMM: dst = act(A[M,K] @ BT[N,K]^T + bias) ================
// grid: (N/128, ceil(M/128), Sr*nbatch).  z: b = z/Sr, s = z%Sr.
// If b==1, uses A2/BT2/dst1b (merged second GEMM). part slot index = z.
__global__ void __launch_bounds__(256) wgemm(
    int M, int nchunks, int Sr,
    const float* __restrict__ A, int lda,
    const float* __restrict__ BT, int ldbt,
    const float* __restrict__ A2,
    const float* __restrict__ BT2,
    float* __restrict__ dst1, int ld1,
    const float* __restrict__ bias, int relu,
    float* __restrict__ dst2, int ld2,
    float* __restrict__ part, int Mtot, int Nn)
{
    extern __shared__ uint32_t sm[];
    uint32_t* sA = sm;            // 2 x 4096
    uint32_t* sB = sm + 8192;     // 2 x 4096
    int tid = threadIdx.x;
    int lane = tid & 31, wid = tid >> 5;
    int wm = wid >> 2, wn = wid & 3;
    int g = lane >> 2, c = lane & 3;
    int m0 = blockIdx.y*128, n0 = blockIdx.x*128;
    int z = blockIdx.z;
    int s = z % Sr, b = z / Sr;
    const float* Ause  = b ? A2  : A;
    const float* BTuse = b ? BT2 : BT;
    int kbase = s*nchunks*32;

    float acc[4][4][4];
    #pragma unroll
    for (int i = 0; i < 4; i++)
        #pragma unroll
        for (int j = 0; j < 4; j++)
            #pragma unroll
            for (int k = 0; k < 4; k++) acc[i][j][k] = 0.f;

    float av[4][4]; float bv[8][2];
    gatherAB(Ause, lda, M, m0, BTuse, ldbt, n0, kbase, tid, av, bv);
    for (int kc = 0; kc < nchunks; kc++) {
        int buf = kc & 1;
        storeAB(sA + buf*4096, sB + buf*4096, tid, av, bv);
        __syncthreads();
        if (kc + 1 < nchunks)
            gatherAB(Ause, lda, M, m0, BTuse, ldbt, n0, kbase + (kc+1)*32, tid, av, bv);
        computeChunk(sA + buf*4096, sB + buf*4096, wm, wn, lane, acc);
        __syncthreads();
    }

    #pragma unroll
    for (int mt = 0; mt < 4; mt++) {
        int r0 = m0 + wm*64 + mt*16 + g;
        int r1 = r0 + 8;
        #pragma unroll
        for (int nt = 0; nt < 4; nt++) {
            int c0 = n0 + wn*32 + nt*8 + 2*c;
            if (part) {
                float* p0 = part + ((size_t)z*Mtot + r0)*Nn + c0;
                float* p1 = part + ((size_t)z*Mtot + r1)*Nn + c0;
                if (r0 < M) { p0[0] = acc[mt][nt][0]; p0[1] = acc[mt][nt][1]; }
                if (r1 < M) { p1[0] = acc[mt][nt][2]; p1[1] = acc[mt][nt][3]; }
            } else {
                float b0 = bias ? bias[c0] : 0.f;
                float b1 = bias ? bias[c0+1] : 0.f;
                float v0 = acc[mt][nt][0] + b0, v1 = acc[mt][nt][1] + b1;
                float v2 = acc[mt][nt][2] + b0, v3 = acc[mt][nt][3] + b1;
                if (relu) { v0=fmaxf(v0,0.f); v1=fmaxf(v1,0.f); v2=fmaxf(v2,0.f); v3=fmaxf(v3,0.f); }
                if (r0 < M) {
                    dst1[(size_t)r0*ld1 + c0] = v0; dst1[(size_t)r0*ld1 + c0+1] = v1;
                    if (dst2) { dst2[(size_t)r0*ld2 + c0] = v0; dst2[(size_t)r0*ld2 + c0+1] = v1; }
                }
                if (r1 < M) {
                    dst1[(size_t)r1*ld1 + c0] = v2; dst1[(size_t)r1*ld1 + c0+1] = v3;
                    if (dst2) { dst2[(size_t)r1*ld2 + c0] = v2; dst2[(size_t)r1*ld2 + c0+1] = v3; }
                }
            }
        }
    }
}

// ===== bilinear: part[kb] = (hs_kb ⊗ ts_kb)[128-row tile] @ WbilT[kb], A built on the fly =====
__global__ void __launch_bounds__(256) wbil(const float* __restrict__ BT)
{
    extern __shared__ uint32_t sm[];
    uint32_t* sA = sm;             // 2 x 4096
    uint32_t* sB = sm + 8192;      // 2 x 4096
    float* hsf = (float*)(sm + 16384);          // [64][129]
    float* tsf = (float*)(sm + 16384 + 8256);   // [64][129]
    int tid = threadIdx.x;
    int lane = tid & 31, wid = tid >> 5;
    int wm = wid >> 2, wn = wid & 3;
    int g = lane >> 2, c = lane & 3;
    int m0 = blockIdx.x*128;
    int kb = blockIdx.y;

    for (int idx = tid; idx < 64*128; idx += 256) {
        int i = idx >> 7, r = idx & 127;
        int rg = m0 + r;
        hsf[i*129 + r] = (rg < NP) ? g_hs[(size_t)rg*DD + kb*64 + i] : 0.f;
        tsf[i*129 + r] = (rg < NP) ? g_ts[(size_t)rg*DD + kb*64 + i] : 0.f;
    }
    __syncthreads();

    float acc[4][4][4];
    #pragma unroll
    for (int i = 0; i < 4; i++)
        #pragma unroll
        for (int j = 0; j < 4; j++)
            #pragma unroll
            for (int k = 0; k < 4; k++) acc[i][j][k] = 0.f;

    float av[4][4]; float bv[8][2];
    const float* Bb = BT + (size_t)kb*4096;

    auto gatherBil = [&](int kc) {
        int k0 = kc*32;
        #pragma unroll
        for (int t = 0; t < 4; t++) {
            int combo = tid + t*256;
            int mt = combo >> 7, ks = (combo >> 5) & 3, ln = combo & 31;
            int gg = ln >> 2, cc = ln & 3;
            int kl0 = k0 + ks*8 + cc;
            int ii = kl0 >> 6, j0 = kl0 & 63, j1 = (kl0 + 4) & 63;
            int r0 = mt*16 + gg, r1 = r0 + 8;
            float h0 = hsf[ii*129 + r0], h1 = hsf[ii*129 + r1];
            av[t][0] = h0 * tsf[j0*129 + r0];
            av[t][1] = h1 * tsf[j0*129 + r1];
            av[t][2] = h0 * tsf[j1*129 + r0];
            av[t][3] = h1 * tsf[j1*129 + r1];
        }
        #pragma unroll
        for (int t = 0; t < 8; t++) {
            int combo = tid + t*256;
            int nt = combo >> 7, ks = (combo >> 5) & 3, ln = combo & 31;
            int gg = ln >> 2, cc = ln & 3;
            int n = nt*8 + gg;
            const float* Br = Bb + (size_t)n*KBIL + k0 + ks*8 + cc;
            bv[t][0] = Br[0];
            bv[t][1] = Br[4];
        }
    };

    gatherBil(0);
    for (int kc = 0; kc < 128; kc++) {
        int buf = kc & 1;
        storeAB(sA + buf*4096, sB + buf*4096, tid, av, bv);
        __syncthreads();
        if (kc + 1 < 128) gatherBil(kc + 1);
        computeChunk(sA + buf*4096, sB + buf*4096, wm, wn, lane, acc);
        __syncthreads();
    }

    #pragma unroll
    for (int mt = 0; mt < 4; mt++) {
        int r0 = m0 + wm*64 + mt*16 + g;
        int r1 = r0 + 8;
        #pragma unroll
        for (int nt = 0; nt < 4; nt++) {
            int c0 = wn*32 + nt*8 + 2*c;
            #pragma unroll
            for (int u = 0; u < 2; u++) {
                int col = c0 + u;
                if (col < LL) {
                    if (r0 < NP) g_part[((size_t)kb*NP + r0)*LL + col] = acc[mt][nt][u];
                    if (r1 < NP) g_part[((size_t)kb*NP + r1)*LL + col] = acc[mt][nt][2+u];
                }
            }
        }
    }
}

// ================= transpose: out[c][r] = in[r][c]; rows c in [C,Cout) -> 0 =================
__global__ void ktrans(const float* __restrict__ in, int R, int C, int Cout,
                       float* __restrict__ out)
{
    __shared__ float t[32][33];
    int c0 = blockIdx.x*32, r0 = blockIdx.y*32;
    int tx = threadIdx.x, ty = threadIdx.y;
    #pragma unroll
    for (int j = 0; j < 32; j += 8) {
        int r = r0 + ty + j, c = c0 + tx;
        t[ty+j][tx] = (r < R && c < C) ? in[(size_t)r*C + c] : 0.f;
    }
    __syncthreads();
    #pragma unroll
    for (int j = 0; j < 32; j += 8) {
        int c = c0 + ty + j, r = r0 + tx;
        if (c < Cout && r < R) out[(size_t)c*R + r] = t[tx][ty+j];
    }
}

// ---------------- K1: gather ----------------
__global__ void k_gather(const float* __restrict__ seq, const float* __restrict__ att,
                         const int* __restrict__ ms)
{
    int ne = blockIdx.x;
    int n  = ne / EE;
    int tid = threadIdx.x;
    for (int m = 0; m < MMENT; m++) {
        int pos = ms[ne*MMENT + m] + 1;
        const float* srow = seq + ((size_t)n*CC + pos)*DD;
        float* erow = g_eemb + ((size_t)ne*MMENT + m)*DD;
        for (int d = tid; d < DD; d += blockDim.x) erow[d] = srow[d];
        float* arow = g_eatt + ((size_t)ne*MMENT + m)*CC;
        for (int c = tid; c < CC; c += blockDim.x) {
            float s = 0.f;
            #pragma unroll
            for (int h = 0; h < HH; h++)
                s += att[(((size_t)n*HH + h)*CC + pos)*CC + c];
            arow[c] = s * (1.0f/HH);
        }
    }
    __syncthreads();
    for (int d = tid; d < DD; d += blockDim.x) {
        float x0 = g_eemb[((size_t)ne*MMENT+0)*DD+d];
        float x1 = g_eemb[((size_t)ne*MMENT+1)*DD+d];
        float x2 = g_eemb[((size_t)ne*MMENT+2)*DD+d];
        float x3 = g_eemb[((size_t)ne*MMENT+3)*DD+d];
        float mx = fmaxf(fmaxf(x0,x1), fmaxf(x2,x3));
        float s = expf(x0-mx)+expf(x1-mx)+expf(x2-mx)+expf(x3-mx);
        g_glob[(size_t)ne*DD + d] = mx + logf(s);
    }
}

// ---------------- K3: edge ----------------
__global__ void k_edge(const float* __restrict__ bm)
{
    int idx = blockIdx.x*blockDim.x + threadIdx.x;
    const int total = NN*EE*EE*DD;
    if (idx >= total) return;
    int d = idx % DD;
    int v = (idx / DD) % EE;
    int u = (idx / (DD*EE)) % EE;
    int n = idx / (DD*EE*EE);
    float val = g_A[((size_t)n*EE+u)*DD+d] + g_B[((size_t)n*EE+v)*DD+d] + bm[d];
    g_edge[idx] = fmaxf(val, 0.f);
}

// ---------------- K4: pair attention ----------------
__global__ void k_pair(const int* __restrict__ hts, const int* __restrict__ ms)
{
    int r = blockIdx.x;
    int n = r / PP;
    int h = hts[r*2 + 0];
    int t = hts[r*2 + 1];
    __shared__ int   s_ph[MMENT], s_pt[MMENT];
    __shared__ float s_phatt[MMENT], s_ptatt[MMENT];
    __shared__ float s_red[256];
    int tid = threadIdx.x;
    if (tid < MMENT) {
        s_ph[tid] = ms[((size_t)n*EE+h)*MMENT + tid] + 1;
        s_pt[tid] = ms[((size_t)n*EE+t)*MMENT + tid] + 1;
    }
    __syncthreads();
    if (tid < 2*MMENT) {
        int m2 = tid & (MMENT-1);
        float s = 0.f;
        if (tid < MMENT) {
            for (int m1 = 0; m1 < MMENT; m1++)
                s += g_eatt[((size_t)(n*EE+h)*MMENT+m1)*CC + s_pt[m2]];
            s_phatt[m2] = s * (1.f/MMENT);
        } else {
            for (int m1 = 0; m1 < MMENT; m1++)
                s += g_eatt[((size_t)(n*EE+t)*MMENT+m1)*CC + s_ph[m2]];
            s_ptatt[m2] = s * (1.f/MMENT);
        }
    }
    __syncthreads();
    if (tid == 0) {
        float sh = 1e-5f, st = 1e-5f;
        for (int m = 0; m < MMENT; m++) { sh += s_phatt[m]; st += s_ptatt[m]; }
        float ih = 1.f/sh, it = 1.f/st;
        for (int m = 0; m < MMENT; m++) { s_phatt[m] *= ih; s_ptatt[m] *= it; }
    }
    __syncthreads();
    for (int d = tid; d < DD; d += blockDim.x) {
        float nh = 0.f, nt = 0.f;
        #pragma unroll
        for (int m = 0; m < MMENT; m++) {
            nh += s_ptatt[m]*g_eemb[((size_t)(n*EE+h)*MMENT+m)*DD + d];
            nt += s_phatt[m]*g_eemb[((size_t)(n*EE+t)*MMENT+m)*DD + d];
        }
        g_hcat[(size_t)r*DIM3 + d] = nh;
        g_tcat[(size_t)r*DIM3 + d] = nt;
        g_q[(size_t)r*DIM2 + d]       = nh;
        g_q[(size_t)r*DIM2 + DD + d]  = nt;
    }
    float local = 0.f;
    for (int c = tid; c < CC; c += blockDim.x) {
        float na = 0.f, ta = 0.f;
        #pragma unroll
        for (int m = 0; m < MMENT; m++) {
            na += s_ptatt[m]*g_eatt[((size_t)(n*EE+h)*MMENT+m)*CC + c];
            ta += s_phatt[m]*g_eatt[((size_t)(n*EE+t)*MMENT+m)*CC + c];
        }
        float v = na*ta;
        g_pa[(size_t)r*CC + c] = v;
        local += v;
    }
    s_red[tid] = local;
    __syncthreads();
    for (int off = 128; off > 0; off >>= 1) {
        if (tid < off) s_red[tid] += s_red[tid+off];
        __syncthreads();
    }
    float inv = 1.f/(s_red[0] + 1e-5f);
    for (int c = tid; c < CC; c += blockDim.x)
        g_pa[(size_t)r*CC + c] *= inv;
}

// ---------------- fp32 SGEMM (Wm1/Wm2, rs) ----------------
__global__ void __launch_bounds__(256) sgemm(
    int M, int Nn, int Kc, int S,
    const float* __restrict__ A, int lda, long long sA,
    const float* __restrict__ B, int ldb, long long sB,
    float* __restrict__ part, int Mtot)
{
    int b = blockIdx.z / S;
    int s = blockIdx.z % S;
    const float* Ab = A + (size_t)b*sA + (size_t)s*Kc;
    const float* Bb = B + (size_t)b*sB + (size_t)s*Kc*ldb;
    int m0 = blockIdx.y*128, n0 = blockIdx.x*128;
    __shared__ float As[8][128];
    __shared__ float Bs[8][128];
    int tid = threadIdx.x;
    int arow = tid >> 1, ak = (tid & 1)*4;
    int bk = tid >> 5,  bn = (tid & 31)*4;
    int tx = tid & 15,  ty = tid >> 4;
    float acc[8][8];
    #pragma unroll
    for (int i = 0; i < 8; i++)
        #pragma unroll
        for (int j = 0; j < 8; j++) acc[i][j] = 0.f;
    for (int k0 = 0; k0 < Kc; k0 += 8) {
        float4 av = make_float4(0.f,0.f,0.f,0.f);
        if (m0 + arow < M)
            av = *(const float4*)(Ab + (size_t)(m0+arow)*lda + k0 + ak);
        float4 bvv = *(const float4*)(Bb + (size_t)(k0+bk)*ldb + n0 + bn);
        __syncthreads();
        As[ak+0][arow] = av.x; As[ak+1][arow] = av.y;
        As[ak+2][arow] = av.z; As[ak+3][arow] = av.w;
        *(float4*)&Bs[bk][bn] = bvv;
        __syncthreads();
        #pragma unroll
        for (int kk = 0; kk < 8; kk++) {
            float a[8], bb[8];
            *(float4*)(a)    = *(const float4*)&As[kk][ty*8];
            *(float4*)(a+4)  = *(const float4*)&As[kk][ty*8+4];
            *(float4*)(bb)   = *(const float4*)&Bs[kk][tx*8];
            *(float4*)(bb+4) = *(const float4*)&Bs[kk][tx*8+4];
            #pragma unroll
            for (int i = 0; i < 8; i++)
                #pragma unroll
                for (int j = 0; j < 8; j++)
                    acc[i][j] += a[i]*bb[j];
        }
    }
    float* pbase = part + ((size_t)s*Mtot + (size_t)b*M)*Nn;
    #pragma unroll
    for (int i = 0; i < 8; i++) {
        int r = m0 + ty*8 + i;
        if (r < M) {
            float* prow = pbase + (size_t)r*Nn + n0 + tx*8;
            *(float4*)(prow)   = make_float4(acc[i][0],acc[i][1],acc[i][2],acc[i][3]);
            *(float4*)(prow+4) = make_float4(acc[i][4],acc[i][5],acc[i][6],acc[i][7]);
        }
    }
}

__global__ void reduce_ep(const float* __restrict__ part, int S, int Mtot, int Nn,
                          const float* __restrict__ bias, int dorelu,
                          float* __restrict__ dst1, int ld1,
                          float* __restrict__ dst2, int ld2)
{
    int idx = blockIdx.x*blockDim.x + threadIdx.x;
    if (idx >= Mtot*Nn) return;
    int r = idx / Nn, c = idx % Nn;
    float v = 0.f;
    for (int s = 0; s < S; s++)
        v += part[((size_t)s*Mtot + r)*Nn + c];
    if (bias) v += bias[c];
    if (dorelu) v = fmaxf(v, 0.f);
    dst1[(size_t)r*ld1 + c] = v;
    if (dst2) dst2[(size_t)r*ld2 + c] = v;
}

// ---------------- K7: score + masked softmax + path ----------------
__global__ void k_scorepath(const int* __restrict__ hts, const float* __restrict__ battp)
{
    int r = blockIdx.x;
    int n = r / PP;
    int h = hts[r*2 + 0];
    int t = hts[r*2 + 1];
    __shared__ float s_q[DIM4];
    __shared__ float s_score[EE];
    __shared__ float s_aw[EE];
    int tid = threadIdx.x;
    for (int i = tid; i < DIM4; i += blockDim.x)
        s_q[i] = g_qW[(size_t)r*DIM4 + i];
    __syncthreads();
    int warp = tid >> 5, lane = tid & 31;
    float batt = battp[0];
    for (int v = warp; v < EE; v += 8) {
        const float* e1 = g_edge + ((size_t)((n*EE+h)*EE + v))*DD;
        const float* e2 = g_edge + ((size_t)((n*EE+v)*EE + t))*DD;
        const float* e3 = g_edge + ((size_t)((n*EE+t)*EE + v))*DD;
        const float* e4 = g_edge + ((size_t)((n*EE+v)*EE + h))*DD;
        float s = 0.f;
        for (int d = lane; d < DD; d += 32)
            s += s_q[d]*e1[d] + s_q[DD+d]*e2[d] + s_q[2*DD+d]*e3[d] + s_q[3*DD+d]*e4[d];
        #pragma unroll
        for (int off = 16; off; off >>= 1)
            s += __shfl_down_sync(0xffffffffu, s, off);
        if (lane == 0) s_score[v] = s + batt;
    }
    __syncthreads();
    if (tid == 0) {
        float mx = -1e38f;
        for (int v = 0; v < EE; v++) {
            float sc = (v == h || v == t) ? NEGV : s_score[v];
            s_score[v] = sc;
            mx = fmaxf(mx, sc);
        }
        float sum = 0.f;
        for (int v = 0; v < EE; v++) {
            float e = expf(s_score[v] - mx);
            s_aw[v] = e;
            sum += e;
        }
        float inv = 1.f/sum;
        for (int v = 0; v < EE; v++) s_aw[v] *= inv;
    }
    __syncthreads();
    for (int idx = tid; idx < DIM4; idx += blockDim.x) {
        int kk = idx / DD, d = idx % DD;
        const float* ep;
        size_t strideV;
        if (kk == 0)      { ep = g_edge + ((size_t)((n*EE+h)*EE))*DD + d;   strideV = DD; }
        else if (kk == 1) { ep = g_edge + ((size_t)(n*EE)*EE + t)*DD + d;   strideV = (size_t)EE*DD; }
        else if (kk == 2) { ep = g_edge + ((size_t)((n*EE+t)*EE))*DD + d;   strideV = DD; }
        else              { ep = g_edge + ((size_t)(n*EE)*EE + h)*DD + d;   strideV = (size_t)EE*DD; }
        float acc = 0.f;
        #pragma unroll 4
        for (int v = 0; v < EE; v++)
            acc += s_aw[v]*ep[(size_t)v*strideV];
        g_pathraw[(size_t)r*DIM4 + idx] = acc;
    }
}

__global__ void k_bilred(const float* __restrict__ bbil, float* __restrict__ out)
{
    int idx = blockIdx.x*blockDim.x + threadIdx.x;
    if (idx >= NP*LL) return;
    int r = idx / LL, l = idx % LL;
    float v = bbil[l];
    #pragma unroll
    for (int k = 0; k < 12; k++)
        v += g_part[((size_t)k*NP + r)*LL + l];
    out[idx] = v;
}

// ---------------- launcher ----------------
static float* symaddr(const void* sym)
{
    void* p = nullptr;
    cudaGetSymbolAddress(&p, sym);
    return (float*)p;
}

extern "C" void kernel_launch(void* const* d_in, const int* in_sizes, int n_in,
                              void* d_out, int out_size)
{
    const float* seq   = (const float*)d_in[0];
    const float* att   = (const float*)d_in[1];
    const int*   ms    = (const int*)  d_in[2];
    const int*   hts   = (const int*)  d_in[3];
    const float* Wm1   = (const float*)d_in[4];
    const float* Wm2   = (const float*)d_in[5];
    const float* bm    = (const float*)d_in[6];
    const float* Watt  = (const float*)d_in[7];
    const float* batt  = (const float*)d_in[8];
    const float* Wpath = (const float*)d_in[9];
    const float* bpath = (const float*)d_in[10];
    const float* Whead = (const float*)d_in[11];
    const float* bhead = (const float*)d_in[12];
    const float* Wtail = (const float*)d_in[13];
    const float* btail = (const float*)d_in[14];
    const float* Wbil  = (const float*)d_in[15];
    const float* bbil  = (const float*)d_in[16];
    float* out = (float*)d_out;

    float* glob   = symaddr(g_glob);
    float* gA     = symaddr(g_A);
    float* gB     = symaddr(g_B);
    float* q      = symaddr(g_q);
    float* pa     = symaddr(g_pa);
    float* hcat   = symaddr(g_hcat);
    float* tcat   = symaddr(g_tcat);
    float* qW     = symaddr(g_qW);
    float* praw   = symaddr(g_pathraw);
    float* hs     = symaddr(g_hs);
    float* ts     = symaddr(g_ts);
    float* part   = symaddr(g_part);
    float* wTatt  = symaddr(g_wT_att);
    float* wTpath = symaddr(g_wT_path);
    float* wThead = symaddr(g_wT_head);
    float* wTtail = symaddr(g_wT_tail);
    float* wTbil  = symaddr(g_wT_bil);

    const int SMEM_WG = 65536;
    const int SMEM_WB = 65536 + 2*8256*4;
    cudaFuncSetAttribute(wgemm, cudaFuncAttributeMaxDynamicSharedMemorySize, SMEM_WG);
    cudaFuncSetAttribute(wbil,  cudaFuncAttributeMaxDynamicSharedMemorySize, SMEM_WB);

    // --- stage 1 (ordered so launch #5 = the big qW wgemm for ncu) ---
    k_gather<<<NN*EE, 256>>>(seq, att, ms);                                     // 0
    k_pair<<<NP, 256>>>(hts, ms);                                               // 1
    ktrans<<<dim3(DIM4/32, DIM2/32), dim3(32,8)>>>(Watt, DIM2, DIM4, DIM4, wTatt); // 2
    sgemm<<<dim3(6,1,12), 256>>>(NN*EE, DD, 64, 12, glob, DD, 0, Wm1, DD, 0,
                                 part, NN*EE);                                  // 3
    reduce_ep<<<(NN*EE*DD+255)/256, 256>>>(part, 12, NN*EE, DD, nullptr, 0,
                                           gA, DD, nullptr, 0);                 // 4
    // 5: qW = q @ Watt  (tf32 mma, direct epilogue)  <-- ncu profiles this
    wgemm<<<dim3(24,12,1), 256, SMEM_WG>>>(NP, 48, 1, q, DIM2, wTatt, DIM2,
                                           nullptr, nullptr,
                                           qW, DIM4, nullptr, 0, nullptr, 0,
                                           nullptr, 0, 0);
    sgemm<<<dim3(6,1,12), 256>>>(NN*EE, DD, 64, 12, glob, DD, 0, Wm2, DD, 0,
                                 part, NN*EE);                                  // 6
    reduce_ep<<<(NN*EE*DD+255)/256, 256>>>(part, 12, NN*EE, DD, nullptr, 0,
                                           gB, DD, nullptr, 0);                 // 7
    k_edge<<<(NN*EE*EE*DD+255)/256, 256>>>(bm);                                 // 8

    // rs = pa @ seq (fp32, batched, split-K 4)
    sgemm<<<dim3(6,3,NN*4), 256>>>(PP, DD, CC/4, 4, pa, CC, (long long)PP*CC,
                                   seq, DD, (long long)CC*DD, part, NP);
    reduce_ep<<<(NP*DD+255)/256, 256>>>(part, 4, NP, DD, nullptr, 0,
                                        hcat + DD, DIM3, tcat + DD, DIM3);

    // score/softmax/path
    k_scorepath<<<NP, 256>>>(hts, batt);

    // path = relu(pathraw @ Wpath + bpath)
    ktrans<<<dim3(DD/32, DIM4/32), dim3(32,8)>>>(Wpath, DIM4, DD, DD, wTpath);
    wgemm<<<dim3(6,12,2), 256, SMEM_WG>>>(NP, 48, 2, praw, DIM4, wTpath, DIM4,
                                          nullptr, nullptr,
                                          nullptr, 0, nullptr, 0, nullptr, 0,
                                          part, NP, DD);
    reduce_ep<<<(NP*DD+255)/256, 256>>>(part, 2, NP, DD, bpath, 1,
                                        hcat + 2*DD, DIM3, tcat + 2*DD, DIM3);

    // hs / ts projections — merged batched launch (z: b=z/2 selects head/tail, s=z%2)
    ktrans<<<dim3(DD/32, DIM3/32), dim3(32,8)>>>(Whead, DIM3, DD, DD, wThead);
    ktrans<<<dim3(DD/32, DIM3/32), dim3(32,8)>>>(Wtail, DIM3, DD, DD, wTtail);
    wgemm<<<dim3(6,12,4), 256, SMEM_WG>>>(NP, 36, 2, hcat, DIM3, wThead, DIM3,
                                          tcat, wTtail,
                                          nullptr, 0, nullptr, 0, nullptr, 0,
                                          part, NP, DD);
    reduce_ep<<<(NP*DD+255)/256, 256>>>(part, 2, NP, DD, bhead, 1, hs, DD, nullptr, 0);
    reduce_ep<<<(NP*DD+255)/256, 256>>>(part + (size_t)2*NP*DD, 2, NP, DD, btail, 1,
                                        ts, DD, nullptr, 0);

    // bilinear head (tf32 mma, fused outer-product A)
    ktrans<<<dim3(4, KBIL/32), dim3(32,8)>>>(Wbil, KBIL, LL, 128, wTbil);
    wbil<<<dim3(12,12), 256, SMEM_WB>>>(wTbil);
    k_bilred<<<(NP*LL+255)/256, 256>>>(bbil, out);
}

// round 9
// speedup vs baseline: 1.5293x; 1.5293x over previous
#include <cuda_runtime.h>
#include <cstdint>
#include <math.h>

#define NN 4
#define CC 512
#define DD 768
#define HH 12
#define EE 20
#define MMENT 4
#define PP 380
#define NP 1520
#define LL 97
#define DIM2 1536
#define DIM3 2304
#define DIM4 3072
#define KBIL 49152
#define NEGV (-1e30f)

// ---------------- static device scratch ----------------
__device__ float g_eemb[NN*EE*MMENT*DD];
__device__ float g_eatt[NN*EE*MMENT*CC];
__device__ float g_glob[NN*EE*DD];
__device__ float g_A[NN*EE*DD];
__device__ float g_B[NN*EE*DD];
__device__ float g_edge[NN*EE*EE*DD];
__device__ float g_q[NP*DIM2];
__device__ float g_pa[NP*CC];
__device__ float g_hcat[NP*DIM3];
__device__ float g_tcat[NP*DIM3];
__device__ float g_qW[NP*DIM4];
__device__ float g_pathraw[NP*DIM4];
__device__ float g_hs[NP*DD];
__device__ float g_ts[NP*DD];
__device__ float g_part[4*NP*DD];
// transposed (K-major) weights for mma B operand
__device__ float g_wT_att[DIM4*DIM2];
__device__ float g_wT_path[DD*DIM4];
__device__ float g_wT_head[DD*DIM3];
__device__ float g_wT_tail[DD*DIM3];
__device__ float g_wT_bil[128*KBIL];   // rows 97..127 zero

// ---------------- helpers ----------------
__device__ __forceinline__ uint32_t f2tf32(float f) {
    uint32_t r;
    asm("cvt.rna.tf32.f32 %0, %1;" : "=r"(r) : "f"(f));
    return r;
}
__device__ __forceinline__ void mma_tf32(float* d, uint32_t a0, uint32_t a1,
                                         uint32_t a2, uint32_t a3,
                                         uint32_t b0, uint32_t b1)
{
    asm volatile(
        "mma.sync.aligned.m16n8k8.row.col.f32.tf32.tf32.f32 "
        "{%0,%1,%2,%3}, {%4,%5,%6,%7}, {%8,%9}, {%0,%1,%2,%3};"
        : "+f"(d[0]), "+f"(d[1]), "+f"(d[2]), "+f"(d[3])
        : "r"(a0), "r"(a1), "r"(a2), "r"(a3), "r"(b0), "r"(b1));
}

// gather one 128x32 A chunk + 128x32 B chunk into mma-fragment order (registers)
__device__ __forceinline__ void gatherAB(
    const float* __restrict__ A, int lda, int M, int m0,
    const float* __restrict__ BT, int ldbt, int n0,
    int k0, int tid, float (&av)[4][4], float (&bv)[8][2])
{
    #pragma unroll
    for (int t = 0; t < 4; t++) {
        int combo = tid + t*256;            // mt(3b) ks(2b) lane(5b)
        int mt = combo >> 7, ks = (combo >> 5) & 3, ln = combo & 31;
        int gg = ln >> 2, cc = ln & 3;
        int r0 = m0 + mt*16 + gg, r1 = r0 + 8;
        int c0 = k0 + ks*8 + cc;
        const float* Ar0 = A + (size_t)r0*lda + c0;
        const float* Ar1 = A + (size_t)r1*lda + c0;
        av[t][0] = (r0 < M) ? Ar0[0] : 0.f;
        av[t][1] = (r1 < M) ? Ar1[0] : 0.f;
        av[t][2] = (r0 < M) ? Ar0[4] : 0.f;
        av[t][3] = (r1 < M) ? Ar1[4] : 0.f;
    }
    #pragma unroll
    for (int t = 0; t < 8; t++) {
        int combo = tid + t*256;            // nt(4b) ks(2b) lane(5b)
        int nt = combo >> 7, ks = (combo >> 5) & 3, ln = combo & 31;
        int gg = ln >> 2, cc = ln & 3;
        int n = n0 + nt*8 + gg;
        const float* Br = BT + (size_t)n*ldbt + k0 + ks*8 + cc;
        bv[t][0] = Br[0];
        bv[t][1] = Br[4];
    }
}

__device__ __forceinline__ void storeAB(uint32_t* sA, uint32_t* sB, int tid,
                                        const float (&av)[4][4], const float (&bv)[8][2])
{
    #pragma unroll
    for (int t = 0; t < 4; t++) {
        int combo = tid + t*256;
        uint4 v = make_uint4(f2tf32(av[t][0]), f2tf32(av[t][1]),
                             f2tf32(av[t][2]), f2tf32(av[t][3]));
        *(uint4*)(sA + combo*4) = v;
    }
    #pragma unroll
    for (int t = 0; t < 8; t++) {
        int combo = tid + t*256;
        uint2 v = make_uint2(f2tf32(bv[t][0]), f2tf32(bv[t][1]));
        *(uint2*)(sB + combo*2) = v;
    }
}

__device__ __forceinline__ void computeChunk(const uint32_t* sA, const uint32_t* sB,
                                             int wm, int wn, int lane,
                                             float (&acc)[4][4][4])
{
    #pragma unroll
    for (int ks = 0; ks < 4; ks++) {
        uint32_t b[4][2];
        #pragma unroll
        for (int nt = 0; nt < 4; nt++) {
            uint2 bb = *(const uint2*)(sB + (((wn*4 + nt)*4 + ks)*32 + lane)*2);
            b[nt][0] = bb.x; b[nt][1] = bb.y;
        }
        #pragma unroll
        for (int mt = 0; mt < 4; mt++) {
            uint4 aa = *(const uint4*)(sA + (((wm*4 + mt)*4 + ks)*32 + lane)*4);
            #pragma unroll
            for (int nt = 0; nt < 4; nt++)
                mma_tf32(acc[mt][nt], aa.x, aa.y, aa.z, aa.w, b[nt][0], b[nt][1]);
        }
    }
}

// ================ tf32 warp-mma GEMM: dst = act(A[M,K] @ BT[N,K]^T + bias) ================
// grid: (N/128, ceil(M/128), Sr*nbatch).  z: b = z/Sr, s = z%Sr.
// If b==1, uses A2/BT2. part slot index = z.
// NOTE: single __syncthreads per k-chunk is race-free with 2 buffers:
// compute(kc) precedes sync(kc+1) in program order, so store(kc+2) to the
// same buffer cannot begin until all compute(kc) completed.
__global__ void __launch_bounds__(256) wgemm(
    int M, int nchunks, int Sr,
    const float* __restrict__ A, int lda,
    const float* __restrict__ BT, int ldbt,
    const float* __restrict__ A2,
    const float* __restrict__ BT2,
    float* __restrict__ dst1, int ld1,
    const float* __restrict__ bias, int relu,
    float* __restrict__ dst2, int ld2,
    float* __restrict__ part, int Mtot, int Nn)
{
    extern __shared__ uint32_t sm[];
    uint32_t* sA = sm;            // 2 x 4096
    uint32_t* sB = sm + 8192;     // 2 x 4096
    int tid = threadIdx.x;
    int lane = tid & 31, wid = tid >> 5;
    int wm = wid >> 2, wn = wid & 3;
    int g = lane >> 2, c = lane & 3;
    int m0 = blockIdx.y*128, n0 = blockIdx.x*128;
    int z = blockIdx.z;
    int s = z % Sr, b = z / Sr;
    const float* Ause  = b ? A2  : A;
    const float* BTuse = b ? BT2 : BT;
    int kbase = s*nchunks*32;

    float acc[4][4][4];
    #pragma unroll
    for (int i = 0; i < 4; i++)
        #pragma unroll
        for (int j = 0; j < 4; j++)
            #pragma unroll
            for (int k = 0; k < 4; k++) acc[i][j][k] = 0.f;

    float av[4][4]; float bv[8][2];
    gatherAB(Ause, lda, M, m0, BTuse, ldbt, n0, kbase, tid, av, bv);
    for (int kc = 0; kc < nchunks; kc++) {
        int buf = kc & 1;
        storeAB(sA + buf*4096, sB + buf*4096, tid, av, bv);
        __syncthreads();
        if (kc + 1 < nchunks)
            gatherAB(Ause, lda, M, m0, BTuse, ldbt, n0, kbase + (kc+1)*32, tid, av, bv);
        computeChunk(sA + buf*4096, sB + buf*4096, wm, wn, lane, acc);
    }

    #pragma unroll
    for (int mt = 0; mt < 4; mt++) {
        int r0 = m0 + wm*64 + mt*16 + g;
        int r1 = r0 + 8;
        #pragma unroll
        for (int nt = 0; nt < 4; nt++) {
            int c0 = n0 + wn*32 + nt*8 + 2*c;
            if (part) {
                float* p0 = part + ((size_t)z*Mtot + r0)*Nn + c0;
                float* p1 = part + ((size_t)z*Mtot + r1)*Nn + c0;
                if (r0 < M) { p0[0] = acc[mt][nt][0]; p0[1] = acc[mt][nt][1]; }
                if (r1 < M) { p1[0] = acc[mt][nt][2]; p1[1] = acc[mt][nt][3]; }
            } else {
                float b0 = bias ? bias[c0] : 0.f;
                float b1 = bias ? bias[c0+1] : 0.f;
                float v0 = acc[mt][nt][0] + b0, v1 = acc[mt][nt][1] + b1;
                float v2 = acc[mt][nt][2] + b0, v3 = acc[mt][nt][3] + b1;
                if (relu) { v0=fmaxf(v0,0.f); v1=fmaxf(v1,0.f); v2=fmaxf(v2,0.f); v3=fmaxf(v3,0.f); }
                if (r0 < M) {
                    dst1[(size_t)r0*ld1 + c0] = v0; dst1[(size_t)r0*ld1 + c0+1] = v1;
                    if (dst2) { dst2[(size_t)r0*ld2 + c0] = v0; dst2[(size_t)r0*ld2 + c0+1] = v1; }
                }
                if (r1 < M) {
                    dst1[(size_t)r1*ld1 + c0] = v2; dst1[(size_t)r1*ld1 + c0+1] = v3;
                    if (dst2) { dst2[(size_t)r1*ld2 + c0] = v2; dst2[(size_t)r1*ld2 + c0+1] = v3; }
                }
            }
        }
    }
}

// ===== bilinear: part[kb] = (hs_kb ⊗ ts_kb)[128-row tile] @ WbilT[kb], A built on the fly =====
__global__ void __launch_bounds__(256) wbil(const float* __restrict__ BT)
{
    extern __shared__ uint32_t sm[];
    uint32_t* sA = sm;             // 2 x 4096
    uint32_t* sB = sm + 8192;      // 2 x 4096
    float* hsf = (float*)(sm + 16384);          // [64][129]
    float* tsf = (float*)(sm + 16384 + 8256);   // [64][129]
    int tid = threadIdx.x;
    int lane = tid & 31, wid = tid >> 5;
    int wm = wid >> 2, wn = wid & 3;
    int g = lane >> 2, c = lane & 3;
    int m0 = blockIdx.x*128;
    int kb = blockIdx.y;

    for (int idx = tid; idx < 64*128; idx += 256) {
        int i = idx >> 7, r = idx & 127;
        int rg = m0 + r;
        hsf[i*129 + r] = (rg < NP) ? g_hs[(size_t)rg*DD + kb*64 + i] : 0.f;
        tsf[i*129 + r] = (rg < NP) ? g_ts[(size_t)rg*DD + kb*64 + i] : 0.f;
    }
    __syncthreads();

    float acc[4][4][4];
    #pragma unroll
    for (int i = 0; i < 4; i++)
        #pragma unroll
        for (int j = 0; j < 4; j++)
            #pragma unroll
            for (int k = 0; k < 4; k++) acc[i][j][k] = 0.f;

    float av[4][4]; float bv[8][2];
    const float* Bb = BT + (size_t)kb*4096;

    auto gatherBil = [&](int kc) {
        int k0 = kc*32;
        #pragma unroll
        for (int t = 0; t < 4; t++) {
            int combo = tid + t*256;
            int mt = combo >> 7, ks = (combo >> 5) & 3, ln = combo & 31;
            int gg = ln >> 2, cc = ln & 3;
            int kl0 = k0 + ks*8 + cc;
            int ii = kl0 >> 6, j0 = kl0 & 63, j1 = (kl0 + 4) & 63;
            int r0 = mt*16 + gg, r1 = r0 + 8;
            float h0 = hsf[ii*129 + r0], h1 = hsf[ii*129 + r1];
            av[t][0] = h0 * tsf[j0*129 + r0];
            av[t][1] = h1 * tsf[j0*129 + r1];
            av[t][2] = h0 * tsf[j1*129 + r0];
            av[t][3] = h1 * tsf[j1*129 + r1];
        }
        #pragma unroll
        for (int t = 0; t < 8; t++) {
            int combo = tid + t*256;
            int nt = combo >> 7, ks = (combo >> 5) & 3, ln = combo & 31;
            int gg = ln >> 2, cc = ln & 3;
            int n = nt*8 + gg;
            const float* Br = Bb + (size_t)n*KBIL + k0 + ks*8 + cc;
            bv[t][0] = Br[0];
            bv[t][1] = Br[4];
        }
    };

    gatherBil(0);
    for (int kc = 0; kc < 128; kc++) {
        int buf = kc & 1;
        storeAB(sA + buf*4096, sB + buf*4096, tid, av, bv);
        __syncthreads();
        if (kc + 1 < 128) gatherBil(kc + 1);
        computeChunk(sA + buf*4096, sB + buf*4096, wm, wn, lane, acc);
    }

    #pragma unroll
    for (int mt = 0; mt < 4; mt++) {
        int r0 = m0 + wm*64 + mt*16 + g;
        int r1 = r0 + 8;
        #pragma unroll
        for (int nt = 0; nt < 4; nt++) {
            int c0 = wn*32 + nt*8 + 2*c;
            #pragma unroll
            for (int u = 0; u < 2; u++) {
                int col = c0 + u;
                if (col < LL) {
                    if (r0 < NP) g_part[((size_t)kb*NP + r0)*LL + col] = acc[mt][nt][u];
                    if (r1 < NP) g_part[((size_t)kb*NP + r1)*LL + col] = acc[mt][nt][2+u];
                }
            }
        }
    }
}

// ================= transpose: out[c][r] = in[r][c]; rows c in [C,Cout) -> 0 =================
__global__ void ktrans(const float* __restrict__ in, int R, int C, int Cout,
                       float* __restrict__ out)
{
    __shared__ float t[32][33];
    int c0 = blockIdx.x*32, r0 = blockIdx.y*32;
    int tx = threadIdx.x, ty = threadIdx.y;
    #pragma unroll
    for (int j = 0; j < 32; j += 8) {
        int r = r0 + ty + j, c = c0 + tx;
        t[ty+j][tx] = (r < R && c < C) ? in[(size_t)r*C + c] : 0.f;
    }
    __syncthreads();
    #pragma unroll
    for (int j = 0; j < 32; j += 8) {
        int c = c0 + ty + j, r = r0 + tx;
        if (c < Cout && r < R) out[(size_t)c*R + r] = t[tx][ty+j];
    }
}

// ---------------- K1: gather ----------------
__global__ void k_gather(const float* __restrict__ seq, const float* __restrict__ att,
                         const int* __restrict__ ms)
{
    int ne = blockIdx.x;
    int n  = ne / EE;
    int tid = threadIdx.x;
    for (int m = 0; m < MMENT; m++) {
        int pos = ms[ne*MMENT + m] + 1;
        const float* srow = seq + ((size_t)n*CC + pos)*DD;
        float* erow = g_eemb + ((size_t)ne*MMENT + m)*DD;
        for (int d = tid; d < DD; d += blockDim.x) erow[d] = srow[d];
        float* arow = g_eatt + ((size_t)ne*MMENT + m)*CC;
        for (int c = tid; c < CC; c += blockDim.x) {
            float s = 0.f;
            #pragma unroll
            for (int h = 0; h < HH; h++)
                s += att[(((size_t)n*HH + h)*CC + pos)*CC + c];
            arow[c] = s * (1.0f/HH);
        }
    }
    __syncthreads();
    for (int d = tid; d < DD; d += blockDim.x) {
        float x0 = g_eemb[((size_t)ne*MMENT+0)*DD+d];
        float x1 = g_eemb[((size_t)ne*MMENT+1)*DD+d];
        float x2 = g_eemb[((size_t)ne*MMENT+2)*DD+d];
        float x3 = g_eemb[((size_t)ne*MMENT+3)*DD+d];
        float mx = fmaxf(fmaxf(x0,x1), fmaxf(x2,x3));
        float s = expf(x0-mx)+expf(x1-mx)+expf(x2-mx)+expf(x3-mx);
        g_glob[(size_t)ne*DD + d] = mx + logf(s);
    }
}

// ---------------- K3: edge ----------------
__global__ void k_edge(const float* __restrict__ bm)
{
    int idx = blockIdx.x*blockDim.x + threadIdx.x;
    const int total = NN*EE*EE*DD;
    if (idx >= total) return;
    int d = idx % DD;
    int v = (idx / DD) % EE;
    int u = (idx / (DD*EE)) % EE;
    int n = idx / (DD*EE*EE);
    float val = g_A[((size_t)n*EE+u)*DD+d] + g_B[((size_t)n*EE+v)*DD+d] + bm[d];
    g_edge[idx] = fmaxf(val, 0.f);
}

// ---------------- K4: pair attention ----------------
__global__ void k_pair(const int* __restrict__ hts, const int* __restrict__ ms)
{
    int r = blockIdx.x;
    int n = r / PP;
    int h = hts[r*2 + 0];
    int t = hts[r*2 + 1];
    __shared__ int   s_ph[MMENT], s_pt[MMENT];
    __shared__ float s_phatt[MMENT], s_ptatt[MMENT];
    __shared__ float s_red[256];
    int tid = threadIdx.x;
    if (tid < MMENT) {
        s_ph[tid] = ms[((size_t)n*EE+h)*MMENT + tid] + 1;
        s_pt[tid] = ms[((size_t)n*EE+t)*MMENT + tid] + 1;
    }
    __syncthreads();
    if (tid < 2*MMENT) {
        int m2 = tid & (MMENT-1);
        float s = 0.f;
        if (tid < MMENT) {
            for (int m1 = 0; m1 < MMENT; m1++)
                s += g_eatt[((size_t)(n*EE+h)*MMENT+m1)*CC + s_pt[m2]];
            s_phatt[m2] = s * (1.f/MMENT);
        } else {
            for (int m1 = 0; m1 < MMENT; m1++)
                s += g_eatt[((size_t)(n*EE+t)*MMENT+m1)*CC + s_ph[m2]];
            s_ptatt[m2] = s * (1.f/MMENT);
        }
    }
    __syncthreads();
    if (tid == 0) {
        float sh = 1e-5f, st = 1e-5f;
        for (int m = 0; m < MMENT; m++) { sh += s_phatt[m]; st += s_ptatt[m]; }
        float ih = 1.f/sh, it = 1.f/st;
        for (int m = 0; m < MMENT; m++) { s_phatt[m] *= ih; s_ptatt[m] *= it; }
    }
    __syncthreads();
    for (int d = tid; d < DD; d += blockDim.x) {
        float nh = 0.f, nt = 0.f;
        #pragma unroll
        for (int m = 0; m < MMENT; m++) {
            nh += s_ptatt[m]*g_eemb[((size_t)(n*EE+h)*MMENT+m)*DD + d];
            nt += s_phatt[m]*g_eemb[((size_t)(n*EE+t)*MMENT+m)*DD + d];
        }
        g_hcat[(size_t)r*DIM3 + d] = nh;
        g_tcat[(size_t)r*DIM3 + d] = nt;
        g_q[(size_t)r*DIM2 + d]       = nh;
        g_q[(size_t)r*DIM2 + DD + d]  = nt;
    }
    float local = 0.f;
    for (int c = tid; c < CC; c += blockDim.x) {
        float na = 0.f, ta = 0.f;
        #pragma unroll
        for (int m = 0; m < MMENT; m++) {
            na += s_ptatt[m]*g_eatt[((size_t)(n*EE+h)*MMENT+m)*CC + c];
            ta += s_phatt[m]*g_eatt[((size_t)(n*EE+t)*MMENT+m)*CC + c];
        }
        float v = na*ta;
        g_pa[(size_t)r*CC + c] = v;
        local += v;
    }
    s_red[tid] = local;
    __syncthreads();
    for (int off = 128; off > 0; off >>= 1) {
        if (tid < off) s_red[tid] += s_red[tid+off];
        __syncthreads();
    }
    float inv = 1.f/(s_red[0] + 1e-5f);
    for (int c = tid; c < CC; c += blockDim.x)
        g_pa[(size_t)r*CC + c] *= inv;
}

// ---------------- fp32 SGEMM (Wm1/Wm2, rs) ----------------
__global__ void __launch_bounds__(256) sgemm(
    int M, int Nn, int Kc, int S,
    const float* __restrict__ A, int lda, long long sA,
    const float* __restrict__ B, int ldb, long long sB,
    float* __restrict__ part, int Mtot)
{
    int b = blockIdx.z / S;
    int s = blockIdx.z % S;
    const float* Ab = A + (size_t)b*sA + (size_t)s*Kc;
    const float* Bb = B + (size_t)b*sB + (size_t)s*Kc*ldb;
    int m0 = blockIdx.y*128, n0 = blockIdx.x*128;
    __shared__ float As[8][128];
    __shared__ float Bs[8][128];
    int tid = threadIdx.x;
    int arow = tid >> 1, ak = (tid & 1)*4;
    int bk = tid >> 5,  bn = (tid & 31)*4;
    int tx = tid & 15,  ty = tid >> 4;
    float acc[8][8];
    #pragma unroll
    for (int i = 0; i < 8; i++)
        #pragma unroll
        for (int j = 0; j < 8; j++) acc[i][j] = 0.f;
    for (int k0 = 0; k0 < Kc; k0 += 8) {
        float4 av = make_float4(0.f,0.f,0.f,0.f);
        if (m0 + arow < M)
            av = *(const float4*)(Ab + (size_t)(m0+arow)*lda + k0 + ak);
        float4 bvv = *(const float4*)(Bb + (size_t)(k0+bk)*ldb + n0 + bn);
        __syncthreads();
        As[ak+0][arow] = av.x; As[ak+1][arow] = av.y;
        As[ak+2][arow] = av.z; As[ak+3][arow] = av.w;
        *(float4*)&Bs[bk][bn] = bvv;
        __syncthreads();
        #pragma unroll
        for (int kk = 0; kk < 8; kk++) {
            float a[8], bb[8];
            *(float4*)(a)    = *(const float4*)&As[kk][ty*8];
            *(float4*)(a+4)  = *(const float4*)&As[kk][ty*8+4];
            *(float4*)(bb)   = *(const float4*)&Bs[kk][tx*8];
            *(float4*)(bb+4) = *(const float4*)&Bs[kk][tx*8+4];
            #pragma unroll
            for (int i = 0; i < 8; i++)
                #pragma unroll
                for (int j = 0; j < 8; j++)
                    acc[i][j] += a[i]*bb[j];
        }
    }
    float* pbase = part + ((size_t)s*Mtot + (size_t)b*M)*Nn;
    #pragma unroll
    for (int i = 0; i < 8; i++) {
        int r = m0 + ty*8 + i;
        if (r < M) {
            float* prow = pbase + (size_t)r*Nn + n0 + tx*8;
            *(float4*)(prow)   = make_float4(acc[i][0],acc[i][1],acc[i][2],acc[i][3]);
            *(float4*)(prow+4) = make_float4(acc[i][4],acc[i][5],acc[i][6],acc[i][7]);
        }
    }
}

__global__ void reduce_ep(const float* __restrict__ part, int S, int Mtot, int Nn,
                          const float* __restrict__ bias, int dorelu,
                          float* __restrict__ dst1, int ld1,
                          float* __restrict__ dst2, int ld2)
{
    int idx = blockIdx.x*blockDim.x + threadIdx.x;
    if (idx >= Mtot*Nn) return;
    int r = idx / Nn, c = idx % Nn;
    float v = 0.f;
    for (int s = 0; s < S; s++)
        v += part[((size_t)s*Mtot + r)*Nn + c];
    if (bias) v += bias[c];
    if (dorelu) v = fmaxf(v, 0.f);
    dst1[(size_t)r*ld1 + c] = v;
    if (dst2) dst2[(size_t)r*ld2 + c] = v;
}

// ---------------- K7: score + masked softmax + path ----------------
__global__ void k_scorepath(const int* __restrict__ hts, const float* __restrict__ battp)
{
    int r = blockIdx.x;
    int n = r / PP;
    int h = hts[r*2 + 0];
    int t = hts[r*2 + 1];
    __shared__ float s_q[DIM4];
    __shared__ float s_score[EE];
    __shared__ float s_aw[EE];
    int tid = threadIdx.x;
    for (int i = tid; i < DIM4; i += blockDim.x)
        s_q[i] = g_qW[(size_t)r*DIM4 + i];
    __syncthreads();
    int warp = tid >> 5, lane = tid & 31;
    float batt = battp[0];
    for (int v = warp; v < EE; v += 8) {
        const float* e1 = g_edge + ((size_t)((n*EE+h)*EE + v))*DD;
        const float* e2 = g_edge + ((size_t)((n*EE+v)*EE + t))*DD;
        const float* e3 = g_edge + ((size_t)((n*EE+t)*EE + v))*DD;
        const float* e4 = g_edge + ((size_t)((n*EE+v)*EE + h))*DD;
        float s = 0.f;
        for (int d = lane; d < DD; d += 32)
            s += s_q[d]*e1[d] + s_q[DD+d]*e2[d] + s_q[2*DD+d]*e3[d] + s_q[3*DD+d]*e4[d];
        #pragma unroll
        for (int off = 16; off; off >>= 1)
            s += __shfl_down_sync(0xffffffffu, s, off);
        if (lane == 0) s_score[v] = s + batt;
    }
    __syncthreads();
    if (tid == 0) {
        float mx = -1e38f;
        for (int v = 0; v < EE; v++) {
            float sc = (v == h || v == t) ? NEGV : s_score[v];
            s_score[v] = sc;
            mx = fmaxf(mx, sc);
        }
        float sum = 0.f;
        for (int v = 0; v < EE; v++) {
            float e = expf(s_score[v] - mx);
            s_aw[v] = e;
            sum += e;
        }
        float inv = 1.f/sum;
        for (int v = 0; v < EE; v++) s_aw[v] *= inv;
    }
    __syncthreads();
    for (int idx = tid; idx < DIM4; idx += blockDim.x) {
        int kk = idx / DD, d = idx % DD;
        const float* ep;
        size_t strideV;
        if (kk == 0)      { ep = g_edge + ((size_t)((n*EE+h)*EE))*DD + d;   strideV = DD; }
        else if (kk == 1) { ep = g_edge + ((size_t)(n*EE)*EE + t)*DD + d;   strideV = (size_t)EE*DD; }
        else if (kk == 2) { ep = g_edge + ((size_t)((n*EE+t)*EE))*DD + d;   strideV = DD; }
        else              { ep = g_edge + ((size_t)(n*EE)*EE + h)*DD + d;   strideV = (size_t)EE*DD; }
        float acc = 0.f;
        #pragma unroll 4
        for (int v = 0; v < EE; v++)
            acc += s_aw[v]*ep[(size_t)v*strideV];
        g_pathraw[(size_t)r*DIM4 + idx] = acc;
    }
}

__global__ void k_bilred(const float* __restrict__ bbil, float* __restrict__ out)
{
    int idx = blockIdx.x*blockDim.x + threadIdx.x;
    if (idx >= NP*LL) return;
    int r = idx / LL, l = idx % LL;
    float v = bbil[l];
    #pragma unroll
    for (int k = 0; k < 12; k++)
        v += g_part[((size_t)k*NP + r)*LL + l];
    out[idx] = v;
}

// ---------------- launcher ----------------
static float* symaddr(const void* sym)
{
    void* p = nullptr;
    cudaGetSymbolAddress(&p, sym);
    return (float*)p;
}

extern "C" void kernel_launch(void* const* d_in, const int* in_sizes, int n_in,
                              void* d_out, int out_size)
{
    const float* seq   = (const float*)d_in[0];
    const float* att   = (const float*)d_in[1];
    const int*   ms    = (const int*)  d_in[2];
    const int*   hts   = (const int*)  d_in[3];
    const float* Wm1   = (const float*)d_in[4];
    const float* Wm2   = (const float*)d_in[5];
    const float* bm    = (const float*)d_in[6];
    const float* Watt  = (const float*)d_in[7];
    const float* batt  = (const float*)d_in[8];
    const float* Wpath = (const float*)d_in[9];
    const float* bpath = (const float*)d_in[10];
    const float* Whead = (const float*)d_in[11];
    const float* bhead = (const float*)d_in[12];
    const float* Wtail = (const float*)d_in[13];
    const float* btail = (const float*)d_in[14];
    const float* Wbil  = (const float*)d_in[15];
    const float* bbil  = (const float*)d_in[16];
    float* out = (float*)d_out;

    float* glob   = symaddr(g_glob);
    float* gA     = symaddr(g_A);
    float* gB     = symaddr(g_B);
    float* q      = symaddr(g_q);
    float* pa     = symaddr(g_pa);
    float* hcat   = symaddr(g_hcat);
    float* tcat   = symaddr(g_tcat);
    float* qW     = symaddr(g_qW);
    float* praw   = symaddr(g_pathraw);
    float* hs     = symaddr(g_hs);
    float* ts     = symaddr(g_ts);
    float* part   = symaddr(g_part);
    float* wTatt  = symaddr(g_wT_att);
    float* wTpath = symaddr(g_wT_path);
    float* wThead = symaddr(g_wT_head);
    float* wTtail = symaddr(g_wT_tail);
    float* wTbil  = symaddr(g_wT_bil);

    const int SMEM_WG = 65536;
    const int SMEM_WB = 65536 + 2*8256*4;
    cudaFuncSetAttribute(wgemm, cudaFuncAttributeMaxDynamicSharedMemorySize, SMEM_WG);
    cudaFuncSetAttribute(wbil,  cudaFuncAttributeMaxDynamicSharedMemorySize, SMEM_WB);

    // --- ordered so my launch index 3 (= ncu capture slot, 2 hidden launches + -s 5) is qW wgemm ---
    k_gather<<<NN*EE, 256>>>(seq, att, ms);                                        // 0
    k_pair<<<NP, 256>>>(hts, ms);                                                  // 1
    ktrans<<<dim3(DIM4/32, DIM2/32), dim3(32,8)>>>(Watt, DIM2, DIM4, DIM4, wTatt); // 2
    // 3: qW = q @ Watt (tf32 mma) <-- ncu profiles this
    wgemm<<<dim3(24,12,1), 256, SMEM_WG>>>(NP, 48, 1, q, DIM2, wTatt, DIM2,
                                           nullptr, nullptr,
                                           qW, DIM4, nullptr, 0, nullptr, 0,
                                           nullptr, 0, 0);

    // Wm1/Wm2 (fp32 for accuracy; feeds edge -> everything downstream)
    sgemm<<<dim3(6,1,12), 256>>>(NN*EE, DD, 64, 12, glob, DD, 0, Wm1, DD, 0,
                                 part, NN*EE);
    reduce_ep<<<(NN*EE*DD+255)/256, 256>>>(part, 12, NN*EE, DD, nullptr, 0,
                                           gA, DD, nullptr, 0);
    sgemm<<<dim3(6,1,12), 256>>>(NN*EE, DD, 64, 12, glob, DD, 0, Wm2, DD, 0,
                                 part, NN*EE);
    reduce_ep<<<(NN*EE*DD+255)/256, 256>>>(part, 12, NN*EE, DD, nullptr, 0,
                                           gB, DD, nullptr, 0);
    k_edge<<<(NN*EE*EE*DD+255)/256, 256>>>(bm);

    // rs = pa @ seq (fp32, batched, split-K 4)
    sgemm<<<dim3(6,3,NN*4), 256>>>(PP, DD, CC/4, 4, pa, CC, (long long)PP*CC,
                                   seq, DD, (long long)CC*DD, part, NP);
    reduce_ep<<<(NP*DD+255)/256, 256>>>(part, 4, NP, DD, nullptr, 0,
                                        hcat + DD, DIM3, tcat + DD, DIM3);

    // score/softmax/path
    k_scorepath<<<NP, 256>>>(hts, batt);

    // path = relu(pathraw @ Wpath + bpath)
    ktrans<<<dim3(DD/32, DIM4/32), dim3(32,8)>>>(Wpath, DIM4, DD, DD, wTpath);
    wgemm<<<dim3(6,12,2), 256, SMEM_WG>>>(NP, 48, 2, praw, DIM4, wTpath, DIM4,
                                          nullptr, nullptr,
                                          nullptr, 0, nullptr, 0, nullptr, 0,
                                          part, NP, DD);
    reduce_ep<<<(NP*DD+255)/256, 256>>>(part, 2, NP, DD, bpath, 1,
                                        hcat + 2*DD, DIM3, tcat + 2*DD, DIM3);

    // hs / ts projections — merged batched launch (z: b=z/2 selects head/tail, s=z%2)
    ktrans<<<dim3(DD/32, DIM3/32), dim3(32,8)>>>(Whead, DIM3, DD, DD, wThead);
    ktrans<<<dim3(DD/32, DIM3/32), dim3(32,8)>>>(Wtail, DIM3, DD, DD, wTtail);
    wgemm<<<dim3(6,12,4), 256, SMEM_WG>>>(NP, 36, 2, hcat, DIM3, wThead, DIM3,
                                          tcat, wTtail,
                                          nullptr, 0, nullptr, 0, nullptr, 0,
                                          part, NP, DD);
    reduce_ep<<<(NP*DD+255)/256, 256>>>(part, 2, NP, DD, bhead, 1, hs, DD, nullptr, 0);
    reduce_ep<<<(NP*DD+255)/256, 256>>>(part + (size_t)2*NP*DD, 2, NP, DD, btail, 1,
                                        ts, DD, nullptr, 0);

    // bilinear head (tf32 mma, fused outer-product A)
    ktrans<<<dim3(4, KBIL/32), dim3(32,8)>>>(Wbil, KBIL, LL, 128, wTbil);
    wbil<<<dim3(12,12), 256, SMEM_WB>>>(wTbil);
    k_bilred<<<(NP*LL+255)/256, 256>>>(bbil, out);
}

// round 10
// speedup vs baseline: 2.0994x; 1.3728x over previous
#include <cuda_runtime.h>
#include <cstdint>
#include <math.h>

#define NN 4
#define CC 512
#define DD 768
#define HH 12
#define EE 20
#define MMENT 4
#define PP 380
#define NP 1520
#define LL 97
#define DIM2 1536
#define DIM3 2304
#define DIM4 3072
#define KBIL 49152
#define NEGV (-1e30f)

// ---------------- static device scratch ----------------
__device__ float g_eemb[NN*EE*MMENT*DD];
__device__ float g_eatt[NN*EE*MMENT*CC];
__device__ float g_glob[NN*EE*DD];
__device__ float g_A[NN*EE*DD];
__device__ float g_B[NN*EE*DD];
__device__ float g_edge[NN*EE*EE*DD];
__device__ float g_q[NP*DIM2];
__device__ float g_pa[NP*CC];
__device__ float g_hcat[NP*DIM3];
__device__ float g_tcat[NP*DIM3];
__device__ float g_qW[NP*DIM4];
__device__ float g_pathraw[NP*DIM4];
__device__ float g_hs[NP*DD];
__device__ float g_ts[NP*DD];
__device__ float g_part[4*NP*DD];
// transposed (K-major) weights for mma B operand
__device__ float g_wT_att[DIM4*DIM2];
__device__ float g_wT_path[DD*DIM4];
__device__ float g_wT_head[DD*DIM3];
__device__ float g_wT_tail[DD*DIM3];
__device__ float g_wT_bil[128*KBIL];   // rows 97..127 zero

// ---------------- helpers ----------------
__device__ __forceinline__ uint32_t f2tf32(float f) {
    uint32_t r;
    asm("cvt.rna.tf32.f32 %0, %1;" : "=r"(r) : "f"(f));
    return r;
}
__device__ __forceinline__ void mma_tf32(float* d, uint32_t a0, uint32_t a1,
                                         uint32_t a2, uint32_t a3,
                                         uint32_t b0, uint32_t b1)
{
    asm volatile(
        "mma.sync.aligned.m16n8k8.row.col.f32.tf32.tf32.f32 "
        "{%0,%1,%2,%3}, {%4,%5,%6,%7}, {%8,%9}, {%0,%1,%2,%3};"
        : "+f"(d[0]), "+f"(d[1]), "+f"(d[2]), "+f"(d[3])
        : "r"(a0), "r"(a1), "r"(a2), "r"(a3), "r"(b0), "r"(b1));
}
__device__ __forceinline__ void ldsm4(uint32_t addr, uint32_t& a, uint32_t& b,
                                      uint32_t& c, uint32_t& d)
{
    asm volatile("ldmatrix.sync.aligned.m8n8.x4.shared.b16 {%0,%1,%2,%3}, [%4];"
                 : "=r"(a), "=r"(b), "=r"(c), "=r"(d) : "r"(addr));
}
__device__ __forceinline__ void sts128(uint32_t addr, uint32_t x, uint32_t y,
                                       uint32_t z, uint32_t w)
{
    asm volatile("st.shared.v4.b32 [%0], {%1,%2,%3,%4};"
                 :: "r"(addr), "r"(x), "r"(y), "r"(z), "r"(w) : "memory");
}

// ================ tf32 warp-mma GEMM (swizzled smem + ldmatrix) ================
// Tiles: CTA 128x128, K-chunk 32. smem: A buf 16KB + B buf 16KB, double buffered.
// Row-major staging with 16B-chunk XOR swizzle: byte = row*128 + ((col16 ^ (row&7))<<4).
// grid: (N/128, ceil(M/128), Sr*nbatch). z: b = z/Sr, s = z%Sr. b==1 -> A2/BT2.
__global__ void __launch_bounds__(256,2) wgemm(
    int M, int nchunks, int Sr,
    const float* __restrict__ A, int lda,
    const float* __restrict__ BT, int ldbt,
    const float* __restrict__ A2,
    const float* __restrict__ BT2,
    float* __restrict__ dst1, int ld1,
    const float* __restrict__ bias, int relu,
    float* __restrict__ dst2, int ld2,
    float* __restrict__ part, int Mtot, int Nn)
{
    extern __shared__ float smf[];
    uint32_t sbase = (uint32_t)__cvta_generic_to_shared(smf);
    int tid = threadIdx.x;
    int lane = tid & 31, wid = tid >> 5;
    int wm = wid >> 2, wn = wid & 3;
    int m0 = blockIdx.y*128, n0 = blockIdx.x*128;
    int z = blockIdx.z;
    int s = z % Sr, b = z / Sr;
    const float* Ause  = b ? A2  : A;
    const float* BTuse = b ? BT2 : BT;
    int kbase = s*nchunks*32;

    // staging coords: thread covers rows r0g+32t, fixed float4-col qf
    int r0g = tid >> 3;
    int qf  = tid & 7;
    uint32_t stc = (uint32_t)((qf ^ (r0g & 7)) << 4);

    // ldmatrix coords
    int lg = lane >> 3, l7 = lane & 7;
    int arow = wm*64 + ((lg & 1) << 3) + l7;
    int brow = wn*32 + ((lg >> 1) << 3) + l7;
    uint32_t acol[4], bcol[4];
    #pragma unroll
    for (int ks = 0; ks < 4; ks++) {
        acol[ks] = (uint32_t)(((((ks<<1) + (lg>>1)) ^ (arow & 7))) << 4);
        bcol[ks] = (uint32_t)(((((ks<<1) + (lg&1))  ^ (brow & 7))) << 4);
    }
    uint32_t aBase = sbase + (uint32_t)(arow*128);
    uint32_t bBase = sbase + 16384u + (uint32_t)(brow*128);

    float acc[4][4][4];
    #pragma unroll
    for (int i = 0; i < 4; i++)
        #pragma unroll
        for (int j = 0; j < 4; j++)
            #pragma unroll
            for (int k = 0; k < 4; k++) acc[i][j][k] = 0.f;

    float4 av[4], bv[4];
    auto gather = [&](int kc) {
        int k0 = kbase + kc*32 + qf*4;
        #pragma unroll
        for (int t = 0; t < 4; t++) {
            int r = r0g + t*32;
            int rm = m0 + r;
            av[t] = (rm < M) ? *(const float4*)(Ause + (size_t)rm*lda + k0)
                             : make_float4(0.f,0.f,0.f,0.f);
            bv[t] = *(const float4*)(BTuse + (size_t)(n0 + r)*ldbt + k0);
        }
    };
    auto store = [&](int buf) {
        uint32_t off = sbase + (uint32_t)(buf*32768);
        #pragma unroll
        for (int t = 0; t < 4; t++) {
            uint32_t rowo = (uint32_t)((r0g + t*32)*128);
            sts128(off + rowo + stc,
                   f2tf32(av[t].x), f2tf32(av[t].y), f2tf32(av[t].z), f2tf32(av[t].w));
            sts128(off + 16384u + rowo + stc,
                   f2tf32(bv[t].x), f2tf32(bv[t].y), f2tf32(bv[t].z), f2tf32(bv[t].w));
        }
    };
    auto compute = [&](int buf) {
        uint32_t ab = aBase + (uint32_t)(buf*32768);
        uint32_t bb = bBase + (uint32_t)(buf*32768);
        #pragma unroll
        for (int ks = 0; ks < 4; ks++) {
            uint32_t bfr[4][2];
            #pragma unroll
            for (int ntp = 0; ntp < 2; ntp++)
                ldsm4(bb + (uint32_t)(ntp*2048) + bcol[ks],
                      bfr[2*ntp][0], bfr[2*ntp][1], bfr[2*ntp+1][0], bfr[2*ntp+1][1]);
            #pragma unroll
            for (int mt = 0; mt < 4; mt++) {
                uint32_t a0, a1, a2, a3;
                ldsm4(ab + (uint32_t)(mt*2048) + acol[ks], a0, a1, a2, a3);
                #pragma unroll
                for (int nt = 0; nt < 4; nt++)
                    mma_tf32(acc[mt][nt], a0, a1, a2, a3, bfr[nt][0], bfr[nt][1]);
            }
        }
    };

    gather(0);
    for (int kc = 0; kc < nchunks; kc++) {
        int buf = kc & 1;
        store(buf);
        __syncthreads();
        if (kc + 1 < nchunks) gather(kc + 1);
        compute(buf);
    }

    int eg = lane >> 2, ec = lane & 3;
    #pragma unroll
    for (int mt = 0; mt < 4; mt++) {
        int r0 = m0 + wm*64 + mt*16 + eg;
        int r1 = r0 + 8;
        #pragma unroll
        for (int nt = 0; nt < 4; nt++) {
            int c0 = n0 + wn*32 + nt*8 + 2*ec;
            if (part) {
                float* p0 = part + ((size_t)z*Mtot + r0)*Nn + c0;
                float* p1 = part + ((size_t)z*Mtot + r1)*Nn + c0;
                if (r0 < M) { p0[0] = acc[mt][nt][0]; p0[1] = acc[mt][nt][1]; }
                if (r1 < M) { p1[0] = acc[mt][nt][2]; p1[1] = acc[mt][nt][3]; }
            } else {
                float b0 = bias ? bias[c0] : 0.f;
                float b1 = bias ? bias[c0+1] : 0.f;
                float v0 = acc[mt][nt][0] + b0, v1 = acc[mt][nt][1] + b1;
                float v2 = acc[mt][nt][2] + b0, v3 = acc[mt][nt][3] + b1;
                if (relu) { v0=fmaxf(v0,0.f); v1=fmaxf(v1,0.f); v2=fmaxf(v2,0.f); v3=fmaxf(v3,0.f); }
                if (r0 < M) {
                    dst1[(size_t)r0*ld1 + c0] = v0; dst1[(size_t)r0*ld1 + c0+1] = v1;
                    if (dst2) { dst2[(size_t)r0*ld2 + c0] = v0; dst2[(size_t)r0*ld2 + c0+1] = v1; }
                }
                if (r1 < M) {
                    dst1[(size_t)r1*ld1 + c0] = v2; dst1[(size_t)r1*ld1 + c0+1] = v3;
                    if (dst2) { dst2[(size_t)r1*ld2 + c0] = v2; dst2[(size_t)r1*ld2 + c0+1] = v3; }
                }
            }
        }
    }
}

// ===== bilinear: part[kb] = (hs_kb ⊗ ts_kb)[128-row tile] @ WbilT[kb] =====
// Same swizzled-smem/ldmatrix core; A tile built on the fly from hs/ts staged row-major.
__global__ void __launch_bounds__(256) wbil(const float* __restrict__ BT)
{
    extern __shared__ float smf[];
    uint32_t sbase = (uint32_t)__cvta_generic_to_shared(smf);
    float* hs_s = smf + 16384;           // [128][64]
    float* ts_s = smf + 16384 + 8192;    // [128][64]
    int tid = threadIdx.x;
    int lane = tid & 31, wid = tid >> 5;
    int wm = wid >> 2, wn = wid & 3;
    int m0 = blockIdx.x*128;
    int kb = blockIdx.y;

    // stage hs/ts row-major
    #pragma unroll
    for (int t = 0; t < 8; t++) {
        int idx = tid + t*256;           // 0..2047 float4 slots over 2 arrays? no: per array
        int r = idx >> 4, qi = idx & 15;
        int rg = m0 + r;
        float4 h = make_float4(0.f,0.f,0.f,0.f), v = h;
        if (rg < NP) {
            h = *(const float4*)(g_hs + (size_t)rg*DD + kb*64 + qi*4);
            v = *(const float4*)(g_ts + (size_t)rg*DD + kb*64 + qi*4);
        }
        *(float4*)(hs_s + r*64 + qi*4) = h;
        *(float4*)(ts_s + r*64 + qi*4) = v;
    }
    __syncthreads();

    int r0g = tid >> 3;
    int qf  = tid & 7;
    uint32_t stc = (uint32_t)((qf ^ (r0g & 7)) << 4);

    int lg = lane >> 3, l7 = lane & 7;
    int arow = wm*64 + ((lg & 1) << 3) + l7;
    int brow = wn*32 + ((lg >> 1) << 3) + l7;
    uint32_t acol[4], bcol[4];
    #pragma unroll
    for (int ks = 0; ks < 4; ks++) {
        acol[ks] = (uint32_t)(((((ks<<1) + (lg>>1)) ^ (arow & 7))) << 4);
        bcol[ks] = (uint32_t)(((((ks<<1) + (lg&1))  ^ (brow & 7))) << 4);
    }
    uint32_t aBase = sbase + (uint32_t)(arow*128);
    uint32_t bBase = sbase + 16384u + (uint32_t)(brow*128);

    float acc[4][4][4];
    #pragma unroll
    for (int i = 0; i < 4; i++)
        #pragma unroll
        for (int j = 0; j < 4; j++)
            #pragma unroll
            for (int k = 0; k < 4; k++) acc[i][j][k] = 0.f;

    float4 av[4], bv[4];
    auto gather = [&](int kc) {
        int ii = kc >> 1;
        int j0 = ((kc & 1) << 5) + qf*4;
        int k0 = kb*4096 + kc*32 + qf*4;
        #pragma unroll
        for (int t = 0; t < 4; t++) {
            int r = r0g + t*32;
            float hv = hs_s[r*64 + ii];
            float4 tv = *(const float4*)(ts_s + r*64 + j0);
            av[t] = make_float4(hv*tv.x, hv*tv.y, hv*tv.z, hv*tv.w);
            bv[t] = *(const float4*)(BT + (size_t)r*KBIL + k0);
        }
    };
    auto store = [&](int buf) {
        uint32_t off = sbase + (uint32_t)(buf*32768);
        #pragma unroll
        for (int t = 0; t < 4; t++) {
            uint32_t rowo = (uint32_t)((r0g + t*32)*128);
            sts128(off + rowo + stc,
                   f2tf32(av[t].x), f2tf32(av[t].y), f2tf32(av[t].z), f2tf32(av[t].w));
            sts128(off + 16384u + rowo + stc,
                   f2tf32(bv[t].x), f2tf32(bv[t].y), f2tf32(bv[t].z), f2tf32(bv[t].w));
        }
    };
    auto compute = [&](int buf) {
        uint32_t ab = aBase + (uint32_t)(buf*32768);
        uint32_t bb = bBase + (uint32_t)(buf*32768);
        #pragma unroll
        for (int ks = 0; ks < 4; ks++) {
            uint32_t bfr[4][2];
            #pragma unroll
            for (int ntp = 0; ntp < 2; ntp++)
                ldsm4(bb + (uint32_t)(ntp*2048) + bcol[ks],
                      bfr[2*ntp][0], bfr[2*ntp][1], bfr[2*ntp+1][0], bfr[2*ntp+1][1]);
            #pragma unroll
            for (int mt = 0; mt < 4; mt++) {
                uint32_t a0, a1, a2, a3;
                ldsm4(ab + (uint32_t)(mt*2048) + acol[ks], a0, a1, a2, a3);
                #pragma unroll
                for (int nt = 0; nt < 4; nt++)
                    mma_tf32(acc[mt][nt], a0, a1, a2, a3, bfr[nt][0], bfr[nt][1]);
            }
        }
    };

    gather(0);
    for (int kc = 0; kc < 128; kc++) {
        int buf = kc & 1;
        store(buf);
        __syncthreads();
        if (kc + 1 < 128) gather(kc + 1);
        compute(buf);
    }

    int eg = lane >> 2, ec = lane & 3;
    #pragma unroll
    for (int mt = 0; mt < 4; mt++) {
        int r0 = m0 + wm*64 + mt*16 + eg;
        int r1 = r0 + 8;
        #pragma unroll
        for (int nt = 0; nt < 4; nt++) {
            int c0 = wn*32 + nt*8 + 2*ec;
            #pragma unroll
            for (int u = 0; u < 2; u++) {
                int col = c0 + u;
                if (col < LL) {
                    if (r0 < NP) g_part[((size_t)kb*NP + r0)*LL + col] = acc[mt][nt][u];
                    if (r1 < NP) g_part[((size_t)kb*NP + r1)*LL + col] = acc[mt][nt][2+u];
                }
            }
        }
    }
}

// ================= transpose: out[c][r] = in[r][c]; rows c in [C,Cout) -> 0 =================
__global__ void ktrans(const float* __restrict__ in, int R, int C, int Cout,
                       float* __restrict__ out)
{
    __shared__ float t[32][33];
    int c0 = blockIdx.x*32, r0 = blockIdx.y*32;
    int tx = threadIdx.x, ty = threadIdx.y;
    #pragma unroll
    for (int j = 0; j < 32; j += 8) {
        int r = r0 + ty + j, c = c0 + tx;
        t[ty+j][tx] = (r < R && c < C) ? in[(size_t)r*C + c] : 0.f;
    }
    __syncthreads();
    #pragma unroll
    for (int j = 0; j < 32; j += 8) {
        int c = c0 + ty + j, r = r0 + tx;
        if (c < Cout && r < R) out[(size_t)c*R + r] = t[tx][ty+j];
    }
}

// ---------------- K1: gather ----------------
__global__ void k_gather(const float* __restrict__ seq, const float* __restrict__ att,
                         const int* __restrict__ ms)
{
    int ne = blockIdx.x;
    int n  = ne / EE;
    int tid = threadIdx.x;
    for (int m = 0; m < MMENT; m++) {
        int pos = ms[ne*MMENT + m] + 1;
        const float* srow = seq + ((size_t)n*CC + pos)*DD;
        float* erow = g_eemb + ((size_t)ne*MMENT + m)*DD;
        for (int d = tid; d < DD; d += blockDim.x) erow[d] = srow[d];
        float* arow = g_eatt + ((size_t)ne*MMENT + m)*CC;
        for (int c = tid; c < CC; c += blockDim.x) {
            float s = 0.f;
            #pragma unroll
            for (int h = 0; h < HH; h++)
                s += att[(((size_t)n*HH + h)*CC + pos)*CC + c];
            arow[c] = s * (1.0f/HH);
        }
    }
    __syncthreads();
    for (int d = tid; d < DD; d += blockDim.x) {
        float x0 = g_eemb[((size_t)ne*MMENT+0)*DD+d];
        float x1 = g_eemb[((size_t)ne*MMENT+1)*DD+d];
        float x2 = g_eemb[((size_t)ne*MMENT+2)*DD+d];
        float x3 = g_eemb[((size_t)ne*MMENT+3)*DD+d];
        float mx = fmaxf(fmaxf(x0,x1), fmaxf(x2,x3));
        float s = expf(x0-mx)+expf(x1-mx)+expf(x2-mx)+expf(x3-mx);
        g_glob[(size_t)ne*DD + d] = mx + logf(s);
    }
}

// ---------------- K3: edge ----------------
__global__ void k_edge(const float* __restrict__ bm)
{
    int idx = blockIdx.x*blockDim.x + threadIdx.x;
    const int total = NN*EE*EE*DD;
    if (idx >= total) return;
    int d = idx % DD;
    int v = (idx / DD) % EE;
    int u = (idx / (DD*EE)) % EE;
    int n = idx / (DD*EE*EE);
    float val = g_A[((size_t)n*EE+u)*DD+d] + g_B[((size_t)n*EE+v)*DD+d] + bm[d];
    g_edge[idx] = fmaxf(val, 0.f);
}

// ---------------- K4: pair attention ----------------
__global__ void k_pair(const int* __restrict__ hts, const int* __restrict__ ms)
{
    int r = blockIdx.x;
    int n = r / PP;
    int h = hts[r*2 + 0];
    int t = hts[r*2 + 1];
    __shared__ int   s_ph[MMENT], s_pt[MMENT];
    __shared__ float s_phatt[MMENT], s_ptatt[MMENT];
    __shared__ float s_red[256];
    int tid = threadIdx.x;
    if (tid < MMENT) {
        s_ph[tid] = ms[((size_t)n*EE+h)*MMENT + tid] + 1;
        s_pt[tid] = ms[((size_t)n*EE+t)*MMENT + tid] + 1;
    }
    __syncthreads();
    if (tid < 2*MMENT) {
        int m2 = tid & (MMENT-1);
        float s = 0.f;
        if (tid < MMENT) {
            for (int m1 = 0; m1 < MMENT; m1++)
                s += g_eatt[((size_t)(n*EE+h)*MMENT+m1)*CC + s_pt[m2]];
            s_phatt[m2] = s * (1.f/MMENT);
        } else {
            for (int m1 = 0; m1 < MMENT; m1++)
                s += g_eatt[((size_t)(n*EE+t)*MMENT+m1)*CC + s_ph[m2]];
            s_ptatt[m2] = s * (1.f/MMENT);
        }
    }
    __syncthreads();
    if (tid == 0) {
        float sh = 1e-5f, st = 1e-5f;
        for (int m = 0; m < MMENT; m++) { sh += s_phatt[m]; st += s_ptatt[m]; }
        float ih = 1.f/sh, it = 1.f/st;
        for (int m = 0; m < MMENT; m++) { s_phatt[m] *= ih; s_ptatt[m] *= it; }
    }
    __syncthreads();
    for (int d = tid; d < DD; d += blockDim.x) {
        float nh = 0.f, nt = 0.f;
        #pragma unroll
        for (int m = 0; m < MMENT; m++) {
            nh += s_ptatt[m]*g_eemb[((size_t)(n*EE+h)*MMENT+m)*DD + d];
            nt += s_phatt[m]*g_eemb[((size_t)(n*EE+t)*MMENT+m)*DD + d];
        }
        g_hcat[(size_t)r*DIM3 + d] = nh;
        g_tcat[(size_t)r*DIM3 + d] = nt;
        g_q[(size_t)r*DIM2 + d]       = nh;
        g_q[(size_t)r*DIM2 + DD + d]  = nt;
    }
    float local = 0.f;
    for (int c = tid; c < CC; c += blockDim.x) {
        float na = 0.f, ta = 0.f;
        #pragma unroll
        for (int m = 0; m < MMENT; m++) {
            na += s_ptatt[m]*g_eatt[((size_t)(n*EE+h)*MMENT+m)*CC + c];
            ta += s_phatt[m]*g_eatt[((size_t)(n*EE+t)*MMENT+m)*CC + c];
        }
        float v = na*ta;
        g_pa[(size_t)r*CC + c] = v;
        local += v;
    }
    s_red[tid] = local;
    __syncthreads();
    for (int off = 128; off > 0; off >>= 1) {
        if (tid < off) s_red[tid] += s_red[tid+off];
        __syncthreads();
    }
    float inv = 1.f/(s_red[0] + 1e-5f);
    for (int c = tid; c < CC; c += blockDim.x)
        g_pa[(size_t)r*CC + c] *= inv;
}

// ---------------- fp32 SGEMM (Wm1/Wm2, rs) ----------------
__global__ void __launch_bounds__(256) sgemm(
    int M, int Nn, int Kc, int S,
    const float* __restrict__ A, int lda, long long sA,
    const float* __restrict__ B, int ldb, long long sB,
    float* __restrict__ part, int Mtot)
{
    int b = blockIdx.z / S;
    int s = blockIdx.z % S;
    const float* Ab = A + (size_t)b*sA + (size_t)s*Kc;
    const float* Bb = B + (size_t)b*sB + (size_t)s*Kc*ldb;
    int m0 = blockIdx.y*128, n0 = blockIdx.x*128;
    __shared__ float As[8][128];
    __shared__ float Bs[8][128];
    int tid = threadIdx.x;
    int arow = tid >> 1, ak = (tid & 1)*4;
    int bk = tid >> 5,  bn = (tid & 31)*4;
    int tx = tid & 15,  ty = tid >> 4;
    float acc[8][8];
    #pragma unroll
    for (int i = 0; i < 8; i++)
        #pragma unroll
        for (int j = 0; j < 8; j++) acc[i][j] = 0.f;
    for (int k0 = 0; k0 < Kc; k0 += 8) {
        float4 av = make_float4(0.f,0.f,0.f,0.f);
        if (m0 + arow < M)
            av = *(const float4*)(Ab + (size_t)(m0+arow)*lda + k0 + ak);
        float4 bvv = *(const float4*)(Bb + (size_t)(k0+bk)*ldb + n0 + bn);
        __syncthreads();
        As[ak+0][arow] = av.x; As[ak+1][arow] = av.y;
        As[ak+2][arow] = av.z; As[ak+3][arow] = av.w;
        *(float4*)&Bs[bk][bn] = bvv;
        __syncthreads();
        #pragma unroll
        for (int kk = 0; kk < 8; kk++) {
            float a[8], bb[8];
            *(float4*)(a)    = *(const float4*)&As[kk][ty*8];
            *(float4*)(a+4)  = *(const float4*)&As[kk][ty*8+4];
            *(float4*)(bb)   = *(const float4*)&Bs[kk][tx*8];
            *(float4*)(bb+4) = *(const float4*)&Bs[kk][tx*8+4];
            #pragma unroll
            for (int i = 0; i < 8; i++)
                #pragma unroll
                for (int j = 0; j < 8; j++)
                    acc[i][j] += a[i]*bb[j];
        }
    }
    float* pbase = part + ((size_t)s*Mtot + (size_t)b*M)*Nn;
    #pragma unroll
    for (int i = 0; i < 8; i++) {
        int r = m0 + ty*8 + i;
        if (r < M) {
            float* prow = pbase + (size_t)r*Nn + n0 + tx*8;
            *(float4*)(prow)   = make_float4(acc[i][0],acc[i][1],acc[i][2],acc[i][3]);
            *(float4*)(prow+4) = make_float4(acc[i][4],acc[i][5],acc[i][6],acc[i][7]);
        }
    }
}

__global__ void reduce_ep(const float* __restrict__ part, int S, int Mtot, int Nn,
                          const float* __restrict__ bias, int dorelu,
                          float* __restrict__ dst1, int ld1,
                          float* __restrict__ dst2, int ld2)
{
    int idx = blockIdx.x*blockDim.x + threadIdx.x;
    if (idx >= Mtot*Nn) return;
    int r = idx / Nn, c = idx % Nn;
    float v = 0.f;
    for (int s = 0; s < S; s++)
        v += part[((size_t)s*Mtot + r)*Nn + c];
    if (bias) v += bias[c];
    if (dorelu) v = fmaxf(v, 0.f);
    dst1[(size_t)r*ld1 + c] = v;
    if (dst2) dst2[(size_t)r*ld2 + c] = v;
}

// ---------------- K7: score + masked softmax + path ----------------
__global__ void k_scorepath(const int* __restrict__ hts, const float* __restrict__ battp)
{
    int r = blockIdx.x;
    int n = r / PP;
    int h = hts[r*2 + 0];
    int t = hts[r*2 + 1];
    __shared__ float s_q[DIM4];
    __shared__ float s_score[EE];
    __shared__ float s_aw[EE];
    int tid = threadIdx.x;
    for (int i = tid; i < DIM4; i += blockDim.x)
        s_q[i] = g_qW[(size_t)r*DIM4 + i];
    __syncthreads();
    int warp = tid >> 5, lane = tid & 31;
    float batt = battp[0];
    for (int v = warp; v < EE; v += 8) {
        const float* e1 = g_edge + ((size_t)((n*EE+h)*EE + v))*DD;
        const float* e2 = g_edge + ((size_t)((n*EE+v)*EE + t))*DD;
        const float* e3 = g_edge + ((size_t)((n*EE+t)*EE + v))*DD;
        const float* e4 = g_edge + ((size_t)((n*EE+v)*EE + h))*DD;
        float s = 0.f;
        for (int d = lane; d < DD; d += 32)
            s += s_q[d]*e1[d] + s_q[DD+d]*e2[d] + s_q[2*DD+d]*e3[d] + s_q[3*DD+d]*e4[d];
        #pragma unroll
        for (int off = 16; off; off >>= 1)
            s += __shfl_down_sync(0xffffffffu, s, off);
        if (lane == 0) s_score[v] = s + batt;
    }
    __syncthreads();
    if (tid == 0) {
        float mx = -1e38f;
        for (int v = 0; v < EE; v++) {
            float sc = (v == h || v == t) ? NEGV : s_score[v];
            s_score[v] = sc;
            mx = fmaxf(mx, sc);
        }
        float sum = 0.f;
        for (int v = 0; v < EE; v++) {
            float e = expf(s_score[v] - mx);
            s_aw[v] = e;
            sum += e;
        }
        float inv = 1.f/sum;
        for (int v = 0; v < EE; v++) s_aw[v] *= inv;
    }
    __syncthreads();
    for (int idx = tid; idx < DIM4; idx += blockDim.x) {
        int kk = idx / DD, d = idx % DD;
        const float* ep;
        size_t strideV;
        if (kk == 0)      { ep = g_edge + ((size_t)((n*EE+h)*EE))*DD + d;   strideV = DD; }
        else if (kk == 1) { ep = g_edge + ((size_t)(n*EE)*EE + t)*DD + d;   strideV = (size_t)EE*DD; }
        else if (kk == 2) { ep = g_edge + ((size_t)((n*EE+t)*EE))*DD + d;   strideV = DD; }
        else              { ep = g_edge + ((size_t)(n*EE)*EE + h)*DD + d;   strideV = (size_t)EE*DD; }
        float acc = 0.f;
        #pragma unroll 4
        for (int v = 0; v < EE; v++)
            acc += s_aw[v]*ep[(size_t)v*strideV];
        g_pathraw[(size_t)r*DIM4 + idx] = acc;
    }
}

__global__ void k_bilred(const float* __restrict__ bbil, float* __restrict__ out)
{
    int idx = blockIdx.x*blockDim.x + threadIdx.x;
    if (idx >= NP*LL) return;
    int r = idx / LL, l = idx % LL;
    float v = bbil[l];
    #pragma unroll
    for (int k = 0; k < 12; k++)
        v += g_part[((size_t)k*NP + r)*LL + l];
    out[idx] = v;
}

// ---------------- launcher ----------------
static float* symaddr(const void* sym)
{
    void* p = nullptr;
    cudaGetSymbolAddress(&p, sym);
    return (float*)p;
}

extern "C" void kernel_launch(void* const* d_in, const int* in_sizes, int n_in,
                              void* d_out, int out_size)
{
    const float* seq   = (const float*)d_in[0];
    const float* att   = (const float*)d_in[1];
    const int*   ms    = (const int*)  d_in[2];
    const int*   hts   = (const int*)  d_in[3];
    const float* Wm1   = (const float*)d_in[4];
    const float* Wm2   = (const float*)d_in[5];
    const float* bm    = (const float*)d_in[6];
    const float* Watt  = (const float*)d_in[7];
    const float* batt  = (const float*)d_in[8];
    const float* Wpath = (const float*)d_in[9];
    const float* bpath = (const float*)d_in[10];
    const float* Whead = (const float*)d_in[11];
    const float* bhead = (const float*)d_in[12];
    const float* Wtail = (const float*)d_in[13];
    const float* btail = (const float*)d_in[14];
    const float* Wbil  = (const float*)d_in[15];
    const float* bbil  = (const float*)d_in[16];
    float* out = (float*)d_out;

    float* glob   = symaddr(g_glob);
    float* gA     = symaddr(g_A);
    float* gB     = symaddr(g_B);
    float* q      = symaddr(g_q);
    float* pa     = symaddr(g_pa);
    float* hcat   = symaddr(g_hcat);
    float* tcat   = symaddr(g_tcat);
    float* qW     = symaddr(g_qW);
    float* praw   = symaddr(g_pathraw);
    float* hs     = symaddr(g_hs);
    float* ts     = symaddr(g_ts);
    float* part   = symaddr(g_part);
    float* wTatt  = symaddr(g_wT_att);
    float* wTpath = symaddr(g_wT_path);
    float* wThead = symaddr(g_wT_head);
    float* wTtail = symaddr(g_wT_tail);
    float* wTbil  = symaddr(g_wT_bil);

    const int SMEM_WG = 65536;
    const int SMEM_WB = 131072;
    cudaFuncSetAttribute(wgemm, cudaFuncAttributeMaxDynamicSharedMemorySize, SMEM_WG);
    cudaFuncSetAttribute(wbil,  cudaFuncAttributeMaxDynamicSharedMemorySize, SMEM_WB);

    // --- ordered so launch index 3 (ncu capture slot) is the qW wgemm ---
    k_gather<<<NN*EE, 256>>>(seq, att, ms);                                        // 0
    k_pair<<<NP, 256>>>(hts, ms);                                                  // 1
    ktrans<<<dim3(DIM4/32, DIM2/32), dim3(32,8)>>>(Watt, DIM2, DIM4, DIM4, wTatt); // 2
    // 3: qW = q @ Watt (tf32 mma) <-- ncu profiles this
    wgemm<<<dim3(24,12,1), 256, SMEM_WG>>>(NP, 48, 1, q, DIM2, wTatt, DIM2,
                                           nullptr, nullptr,
                                           qW, DIM4, nullptr, 0, nullptr, 0,
                                           nullptr, 0, 0);

    // Wm1/Wm2 (fp32 for accuracy; feeds edge -> everything downstream)
    sgemm<<<dim3(6,1,12), 256>>>(NN*EE, DD, 64, 12, glob, DD, 0, Wm1, DD, 0,
                                 part, NN*EE);
    reduce_ep<<<(NN*EE*DD+255)/256, 256>>>(part, 12, NN*EE, DD, nullptr, 0,
                                           gA, DD, nullptr, 0);
    sgemm<<<dim3(6,1,12), 256>>>(NN*EE, DD, 64, 12, glob, DD, 0, Wm2, DD, 0,
                                 part, NN*EE);
    reduce_ep<<<(NN*EE*DD+255)/256, 256>>>(part, 12, NN*EE, DD, nullptr, 0,
                                           gB, DD, nullptr, 0);
    k_edge<<<(NN*EE*EE*DD+255)/256, 256>>>(bm);

    // rs = pa @ seq (fp32, batched, split-K 4)
    sgemm<<<dim3(6,3,NN*4), 256>>>(PP, DD, CC/4, 4, pa, CC, (long long)PP*CC,
                                   seq, DD, (long long)CC*DD, part, NP);
    reduce_ep<<<(NP*DD+255)/256, 256>>>(part, 4, NP, DD, nullptr, 0,
                                        hcat + DD, DIM3, tcat + DD, DIM3);

    // score/softmax/path
    k_scorepath<<<NP, 256>>>(hts, batt);

    // path = relu(pathraw @ Wpath + bpath)
    ktrans<<<dim3(DD/32, DIM4/32), dim3(32,8)>>>(Wpath, DIM4, DD, DD, wTpath);
    wgemm<<<dim3(6,12,2), 256, SMEM_WG>>>(NP, 48, 2, praw, DIM4, wTpath, DIM4,
                                          nullptr, nullptr,
                                          nullptr, 0, nullptr, 0, nullptr, 0,
                                          part, NP, DD);
    reduce_ep<<<(NP*DD+255)/256, 256>>>(part, 2, NP, DD, bpath, 1,
                                        hcat + 2*DD, DIM3, tcat + 2*DD, DIM3);

    // hs / ts projections — merged batched launch (z: b=z/2 selects head/tail, s=z%2)
    ktrans<<<dim3(DD/32, DIM3/32), dim3(32,8)>>>(Whead, DIM3, DD, DD, wThead);
    ktrans<<<dim3(DD/32, DIM3/32), dim3(32,8)>>>(Wtail, DIM3, DD, DD, wTtail);
    wgemm<<<dim3(6,12,4), 256, SMEM_WG>>>(NP, 36, 2, hcat, DIM3, wThead, DIM3,
                                          tcat, wTtail,
                                          nullptr, 0, nullptr, 0, nullptr, 0,
                                          part, NP, DD);
    reduce_ep<<<(NP*DD+255)/256, 256>>>(part, 2, NP, DD, bhead, 1, hs, DD, nullptr, 0);
    reduce_ep<<<(NP*DD+255)/256, 256>>>(part + (size_t)2*NP*DD, 2, NP, DD, btail, 1,
                                        ts, DD, nullptr, 0);

    // bilinear head (tf32 mma, fused outer-product A)
    ktrans<<<dim3(4, KBIL/32), dim3(32,8)>>>(Wbil, KBIL, LL, 128, wTbil);
    wbil<<<dim3(12,12), 256, SMEM_WB>>>(wTbil);
    k_bilred<<<(NP*LL+255)/256, 256>>>(bbil, out);
}

// round 11
// speedup vs baseline: 2.4223x; 1.1538x over previous
#include <cuda_runtime.h>
#include <cstdint>
#include <math.h>

#define NN 4
#define CC 512
#define DD 768
#define HH 12
#define EE 20
#define MMENT 4
#define PP 380
#define NP 1520
#define LL 97
#define DIM2 1536
#define DIM3 2304
#define DIM4 3072
#define KBIL 49152
#define NEGV (-1e30f)

// ---------------- static device scratch ----------------
__device__ float g_eemb[NN*EE*MMENT*DD];
__device__ float g_eatt[NN*EE*MMENT*CC];
__device__ float g_glob[NN*EE*DD];
__device__ float g_A[NN*EE*DD];
__device__ float g_B[NN*EE*DD];
__device__ float g_edge[NN*EE*EE*DD];
__device__ float g_pa[NP*CC];
__device__ float g_qW[NP*DIM4];
__device__ float g_hs[NP*DD];
__device__ float g_ts[NP*DD];
__device__ float g_part[4*NP*DD];
// tf32 (u32 bit pattern) GEMM operands
__device__ uint32_t g_q32[NP*DIM2];
__device__ uint32_t g_hcat32[NP*DIM3];
__device__ uint32_t g_tcat32[NP*DIM3];
__device__ uint32_t g_praw32[NP*DIM4];
__device__ uint32_t g_wT_att32[DIM4*DIM2];
__device__ uint32_t g_wT_path32[DD*DIM4];
__device__ uint32_t g_wT_head32[DD*DIM3];
__device__ uint32_t g_wT_tail32[DD*DIM3];
__device__ uint32_t g_wT_bil32[128*KBIL];   // rows 97..127 zero

// ---------------- helpers ----------------
__device__ __forceinline__ uint32_t f2tf32(float f) {
    uint32_t r;
    asm("cvt.rna.tf32.f32 %0, %1;" : "=r"(r) : "f"(f));
    return r;
}
__device__ __forceinline__ void mma_tf32(float* d, uint32_t a0, uint32_t a1,
                                         uint32_t a2, uint32_t a3,
                                         uint32_t b0, uint32_t b1)
{
    asm volatile(
        "mma.sync.aligned.m16n8k8.row.col.f32.tf32.tf32.f32 "
        "{%0,%1,%2,%3}, {%4,%5,%6,%7}, {%8,%9}, {%0,%1,%2,%3};"
        : "+f"(d[0]), "+f"(d[1]), "+f"(d[2]), "+f"(d[3])
        : "r"(a0), "r"(a1), "r"(a2), "r"(a3), "r"(b0), "r"(b1));
}
__device__ __forceinline__ void ldsm4(uint32_t addr, uint32_t& a, uint32_t& b,
                                      uint32_t& c, uint32_t& d)
{
    asm volatile("ldmatrix.sync.aligned.m8n8.x4.shared.b16 {%0,%1,%2,%3}, [%4];"
                 : "=r"(a), "=r"(b), "=r"(c), "=r"(d) : "r"(addr));
}
__device__ __forceinline__ void sts128(uint32_t addr, uint32_t x, uint32_t y,
                                       uint32_t z, uint32_t w)
{
    asm volatile("st.shared.v4.b32 [%0], {%1,%2,%3,%4};"
                 :: "r"(addr), "r"(x), "r"(y), "r"(z), "r"(w) : "memory");
}
__device__ __forceinline__ void cpa16(uint32_t dst, const void* src, uint32_t sz)
{
    asm volatile("cp.async.cg.shared.global [%0], [%1], 16, %2;"
                 :: "r"(dst), "l"(src), "r"(sz) : "memory");
}
#define CP_COMMIT() asm volatile("cp.async.commit_group;" ::: "memory")
#define CP_WAIT0()  asm volatile("cp.async.wait_group 0;" ::: "memory")

// ================ tf32 warp-mma GEMM: cp.async staging + ldmatrix ================
// Operands are pre-converted tf32 (u32). CTA tile 128x128, K-chunk 32, double buffer.
// Swizzle: byte = row*128 + ((col16 ^ (row&7))<<4).
// grid: (N/128, ceil(M/128), Sr*nbatch). z: b=z/Sr, s=z%Sr; b==1 -> A2/BT2.
__global__ void __launch_bounds__(256,2) wgemm(
    int M, int nchunks, int Sr,
    const uint32_t* __restrict__ A, int lda,
    const uint32_t* __restrict__ BT, int ldbt,
    const uint32_t* __restrict__ A2,
    const uint32_t* __restrict__ BT2,
    float* __restrict__ dst1, int ld1,
    const float* __restrict__ bias, int relu,
    float* __restrict__ dst2, int ld2,
    float* __restrict__ part, int Mtot, int Nn)
{
    extern __shared__ float smf[];
    uint32_t sbase = (uint32_t)__cvta_generic_to_shared(smf);
    int tid = threadIdx.x;
    int lane = tid & 31, wid = tid >> 5;
    int wm = wid >> 2, wn = wid & 3;
    int m0 = blockIdx.y*128, n0 = blockIdx.x*128;
    int z = blockIdx.z;
    int s = z % Sr, b = z / Sr;
    const uint32_t* Ause  = b ? A2  : A;
    const uint32_t* BTuse = b ? BT2 : BT;
    int kbase = s*nchunks*32;

    // cp.async staging coords: 4 rows per thread (r0g + 32t), 16B col qf
    int r0g = tid >> 3;
    int qf  = tid & 7;
    uint32_t dstoff[4];
    const uint32_t* aS[4]; uint32_t aSz[4];
    const uint32_t* bS[4];
    #pragma unroll
    for (int t = 0; t < 4; t++) {
        int r = r0g + t*32;
        dstoff[t] = (uint32_t)(r*128) + (uint32_t)((qf ^ (r & 7)) << 4);
        int rm = m0 + r;
        int rcl = rm < M ? rm : (M-1);
        aS[t]  = Ause + (size_t)rcl*lda + kbase + qf*4;
        aSz[t] = (rm < M) ? 16u : 0u;
        bS[t]  = BTuse + (size_t)(n0 + r)*ldbt + kbase + qf*4;
    }

    // ldmatrix coords
    int lg = lane >> 3, l7 = lane & 7;
    int arow = wm*64 + ((lg & 1) << 3) + l7;
    int brow = wn*32 + ((lg >> 1) << 3) + l7;
    uint32_t acol[4], bcol[4];
    #pragma unroll
    for (int ks = 0; ks < 4; ks++) {
        acol[ks] = (uint32_t)(((((ks<<1) + (lg>>1)) ^ (arow & 7))) << 4);
        bcol[ks] = (uint32_t)(((((ks<<1) + (lg&1))  ^ (brow & 7))) << 4);
    }
    uint32_t aBase = sbase + (uint32_t)(arow*128);
    uint32_t bBase = sbase + 16384u + (uint32_t)(brow*128);

    float acc[4][4][4];
    #pragma unroll
    for (int i = 0; i < 4; i++)
        #pragma unroll
        for (int j = 0; j < 4; j++)
            #pragma unroll
            for (int k = 0; k < 4; k++) acc[i][j][k] = 0.f;

    auto issue = [&](int kc, int buf) {
        uint32_t off = sbase + (uint32_t)(buf*32768);
        int ko = kc*32;
        #pragma unroll
        for (int t = 0; t < 4; t++) {
            cpa16(off + dstoff[t], aS[t] + ko, aSz[t]);
            cpa16(off + 16384u + dstoff[t], bS[t] + ko, 16u);
        }
        CP_COMMIT();
    };
    auto compute = [&](int buf) {
        uint32_t ab = aBase + (uint32_t)(buf*32768);
        uint32_t bb = bBase + (uint32_t)(buf*32768);
        #pragma unroll
        for (int ks = 0; ks < 4; ks++) {
            uint32_t bfr[4][2];
            #pragma unroll
            for (int ntp = 0; ntp < 2; ntp++)
                ldsm4(bb + (uint32_t)(ntp*2048) + bcol[ks],
                      bfr[2*ntp][0], bfr[2*ntp][1], bfr[2*ntp+1][0], bfr[2*ntp+1][1]);
            #pragma unroll
            for (int mt = 0; mt < 4; mt++) {
                uint32_t a0, a1, a2, a3;
                ldsm4(ab + (uint32_t)(mt*2048) + acol[ks], a0, a1, a2, a3);
                #pragma unroll
                for (int nt = 0; nt < 4; nt++)
                    mma_tf32(acc[mt][nt], a0, a1, a2, a3, bfr[nt][0], bfr[nt][1]);
            }
        }
    };

    issue(0, 0);
    for (int kc = 0; kc < nchunks; kc++) {
        CP_WAIT0();
        __syncthreads();   // all chunk-kc data visible; all compute(kc-1) done
        if (kc + 1 < nchunks) issue(kc + 1, (kc + 1) & 1);
        compute(kc & 1);
    }

    int eg = lane >> 2, ec = lane & 3;
    #pragma unroll
    for (int mt = 0; mt < 4; mt++) {
        int r0 = m0 + wm*64 + mt*16 + eg;
        int r1 = r0 + 8;
        #pragma unroll
        for (int nt = 0; nt < 4; nt++) {
            int c0 = n0 + wn*32 + nt*8 + 2*ec;
            if (part) {
                float* p0 = part + ((size_t)z*Mtot + r0)*Nn + c0;
                float* p1 = part + ((size_t)z*Mtot + r1)*Nn + c0;
                if (r0 < M) { p0[0] = acc[mt][nt][0]; p0[1] = acc[mt][nt][1]; }
                if (r1 < M) { p1[0] = acc[mt][nt][2]; p1[1] = acc[mt][nt][3]; }
            } else {
                float b0 = bias ? bias[c0] : 0.f;
                float b1 = bias ? bias[c0+1] : 0.f;
                float v0 = acc[mt][nt][0] + b0, v1 = acc[mt][nt][1] + b1;
                float v2 = acc[mt][nt][2] + b0, v3 = acc[mt][nt][3] + b1;
                if (relu) { v0=fmaxf(v0,0.f); v1=fmaxf(v1,0.f); v2=fmaxf(v2,0.f); v3=fmaxf(v3,0.f); }
                if (r0 < M) {
                    dst1[(size_t)r0*ld1 + c0] = v0; dst1[(size_t)r0*ld1 + c0+1] = v1;
                    if (dst2) { dst2[(size_t)r0*ld2 + c0] = v0; dst2[(size_t)r0*ld2 + c0+1] = v1; }
                }
                if (r1 < M) {
                    dst1[(size_t)r1*ld1 + c0] = v2; dst1[(size_t)r1*ld1 + c0+1] = v3;
                    if (dst2) { dst2[(size_t)r1*ld2 + c0] = v2; dst2[(size_t)r1*ld2 + c0+1] = v3; }
                }
            }
        }
    }
}

// ===== bilinear: part[kb] = (hs_kb ⊗ ts_kb) @ WbilT[kb]; B via cp.async, A on the fly =====
__global__ void __launch_bounds__(256) wbil(const uint32_t* __restrict__ BT)
{
    extern __shared__ float smf[];
    uint32_t sbase = (uint32_t)__cvta_generic_to_shared(smf);
    float* hs_s = smf + 16384;           // [128][64]
    float* ts_s = smf + 16384 + 8192;    // [128][64]
    int tid = threadIdx.x;
    int lane = tid & 31, wid = tid >> 5;
    int wm = wid >> 2, wn = wid & 3;
    int m0 = blockIdx.x*128;
    int kb = blockIdx.y;

    #pragma unroll
    for (int t = 0; t < 8; t++) {
        int idx = tid + t*256;
        int r = idx >> 4, qi = idx & 15;
        int rg = m0 + r;
        float4 h = make_float4(0.f,0.f,0.f,0.f), v = h;
        if (rg < NP) {
            h = *(const float4*)(g_hs + (size_t)rg*DD + kb*64 + qi*4);
            v = *(const float4*)(g_ts + (size_t)rg*DD + kb*64 + qi*4);
        }
        *(float4*)(hs_s + r*64 + qi*4) = h;
        *(float4*)(ts_s + r*64 + qi*4) = v;
    }
    __syncthreads();

    int r0g = tid >> 3;
    int qf  = tid & 7;
    uint32_t dstoff[4];
    const uint32_t* bS[4];
    #pragma unroll
    for (int t = 0; t < 4; t++) {
        int r = r0g + t*32;
        dstoff[t] = (uint32_t)(r*128) + (uint32_t)((qf ^ (r & 7)) << 4);
        bS[t] = BT + (size_t)r*KBIL + kb*4096 + qf*4;
    }

    int lg = lane >> 3, l7 = lane & 7;
    int arow = wm*64 + ((lg & 1) << 3) + l7;
    int brow = wn*32 + ((lg >> 1) << 3) + l7;
    uint32_t acol[4], bcol[4];
    #pragma unroll
    for (int ks = 0; ks < 4; ks++) {
        acol[ks] = (uint32_t)(((((ks<<1) + (lg>>1)) ^ (arow & 7))) << 4);
        bcol[ks] = (uint32_t)(((((ks<<1) + (lg&1))  ^ (brow & 7))) << 4);
    }
    uint32_t aBase = sbase + (uint32_t)(arow*128);
    uint32_t bBase = sbase + 16384u + (uint32_t)(brow*128);

    float acc[4][4][4];
    #pragma unroll
    for (int i = 0; i < 4; i++)
        #pragma unroll
        for (int j = 0; j < 4; j++)
            #pragma unroll
            for (int k = 0; k < 4; k++) acc[i][j][k] = 0.f;

    float4 av[4];
    auto issueB = [&](int kc, int buf) {
        uint32_t off = sbase + (uint32_t)(buf*32768) + 16384u;
        int ko = kc*32;
        #pragma unroll
        for (int t = 0; t < 4; t++)
            cpa16(off + dstoff[t], bS[t] + ko, 16u);
        CP_COMMIT();
    };
    auto gatherA = [&](int kc) {
        int ii = kc >> 1;
        int j0 = ((kc & 1) << 5) + qf*4;
        #pragma unroll
        for (int t = 0; t < 4; t++) {
            int r = r0g + t*32;
            float hv = hs_s[r*64 + ii];
            float4 tv = *(const float4*)(ts_s + r*64 + j0);
            av[t] = make_float4(hv*tv.x, hv*tv.y, hv*tv.z, hv*tv.w);
        }
    };
    auto storeA = [&](int buf) {
        uint32_t off = sbase + (uint32_t)(buf*32768);
        #pragma unroll
        for (int t = 0; t < 4; t++)
            sts128(off + dstoff[t],
                   f2tf32(av[t].x), f2tf32(av[t].y), f2tf32(av[t].z), f2tf32(av[t].w));
    };
    auto compute = [&](int buf) {
        uint32_t ab = aBase + (uint32_t)(buf*32768);
        uint32_t bb = bBase + (uint32_t)(buf*32768);
        #pragma unroll
        for (int ks = 0; ks < 4; ks++) {
            uint32_t bfr[4][2];
            #pragma unroll
            for (int ntp = 0; ntp < 2; ntp++)
                ldsm4(bb + (uint32_t)(ntp*2048) + bcol[ks],
                      bfr[2*ntp][0], bfr[2*ntp][1], bfr[2*ntp+1][0], bfr[2*ntp+1][1]);
            #pragma unroll
            for (int mt = 0; mt < 4; mt++) {
                uint32_t a0, a1, a2, a3;
                ldsm4(ab + (uint32_t)(mt*2048) + acol[ks], a0, a1, a2, a3);
                #pragma unroll
                for (int nt = 0; nt < 4; nt++)
                    mma_tf32(acc[mt][nt], a0, a1, a2, a3, bfr[nt][0], bfr[nt][1]);
            }
        }
    };

    issueB(0, 0);
    gatherA(0);
    for (int kc = 0; kc < 128; kc++) {
        int buf = kc & 1;
        storeA(buf);
        CP_WAIT0();
        __syncthreads();
        if (kc + 1 < 128) { issueB(kc + 1, buf ^ 1); gatherA(kc + 1); }
        compute(buf);
    }

    int eg = lane >> 2, ec = lane & 3;
    #pragma unroll
    for (int mt = 0; mt < 4; mt++) {
        int r0 = m0 + wm*64 + mt*16 + eg;
        int r1 = r0 + 8;
        #pragma unroll
        for (int nt = 0; nt < 4; nt++) {
            int c0 = wn*32 + nt*8 + 2*ec;
            #pragma unroll
            for (int u = 0; u < 2; u++) {
                int col = c0 + u;
                if (col < LL) {
                    if (r0 < NP) g_part[((size_t)kb*NP + r0)*LL + col] = acc[mt][nt][u];
                    if (r1 < NP) g_part[((size_t)kb*NP + r1)*LL + col] = acc[mt][nt][2+u];
                }
            }
        }
    }
}

// ================= transpose -> tf32: out[c][r] = tf32(in[r][c]); c in [C,Cout) -> 0 =================
__global__ void ktrans(const float* __restrict__ in, int R, int C, int Cout,
                       uint32_t* __restrict__ out)
{
    __shared__ float t[32][33];
    int c0 = blockIdx.x*32, r0 = blockIdx.y*32;
    int tx = threadIdx.x, ty = threadIdx.y;
    #pragma unroll
    for (int j = 0; j < 32; j += 8) {
        int r = r0 + ty + j, c = c0 + tx;
        t[ty+j][tx] = (r < R && c < C) ? in[(size_t)r*C + c] : 0.f;
    }
    __syncthreads();
    #pragma unroll
    for (int j = 0; j < 32; j += 8) {
        int c = c0 + ty + j, r = r0 + tx;
        if (c < Cout && r < R) out[(size_t)c*R + r] = f2tf32(t[tx][ty+j]);
    }
}

// ---------------- K1: gather ----------------
__global__ void k_gather(const float* __restrict__ seq, const float* __restrict__ att,
                         const int* __restrict__ ms)
{
    int ne = blockIdx.x;
    int n  = ne / EE;
    int tid = threadIdx.x;
    for (int m = 0; m < MMENT; m++) {
        int pos = ms[ne*MMENT + m] + 1;
        const float* srow = seq + ((size_t)n*CC + pos)*DD;
        float* erow = g_eemb + ((size_t)ne*MMENT + m)*DD;
        for (int d = tid; d < DD; d += blockDim.x) erow[d] = srow[d];
        float* arow = g_eatt + ((size_t)ne*MMENT + m)*CC;
        for (int c = tid; c < CC; c += blockDim.x) {
            float s = 0.f;
            #pragma unroll
            for (int h = 0; h < HH; h++)
                s += att[(((size_t)n*HH + h)*CC + pos)*CC + c];
            arow[c] = s * (1.0f/HH);
        }
    }
    __syncthreads();
    for (int d = tid; d < DD; d += blockDim.x) {
        float x0 = g_eemb[((size_t)ne*MMENT+0)*DD+d];
        float x1 = g_eemb[((size_t)ne*MMENT+1)*DD+d];
        float x2 = g_eemb[((size_t)ne*MMENT+2)*DD+d];
        float x3 = g_eemb[((size_t)ne*MMENT+3)*DD+d];
        float mx = fmaxf(fmaxf(x0,x1), fmaxf(x2,x3));
        float s = expf(x0-mx)+expf(x1-mx)+expf(x2-mx)+expf(x3-mx);
        g_glob[(size_t)ne*DD + d] = mx + logf(s);
    }
}

// ---------------- K3: edge ----------------
__global__ void k_edge(const float* __restrict__ bm)
{
    int idx = blockIdx.x*blockDim.x + threadIdx.x;
    const int total = NN*EE*EE*DD;
    if (idx >= total) return;
    int d = idx % DD;
    int v = (idx / DD) % EE;
    int u = (idx / (DD*EE)) % EE;
    int n = idx / (DD*EE*EE);
    float val = g_A[((size_t)n*EE+u)*DD+d] + g_B[((size_t)n*EE+v)*DD+d] + bm[d];
    g_edge[idx] = fmaxf(val, 0.f);
}

// ---------------- K4: pair attention ----------------
__global__ void k_pair(const int* __restrict__ hts, const int* __restrict__ ms)
{
    int r = blockIdx.x;
    int n = r / PP;
    int h = hts[r*2 + 0];
    int t = hts[r*2 + 1];
    __shared__ int   s_ph[MMENT], s_pt[MMENT];
    __shared__ float s_phatt[MMENT], s_ptatt[MMENT];
    __shared__ float s_red[256];
    int tid = threadIdx.x;
    if (tid < MMENT) {
        s_ph[tid] = ms[((size_t)n*EE+h)*MMENT + tid] + 1;
        s_pt[tid] = ms[((size_t)n*EE+t)*MMENT + tid] + 1;
    }
    __syncthreads();
    if (tid < 2*MMENT) {
        int m2 = tid & (MMENT-1);
        float s = 0.f;
        if (tid < MMENT) {
            for (int m1 = 0; m1 < MMENT; m1++)
                s += g_eatt[((size_t)(n*EE+h)*MMENT+m1)*CC + s_pt[m2]];
            s_phatt[m2] = s * (1.f/MMENT);
        } else {
            for (int m1 = 0; m1 < MMENT; m1++)
                s += g_eatt[((size_t)(n*EE+t)*MMENT+m1)*CC + s_ph[m2]];
            s_ptatt[m2] = s * (1.f/MMENT);
        }
    }
    __syncthreads();
    if (tid == 0) {
        float sh = 1e-5f, st = 1e-5f;
        for (int m = 0; m < MMENT; m++) { sh += s_phatt[m]; st += s_ptatt[m]; }
        float ih = 1.f/sh, it = 1.f/st;
        for (int m = 0; m < MMENT; m++) { s_phatt[m] *= ih; s_ptatt[m] *= it; }
    }
    __syncthreads();
    for (int d = tid; d < DD; d += blockDim.x) {
        float nh = 0.f, nt = 0.f;
        #pragma unroll
        for (int m = 0; m < MMENT; m++) {
            nh += s_ptatt[m]*g_eemb[((size_t)(n*EE+h)*MMENT+m)*DD + d];
            nt += s_phatt[m]*g_eemb[((size_t)(n*EE+t)*MMENT+m)*DD + d];
        }
        uint32_t nh32 = f2tf32(nh), nt32 = f2tf32(nt);
        g_hcat32[(size_t)r*DIM3 + d] = nh32;
        g_tcat32[(size_t)r*DIM3 + d] = nt32;
        g_q32[(size_t)r*DIM2 + d]      = nh32;
        g_q32[(size_t)r*DIM2 + DD + d] = nt32;
    }
    float local = 0.f;
    for (int c = tid; c < CC; c += blockDim.x) {
        float na = 0.f, ta = 0.f;
        #pragma unroll
        for (int m = 0; m < MMENT; m++) {
            na += s_ptatt[m]*g_eatt[((size_t)(n*EE+h)*MMENT+m)*CC + c];
            ta += s_phatt[m]*g_eatt[((size_t)(n*EE+t)*MMENT+m)*CC + c];
        }
        float v = na*ta;
        g_pa[(size_t)r*CC + c] = v;
        local += v;
    }
    s_red[tid] = local;
    __syncthreads();
    for (int off = 128; off > 0; off >>= 1) {
        if (tid < off) s_red[tid] += s_red[tid+off];
        __syncthreads();
    }
    float inv = 1.f/(s_red[0] + 1e-5f);
    for (int c = tid; c < CC; c += blockDim.x)
        g_pa[(size_t)r*CC + c] *= inv;
}

// ---------------- fp32 SGEMM (Wm1/Wm2, rs) ----------------
__global__ void __launch_bounds__(256) sgemm(
    int M, int Nn, int Kc, int S,
    const float* __restrict__ A, int lda, long long sA,
    const float* __restrict__ B, int ldb, long long sB,
    float* __restrict__ part, int Mtot)
{
    int b = blockIdx.z / S;
    int s = blockIdx.z % S;
    const float* Ab = A + (size_t)b*sA + (size_t)s*Kc;
    const float* Bb = B + (size_t)b*sB + (size_t)s*Kc*ldb;
    int m0 = blockIdx.y*128, n0 = blockIdx.x*128;
    __shared__ float As[8][128];
    __shared__ float Bs[8][128];
    int tid = threadIdx.x;
    int arow = tid >> 1, ak = (tid & 1)*4;
    int bk = tid >> 5,  bn = (tid & 31)*4;
    int tx = tid & 15,  ty = tid >> 4;
    float acc[8][8];
    #pragma unroll
    for (int i = 0; i < 8; i++)
        #pragma unroll
        for (int j = 0; j < 8; j++) acc[i][j] = 0.f;
    for (int k0 = 0; k0 < Kc; k0 += 8) {
        float4 av = make_float4(0.f,0.f,0.f,0.f);
        if (m0 + arow < M)
            av = *(const float4*)(Ab + (size_t)(m0+arow)*lda + k0 + ak);
        float4 bvv = *(const float4*)(Bb + (size_t)(k0+bk)*ldb + n0 + bn);
        __syncthreads();
        As[ak+0][arow] = av.x; As[ak+1][arow] = av.y;
        As[ak+2][arow] = av.z; As[ak+3][arow] = av.w;
        *(float4*)&Bs[bk][bn] = bvv;
        __syncthreads();
        #pragma unroll
        for (int kk = 0; kk < 8; kk++) {
            float a[8], bb[8];
            *(float4*)(a)    = *(const float4*)&As[kk][ty*8];
            *(float4*)(a+4)  = *(const float4*)&As[kk][ty*8+4];
            *(float4*)(bb)   = *(const float4*)&Bs[kk][tx*8];
            *(float4*)(bb+4) = *(const float4*)&Bs[kk][tx*8+4];
            #pragma unroll
            for (int i = 0; i < 8; i++)
                #pragma unroll
                for (int j = 0; j < 8; j++)
                    acc[i][j] += a[i]*bb[j];
        }
    }
    float* pbase = part + ((size_t)s*Mtot + (size_t)b*M)*Nn;
    #pragma unroll
    for (int i = 0; i < 8; i++) {
        int r = m0 + ty*8 + i;
        if (r < M) {
            float* prow = pbase + (size_t)r*Nn + n0 + tx*8;
            *(float4*)(prow)   = make_float4(acc[i][0],acc[i][1],acc[i][2],acc[i][3]);
            *(float4*)(prow+4) = make_float4(acc[i][4],acc[i][5],acc[i][6],acc[i][7]);
        }
    }
}

// reduce + bias + relu; tf32out: dst pointers are uint32_t* (tf32)
__global__ void reduce_ep(const float* __restrict__ part, int S, int Mtot, int Nn,
                          const float* __restrict__ bias, int dorelu, int tf32out,
                          float* __restrict__ dst1, int ld1,
                          float* __restrict__ dst2, int ld2)
{
    int idx = blockIdx.x*blockDim.x + threadIdx.x;
    if (idx >= Mtot*Nn) return;
    int r = idx / Nn, c = idx % Nn;
    float v = 0.f;
    for (int s = 0; s < S; s++)
        v += part[((size_t)s*Mtot + r)*Nn + c];
    if (bias) v += bias[c];
    if (dorelu) v = fmaxf(v, 0.f);
    if (tf32out) {
        uint32_t u = f2tf32(v);
        ((uint32_t*)dst1)[(size_t)r*ld1 + c] = u;
        if (dst2) ((uint32_t*)dst2)[(size_t)r*ld2 + c] = u;
    } else {
        dst1[(size_t)r*ld1 + c] = v;
        if (dst2) dst2[(size_t)r*ld2 + c] = v;
    }
}

// ---------------- K7: score + masked softmax + path ----------------
__global__ void k_scorepath(const int* __restrict__ hts, const float* __restrict__ battp)
{
    int r = blockIdx.x;
    int n = r / PP;
    int h = hts[r*2 + 0];
    int t = hts[r*2 + 1];
    __shared__ float s_q[DIM4];
    __shared__ float s_score[EE];
    __shared__ float s_aw[EE];
    int tid = threadIdx.x;
    for (int i = tid; i < DIM4; i += blockDim.x)
        s_q[i] = g_qW[(size_t)r*DIM4 + i];
    __syncthreads();
    int warp = tid >> 5, lane = tid & 31;
    float batt = battp[0];
    for (int v = warp; v < EE; v += 8) {
        const float* e1 = g_edge + ((size_t)((n*EE+h)*EE + v))*DD;
        const float* e2 = g_edge + ((size_t)((n*EE+v)*EE + t))*DD;
        const float* e3 = g_edge + ((size_t)((n*EE+t)*EE + v))*DD;
        const float* e4 = g_edge + ((size_t)((n*EE+v)*EE + h))*DD;
        float s = 0.f;
        for (int d = lane; d < DD; d += 32)
            s += s_q[d]*e1[d] + s_q[DD+d]*e2[d] + s_q[2*DD+d]*e3[d] + s_q[3*DD+d]*e4[d];
        #pragma unroll
        for (int off = 16; off; off >>= 1)
            s += __shfl_down_sync(0xffffffffu, s, off);
        if (lane == 0) s_score[v] = s + batt;
    }
    __syncthreads();
    if (tid == 0) {
        float mx = -1e38f;
        for (int v = 0; v < EE; v++) {
            float sc = (v == h || v == t) ? NEGV : s_score[v];
            s_score[v] = sc;
            mx = fmaxf(mx, sc);
        }
        float sum = 0.f;
        for (int v = 0; v < EE; v++) {
            float e = expf(s_score[v] - mx);
            s_aw[v] = e;
            sum += e;
        }
        float inv = 1.f/sum;
        for (int v = 0; v < EE; v++) s_aw[v] *= inv;
    }
    __syncthreads();
    for (int idx = tid; idx < DIM4; idx += blockDim.x) {
        int kk = idx / DD, d = idx % DD;
        const float* ep;
        size_t strideV;
        if (kk == 0)      { ep = g_edge + ((size_t)((n*EE+h)*EE))*DD + d;   strideV = DD; }
        else if (kk == 1) { ep = g_edge + ((size_t)(n*EE)*EE + t)*DD + d;   strideV = (size_t)EE*DD; }
        else if (kk == 2) { ep = g_edge + ((size_t)((n*EE+t)*EE))*DD + d;   strideV = DD; }
        else              { ep = g_edge + ((size_t)(n*EE)*EE + h)*DD + d;   strideV = (size_t)EE*DD; }
        float acc = 0.f;
        #pragma unroll 4
        for (int v = 0; v < EE; v++)
            acc += s_aw[v]*ep[(size_t)v*strideV];
        g_praw32[(size_t)r*DIM4 + idx] = f2tf32(acc);
    }
}

__global__ void k_bilred(const float* __restrict__ bbil, float* __restrict__ out)
{
    int idx = blockIdx.x*blockDim.x + threadIdx.x;
    if (idx >= NP*LL) return;
    int r = idx / LL, l = idx % LL;
    float v = bbil[l];
    #pragma unroll
    for (int k = 0; k < 12; k++)
        v += g_part[((size_t)k*NP + r)*LL + l];
    out[idx] = v;
}

// ---------------- launcher ----------------
static void* symaddr(const void* sym)
{
    void* p = nullptr;
    cudaGetSymbolAddress(&p, sym);
    return p;
}

extern "C" void kernel_launch(void* const* d_in, const int* in_sizes, int n_in,
                              void* d_out, int out_size)
{
    const float* seq   = (const float*)d_in[0];
    const float* att   = (const float*)d_in[1];
    const int*   ms    = (const int*)  d_in[2];
    const int*   hts   = (const int*)  d_in[3];
    const float* Wm1   = (const float*)d_in[4];
    const float* Wm2   = (const float*)d_in[5];
    const float* bm    = (const float*)d_in[6];
    const float* Watt  = (const float*)d_in[7];
    const float* batt  = (const float*)d_in[8];
    const float* Wpath = (const float*)d_in[9];
    const float* bpath = (const float*)d_in[10];
    const float* Whead = (const float*)d_in[11];
    const float* bhead = (const float*)d_in[12];
    const float* Wtail = (const float*)d_in[13];
    const float* btail = (const float*)d_in[14];
    const float* Wbil  = (const float*)d_in[15];
    const float* bbil  = (const float*)d_in[16];
    float* out = (float*)d_out;

    float*    glob   = (float*)symaddr(g_glob);
    float*    gA     = (float*)symaddr(g_A);
    float*    gB     = (float*)symaddr(g_B);
    float*    pa     = (float*)symaddr(g_pa);
    float*    qW     = (float*)symaddr(g_qW);
    float*    hs     = (float*)symaddr(g_hs);
    float*    ts     = (float*)symaddr(g_ts);
    float*    part   = (float*)symaddr(g_part);
    uint32_t* q32    = (uint32_t*)symaddr(g_q32);
    uint32_t* hcat32 = (uint32_t*)symaddr(g_hcat32);
    uint32_t* tcat32 = (uint32_t*)symaddr(g_tcat32);
    uint32_t* praw32 = (uint32_t*)symaddr(g_praw32);
    uint32_t* wTatt  = (uint32_t*)symaddr(g_wT_att32);
    uint32_t* wTpath = (uint32_t*)symaddr(g_wT_path32);
    uint32_t* wThead = (uint32_t*)symaddr(g_wT_head32);
    uint32_t* wTtail = (uint32_t*)symaddr(g_wT_tail32);
    uint32_t* wTbil  = (uint32_t*)symaddr(g_wT_bil32);

    const int SMEM_WG = 65536;
    const int SMEM_WB = 131072;
    cudaFuncSetAttribute(wgemm, cudaFuncAttributeMaxDynamicSharedMemorySize, SMEM_WG);
    cudaFuncSetAttribute(wbil,  cudaFuncAttributeMaxDynamicSharedMemorySize, SMEM_WB);

    // --- ordered so launch index 3 (ncu capture slot) is the qW wgemm ---
    k_gather<<<NN*EE, 256>>>(seq, att, ms);                                        // 0
    k_pair<<<NP, 256>>>(hts, ms);                                                  // 1
    ktrans<<<dim3(DIM4/32, DIM2/32), dim3(32,8)>>>(Watt, DIM2, DIM4, DIM4, wTatt); // 2
    // 3: qW = q @ Watt (tf32 mma + cp.async) <-- ncu profiles this
    wgemm<<<dim3(24,12,1), 256, SMEM_WG>>>(NP, 48, 1, q32, DIM2, wTatt, DIM2,
                                           nullptr, nullptr,
                                           qW, DIM4, nullptr, 0, nullptr, 0,
                                           nullptr, 0, 0);

    // Wm1/Wm2 (fp32 for accuracy; feeds edge -> everything downstream)
    sgemm<<<dim3(6,1,12), 256>>>(NN*EE, DD, 64, 12, glob, DD, 0, Wm1, DD, 0,
                                 part, NN*EE);
    reduce_ep<<<(NN*EE*DD+255)/256, 256>>>(part, 12, NN*EE, DD, nullptr, 0, 0,
                                           gA, DD, nullptr, 0);
    sgemm<<<dim3(6,1,12), 256>>>(NN*EE, DD, 64, 12, glob, DD, 0, Wm2, DD, 0,
                                 part, NN*EE);
    reduce_ep<<<(NN*EE*DD+255)/256, 256>>>(part, 12, NN*EE, DD, nullptr, 0, 0,
                                           gB, DD, nullptr, 0);
    k_edge<<<(NN*EE*EE*DD+255)/256, 256>>>(bm);

    // rs = pa @ seq (fp32, batched, split-K 4) -> tf32 into hcat32/tcat32 [D,2D)
    sgemm<<<dim3(6,3,NN*4), 256>>>(PP, DD, CC/4, 4, pa, CC, (long long)PP*CC,
                                   seq, DD, (long long)CC*DD, part, NP);
    reduce_ep<<<(NP*DD+255)/256, 256>>>(part, 4, NP, DD, nullptr, 0, 1,
                                        (float*)(hcat32 + DD), DIM3,
                                        (float*)(tcat32 + DD), DIM3);

    // score/softmax/path (writes praw32 tf32)
    k_scorepath<<<NP, 256>>>(hts, batt);

    // path = relu(pathraw @ Wpath + bpath) -> tf32 into hcat32/tcat32 [2D,3D)
    ktrans<<<dim3(DD/32, DIM4/32), dim3(32,8)>>>(Wpath, DIM4, DD, DD, wTpath);
    wgemm<<<dim3(6,12,2), 256, SMEM_WG>>>(NP, 48, 2, praw32, DIM4, wTpath, DIM4,
                                          nullptr, nullptr,
                                          nullptr, 0, nullptr, 0, nullptr, 0,
                                          part, NP, DD);
    reduce_ep<<<(NP*DD+255)/256, 256>>>(part, 2, NP, DD, bpath, 1, 1,
                                        (float*)(hcat32 + 2*DD), DIM3,
                                        (float*)(tcat32 + 2*DD), DIM3);

    // hs / ts projections — merged batched launch
    ktrans<<<dim3(DD/32, DIM3/32), dim3(32,8)>>>(Whead, DIM3, DD, DD, wThead);
    ktrans<<<dim3(DD/32, DIM3/32), dim3(32,8)>>>(Wtail, DIM3, DD, DD, wTtail);
    wgemm<<<dim3(6,12,4), 256, SMEM_WG>>>(NP, 36, 2, hcat32, DIM3, wThead, DIM3,
                                          tcat32, wTtail,
                                          nullptr, 0, nullptr, 0, nullptr, 0,
                                          part, NP, DD);
    reduce_ep<<<(NP*DD+255)/256, 256>>>(part, 2, NP, DD, bhead, 1, 0,
                                        hs, DD, nullptr, 0);
    reduce_ep<<<(NP*DD+255)/256, 256>>>(part + (size_t)2*NP*DD, 2, NP, DD, btail, 1, 0,
                                        ts, DD, nullptr, 0);

    // bilinear head (tf32 mma, cp.async B, fused outer-product A)
    ktrans<<<dim3(4, KBIL/32), dim3(32,8)>>>(Wbil, KBIL, LL, 128, wTbil);
    wbil<<<dim3(12,12), 256, SMEM_WB>>>(wTbil);
    k_bilred<<<(NP*LL+255)/256, 256>>>(bbil, out);
}

// round 12
// speedup vs baseline: 2.6008x; 1.0737x over previous
#include <cuda_runtime.h>
#include <cstdint>
#include <math.h>

#define NN 4
#define CC 512
#define DD 768
#define HH 12
#define EE 20
#define MMENT 4
#define PP 380
#define NP 1520
#define LL 97
#define DIM2 1536
#define DIM3 2304
#define DIM4 3072
#define KBIL 49152
#define NEGV (-1e30f)

// ---------------- static device scratch ----------------
__device__ float g_eemb[NN*EE*MMENT*DD];
__device__ float g_eatt[NN*EE*MMENT*CC];
__device__ float g_glob[NN*EE*DD];
__device__ float g_A[NN*EE*DD];
__device__ float g_B[NN*EE*DD];
__device__ float g_edge[NN*EE*EE*DD];
__device__ float g_pa[NP*CC];
__device__ float g_qW[NP*DIM4];
__device__ float g_hs[NP*DD];
__device__ float g_ts[NP*DD];
__device__ float g_part[4*NP*DD];
// tf32 (u32 bit pattern) GEMM operands
__device__ uint32_t g_pa32[NP*CC];
__device__ uint32_t g_seqT32[NN*DD*CC];
__device__ uint32_t g_q32[NP*DIM2];
__device__ uint32_t g_hcat32[NP*DIM3];
__device__ uint32_t g_tcat32[NP*DIM3];
__device__ uint32_t g_praw32[NP*DIM4];
__device__ uint32_t g_wT_att32[DIM4*DIM2];
__device__ uint32_t g_wT_path32[DD*DIM4];
__device__ uint32_t g_wT_head32[DD*DIM3];
__device__ uint32_t g_wT_tail32[DD*DIM3];
__device__ uint32_t g_wT_bil32[128*KBIL];   // rows 97..127 zero

// ---------------- helpers ----------------
__device__ __forceinline__ uint32_t f2tf32(float f) {
    uint32_t r;
    asm("cvt.rna.tf32.f32 %0, %1;" : "=r"(r) : "f"(f));
    return r;
}
__device__ __forceinline__ void mma_tf32(float* d, uint32_t a0, uint32_t a1,
                                         uint32_t a2, uint32_t a3,
                                         uint32_t b0, uint32_t b1)
{
    asm volatile(
        "mma.sync.aligned.m16n8k8.row.col.f32.tf32.tf32.f32 "
        "{%0,%1,%2,%3}, {%4,%5,%6,%7}, {%8,%9}, {%0,%1,%2,%3};"
        : "+f"(d[0]), "+f"(d[1]), "+f"(d[2]), "+f"(d[3])
        : "r"(a0), "r"(a1), "r"(a2), "r"(a3), "r"(b0), "r"(b1));
}
__device__ __forceinline__ void ldsm4(uint32_t addr, uint32_t& a, uint32_t& b,
                                      uint32_t& c, uint32_t& d)
{
    asm volatile("ldmatrix.sync.aligned.m8n8.x4.shared.b16 {%0,%1,%2,%3}, [%4];"
                 : "=r"(a), "=r"(b), "=r"(c), "=r"(d) : "r"(addr));
}
__device__ __forceinline__ void sts128(uint32_t addr, uint32_t x, uint32_t y,
                                       uint32_t z, uint32_t w)
{
    asm volatile("st.shared.v4.b32 [%0], {%1,%2,%3,%4};"
                 :: "r"(addr), "r"(x), "r"(y), "r"(z), "r"(w) : "memory");
}
__device__ __forceinline__ void cpa16(uint32_t dst, const void* src, uint32_t sz)
{
    asm volatile("cp.async.cg.shared.global [%0], [%1], 16, %2;"
                 :: "r"(dst), "l"(src), "r"(sz) : "memory");
}
#define CP_COMMIT() asm volatile("cp.async.commit_group;" ::: "memory")
#define CP_WAIT0()  asm volatile("cp.async.wait_group 0;" ::: "memory")

// ================ tf32 warp-mma GEMM: cp.async staging + ldmatrix ================
// CTA 128x128, K-chunk 32, double buffer. Swizzle: byte = row*128 + ((col16 ^ (row&7))<<4).
// grid: (N/128, ceil(M/128), Sr*nbatch). z: s=z%Sr, b=z/Sr.
// Batch select: if A2!=null -> pointer swap (A2/BT2/dst1b/bias2 for b==1);
//               else offsets A+b*sAb, BT+b*sBTb, dst1+b*d1b, dst2+b*d2b.
// Epilogue: part!=null -> split-K partials (slot z); else bias/relu/dual-write, tf32out optional.
__global__ void __launch_bounds__(256,2) wgemm(
    int M, int nchunks, int Sr,
    const uint32_t* __restrict__ A, int lda, long long sAb,
    const uint32_t* __restrict__ BT, int ldbt, long long sBTb,
    const uint32_t* __restrict__ A2, const uint32_t* __restrict__ BT2,
    float* __restrict__ dst1, int ld1, long long d1b, float* __restrict__ dst1b,
    float* __restrict__ dst2, int ld2, long long d2b,
    const float* __restrict__ bias, const float* __restrict__ bias2,
    int relu, int tf32out,
    float* __restrict__ part, int Mtot, int Nn)
{
    extern __shared__ float smf[];
    uint32_t sbase = (uint32_t)__cvta_generic_to_shared(smf);
    int tid = threadIdx.x;
    int lane = tid & 31, wid = tid >> 5;
    int wm = wid >> 2, wn = wid & 3;
    int m0 = blockIdx.y*128, n0 = blockIdx.x*128;
    int z = blockIdx.z;
    int s = z % Sr, b = z / Sr;
    const uint32_t* Ause;
    const uint32_t* BTuse;
    float* d1; float* d2;
    const float* biasu;
    if (A2) {
        Ause  = b ? A2  : A;
        BTuse = b ? BT2 : BT;
        d1 = b ? dst1b : dst1;
        d2 = dst2;
        biasu = (b && bias2) ? bias2 : bias;
    } else {
        Ause  = A + (size_t)b*sAb;
        BTuse = BT + (size_t)b*sBTb;
        d1 = dst1 ? dst1 + (size_t)b*d1b : nullptr;
        d2 = dst2 ? dst2 + (size_t)b*d2b : nullptr;
        biasu = bias;
    }
    int kbase = s*nchunks*32;

    int r0g = tid >> 3;
    int qf  = tid & 7;
    uint32_t dstoff[4];
    const uint32_t* aS[4]; uint32_t aSz[4];
    const uint32_t* bS[4];
    #pragma unroll
    for (int t = 0; t < 4; t++) {
        int r = r0g + t*32;
        dstoff[t] = (uint32_t)(r*128) + (uint32_t)((qf ^ (r & 7)) << 4);
        int rm = m0 + r;
        int rcl = rm < M ? rm : (M-1);
        aS[t]  = Ause + (size_t)rcl*lda + kbase + qf*4;
        aSz[t] = (rm < M) ? 16u : 0u;
        bS[t]  = BTuse + (size_t)(n0 + r)*ldbt + kbase + qf*4;
    }

    int lg = lane >> 3, l7 = lane & 7;
    int arow = wm*64 + ((lg & 1) << 3) + l7;
    int brow = wn*32 + ((lg >> 1) << 3) + l7;
    uint32_t acol[4], bcol[4];
    #pragma unroll
    for (int ks = 0; ks < 4; ks++) {
        acol[ks] = (uint32_t)(((((ks<<1) + (lg>>1)) ^ (arow & 7))) << 4);
        bcol[ks] = (uint32_t)(((((ks<<1) + (lg&1))  ^ (brow & 7))) << 4);
    }
    uint32_t aBase = sbase + (uint32_t)(arow*128);
    uint32_t bBase = sbase + 16384u + (uint32_t)(brow*128);

    float acc[4][4][4];
    #pragma unroll
    for (int i = 0; i < 4; i++)
        #pragma unroll
        for (int j = 0; j < 4; j++)
            #pragma unroll
            for (int k = 0; k < 4; k++) acc[i][j][k] = 0.f;

    auto issue = [&](int kc, int buf) {
        uint32_t off = sbase + (uint32_t)(buf*32768);
        int ko = kc*32;
        #pragma unroll
        for (int t = 0; t < 4; t++) {
            cpa16(off + dstoff[t], aS[t] + ko, aSz[t]);
            cpa16(off + 16384u + dstoff[t], bS[t] + ko, 16u);
        }
        CP_COMMIT();
    };
    auto compute = [&](int buf) {
        uint32_t ab = aBase + (uint32_t)(buf*32768);
        uint32_t bb = bBase + (uint32_t)(buf*32768);
        #pragma unroll
        for (int ks = 0; ks < 4; ks++) {
            uint32_t bfr[4][2];
            #pragma unroll
            for (int ntp = 0; ntp < 2; ntp++)
                ldsm4(bb + (uint32_t)(ntp*2048) + bcol[ks],
                      bfr[2*ntp][0], bfr[2*ntp][1], bfr[2*ntp+1][0], bfr[2*ntp+1][1]);
            #pragma unroll
            for (int mt = 0; mt < 4; mt++) {
                uint32_t a0, a1, a2, a3;
                ldsm4(ab + (uint32_t)(mt*2048) + acol[ks], a0, a1, a2, a3);
                #pragma unroll
                for (int nt = 0; nt < 4; nt++)
                    mma_tf32(acc[mt][nt], a0, a1, a2, a3, bfr[nt][0], bfr[nt][1]);
            }
        }
    };

    issue(0, 0);
    for (int kc = 0; kc < nchunks; kc++) {
        CP_WAIT0();
        __syncthreads();
        if (kc + 1 < nchunks) issue(kc + 1, (kc + 1) & 1);
        compute(kc & 1);
    }

    int eg = lane >> 2, ec = lane & 3;
    #pragma unroll
    for (int mt = 0; mt < 4; mt++) {
        int r0 = m0 + wm*64 + mt*16 + eg;
        int r1 = r0 + 8;
        #pragma unroll
        for (int nt = 0; nt < 4; nt++) {
            int c0 = n0 + wn*32 + nt*8 + 2*ec;
            if (part) {
                float* p0 = part + ((size_t)z*Mtot + r0)*Nn + c0;
                float* p1 = part + ((size_t)z*Mtot + r1)*Nn + c0;
                if (r0 < M) { p0[0] = acc[mt][nt][0]; p0[1] = acc[mt][nt][1]; }
                if (r1 < M) { p1[0] = acc[mt][nt][2]; p1[1] = acc[mt][nt][3]; }
            } else {
                float b0 = biasu ? biasu[c0] : 0.f;
                float b1 = biasu ? biasu[c0+1] : 0.f;
                float v0 = acc[mt][nt][0] + b0, v1 = acc[mt][nt][1] + b1;
                float v2 = acc[mt][nt][2] + b0, v3 = acc[mt][nt][3] + b1;
                if (relu) { v0=fmaxf(v0,0.f); v1=fmaxf(v1,0.f); v2=fmaxf(v2,0.f); v3=fmaxf(v3,0.f); }
                if (tf32out) {
                    uint32_t u0 = f2tf32(v0), u1 = f2tf32(v1), u2 = f2tf32(v2), u3 = f2tf32(v3);
                    if (r0 < M) {
                        ((uint32_t*)d1)[(size_t)r0*ld1 + c0] = u0;
                        ((uint32_t*)d1)[(size_t)r0*ld1 + c0+1] = u1;
                        if (d2) { ((uint32_t*)d2)[(size_t)r0*ld2 + c0] = u0;
                                  ((uint32_t*)d2)[(size_t)r0*ld2 + c0+1] = u1; }
                    }
                    if (r1 < M) {
                        ((uint32_t*)d1)[(size_t)r1*ld1 + c0] = u2;
                        ((uint32_t*)d1)[(size_t)r1*ld1 + c0+1] = u3;
                        if (d2) { ((uint32_t*)d2)[(size_t)r1*ld2 + c0] = u2;
                                  ((uint32_t*)d2)[(size_t)r1*ld2 + c0+1] = u3; }
                    }
                } else {
                    if (r0 < M) {
                        d1[(size_t)r0*ld1 + c0] = v0; d1[(size_t)r0*ld1 + c0+1] = v1;
                        if (d2) { d2[(size_t)r0*ld2 + c0] = v0; d2[(size_t)r0*ld2 + c0+1] = v1; }
                    }
                    if (r1 < M) {
                        d1[(size_t)r1*ld1 + c0] = v2; d1[(size_t)r1*ld1 + c0+1] = v3;
                        if (d2) { d2[(size_t)r1*ld2 + c0] = v2; d2[(size_t)r1*ld2 + c0+1] = v3; }
                    }
                }
            }
        }
    }
}

// ===== bilinear: part[kb] = (hs_kb ⊗ ts_kb) @ WbilT[kb]; B via cp.async, A on the fly =====
__global__ void __launch_bounds__(256) wbil(const uint32_t* __restrict__ BT)
{
    extern __shared__ float smf[];
    uint32_t sbase = (uint32_t)__cvta_generic_to_shared(smf);
    float* hs_s = smf + 16384;           // [128][64]
    float* ts_s = smf + 16384 + 8192;    // [128][64]
    int tid = threadIdx.x;
    int lane = tid & 31, wid = tid >> 5;
    int wm = wid >> 2, wn = wid & 3;
    int m0 = blockIdx.x*128;
    int kb = blockIdx.y;

    #pragma unroll
    for (int t = 0; t < 8; t++) {
        int idx = tid + t*256;
        int r = idx >> 4, qi = idx & 15;
        int rg = m0 + r;
        float4 h = make_float4(0.f,0.f,0.f,0.f), v = h;
        if (rg < NP) {
            h = *(const float4*)(g_hs + (size_t)rg*DD + kb*64 + qi*4);
            v = *(const float4*)(g_ts + (size_t)rg*DD + kb*64 + qi*4);
        }
        *(float4*)(hs_s + r*64 + qi*4) = h;
        *(float4*)(ts_s + r*64 + qi*4) = v;
    }
    __syncthreads();

    int r0g = tid >> 3;
    int qf  = tid & 7;
    uint32_t dstoff[4];
    const uint32_t* bS[4];
    #pragma unroll
    for (int t = 0; t < 4; t++) {
        int r = r0g + t*32;
        dstoff[t] = (uint32_t)(r*128) + (uint32_t)((qf ^ (r & 7)) << 4);
        bS[t] = BT + (size_t)r*KBIL + kb*4096 + qf*4;
    }

    int lg = lane >> 3, l7 = lane & 7;
    int arow = wm*64 + ((lg & 1) << 3) + l7;
    int brow = wn*32 + ((lg >> 1) << 3) + l7;
    uint32_t acol[4], bcol[4];
    #pragma unroll
    for (int ks = 0; ks < 4; ks++) {
        acol[ks] = (uint32_t)(((((ks<<1) + (lg>>1)) ^ (arow & 7))) << 4);
        bcol[ks] = (uint32_t)(((((ks<<1) + (lg&1))  ^ (brow & 7))) << 4);
    }
    uint32_t aBase = sbase + (uint32_t)(arow*128);
    uint32_t bBase = sbase + 16384u + (uint32_t)(brow*128);

    float acc[4][4][4];
    #pragma unroll
    for (int i = 0; i < 4; i++)
        #pragma unroll
        for (int j = 0; j < 4; j++)
            #pragma unroll
            for (int k = 0; k < 4; k++) acc[i][j][k] = 0.f;

    float4 av[4];
    auto issueB = [&](int kc, int buf) {
        uint32_t off = sbase + (uint32_t)(buf*32768) + 16384u;
        int ko = kc*32;
        #pragma unroll
        for (int t = 0; t < 4; t++)
            cpa16(off + dstoff[t], bS[t] + ko, 16u);
        CP_COMMIT();
    };
    auto gatherA = [&](int kc) {
        int ii = kc >> 1;
        int j0 = ((kc & 1) << 5) + qf*4;
        #pragma unroll
        for (int t = 0; t < 4; t++) {
            int r = r0g + t*32;
            float hv = hs_s[r*64 + ii];
            float4 tv = *(const float4*)(ts_s + r*64 + j0);
            av[t] = make_float4(hv*tv.x, hv*tv.y, hv*tv.z, hv*tv.w);
        }
    };
    auto storeA = [&](int buf) {
        uint32_t off = sbase + (uint32_t)(buf*32768);
        #pragma unroll
        for (int t = 0; t < 4; t++)
            sts128(off + dstoff[t],
                   f2tf32(av[t].x), f2tf32(av[t].y), f2tf32(av[t].z), f2tf32(av[t].w));
    };
    auto compute = [&](int buf) {
        uint32_t ab = aBase + (uint32_t)(buf*32768);
        uint32_t bb = bBase + (uint32_t)(buf*32768);
        #pragma unroll
        for (int ks = 0; ks < 4; ks++) {
            uint32_t bfr[4][2];
            #pragma unroll
            for (int ntp = 0; ntp < 2; ntp++)
                ldsm4(bb + (uint32_t)(ntp*2048) + bcol[ks],
                      bfr[2*ntp][0], bfr[2*ntp][1], bfr[2*ntp+1][0], bfr[2*ntp+1][1]);
            #pragma unroll
            for (int mt = 0; mt < 4; mt++) {
                uint32_t a0, a1, a2, a3;
                ldsm4(ab + (uint32_t)(mt*2048) + acol[ks], a0, a1, a2, a3);
                #pragma unroll
                for (int nt = 0; nt < 4; nt++)
                    mma_tf32(acc[mt][nt], a0, a1, a2, a3, bfr[nt][0], bfr[nt][1]);
            }
        }
    };

    issueB(0, 0);
    gatherA(0);
    for (int kc = 0; kc < 128; kc++) {
        int buf = kc & 1;
        storeA(buf);
        CP_WAIT0();
        __syncthreads();
        if (kc + 1 < 128) { issueB(kc + 1, buf ^ 1); gatherA(kc + 1); }
        compute(buf);
    }

    int eg = lane >> 2, ec = lane & 3;
    #pragma unroll
    for (int mt = 0; mt < 4; mt++) {
        int r0 = m0 + wm*64 + mt*16 + eg;
        int r1 = r0 + 8;
        #pragma unroll
        for (int nt = 0; nt < 4; nt++) {
            int c0 = wn*32 + nt*8 + 2*ec;
            #pragma unroll
            for (int u = 0; u < 2; u++) {
                int col = c0 + u;
                if (col < LL) {
                    if (r0 < NP) g_part[((size_t)kb*NP + r0)*LL + col] = acc[mt][nt][u];
                    if (r1 < NP) g_part[((size_t)kb*NP + r1)*LL + col] = acc[mt][nt][2+u];
                }
            }
        }
    }
}

// ================= transpose -> tf32 =================
__global__ void ktrans(const float* __restrict__ in, int R, int C, int Cout,
                       uint32_t* __restrict__ out)
{
    __shared__ float t[32][33];
    int c0 = blockIdx.x*32, r0 = blockIdx.y*32;
    int tx = threadIdx.x, ty = threadIdx.y;
    #pragma unroll
    for (int j = 0; j < 32; j += 8) {
        int r = r0 + ty + j, c = c0 + tx;
        t[ty+j][tx] = (r < R && c < C) ? in[(size_t)r*C + c] : 0.f;
    }
    __syncthreads();
    #pragma unroll
    for (int j = 0; j < 32; j += 8) {
        int c = c0 + ty + j, r = r0 + tx;
        if (c < Cout && r < R) out[(size_t)c*R + r] = f2tf32(t[tx][ty+j]);
    }
}

// batched seq transpose: out[n][d][c] = tf32(seq[n][c][d])
__global__ void ktransB(const float* __restrict__ in, uint32_t* __restrict__ out)
{
    __shared__ float t[32][33];
    int d0 = blockIdx.x*32, c0 = blockIdx.y*32, n = blockIdx.z;
    int tx = threadIdx.x, ty = threadIdx.y;
    const float* inb = in + (size_t)n*CC*DD;
    uint32_t* outb = out + (size_t)n*DD*CC;
    #pragma unroll
    for (int j = 0; j < 32; j += 8)
        t[ty+j][tx] = inb[(size_t)(c0+ty+j)*DD + d0 + tx];
    __syncthreads();
    #pragma unroll
    for (int j = 0; j < 32; j += 8)
        outb[(size_t)(d0+ty+j)*CC + c0 + tx] = f2tf32(t[tx][ty+j]);
}

// ---------------- K1: gather ----------------
__global__ void k_gather(const float* __restrict__ seq, const float* __restrict__ att,
                         const int* __restrict__ ms)
{
    int ne = blockIdx.x;
    int n  = ne / EE;
    int tid = threadIdx.x;
    for (int m = 0; m < MMENT; m++) {
        int pos = ms[ne*MMENT + m] + 1;
        const float* srow = seq + ((size_t)n*CC + pos)*DD;
        float* erow = g_eemb + ((size_t)ne*MMENT + m)*DD;
        for (int d = tid; d < DD; d += blockDim.x) erow[d] = srow[d];
        float* arow = g_eatt + ((size_t)ne*MMENT + m)*CC;
        for (int c = tid; c < CC; c += blockDim.x) {
            float s = 0.f;
            #pragma unroll
            for (int h = 0; h < HH; h++)
                s += att[(((size_t)n*HH + h)*CC + pos)*CC + c];
            arow[c] = s * (1.0f/HH);
        }
    }
    __syncthreads();
    for (int d = tid; d < DD; d += blockDim.x) {
        float x0 = g_eemb[((size_t)ne*MMENT+0)*DD+d];
        float x1 = g_eemb[((size_t)ne*MMENT+1)*DD+d];
        float x2 = g_eemb[((size_t)ne*MMENT+2)*DD+d];
        float x3 = g_eemb[((size_t)ne*MMENT+3)*DD+d];
        float mx = fmaxf(fmaxf(x0,x1), fmaxf(x2,x3));
        float s = expf(x0-mx)+expf(x1-mx)+expf(x2-mx)+expf(x3-mx);
        g_glob[(size_t)ne*DD + d] = mx + logf(s);
    }
}

// ---------------- K3: edge ----------------
__global__ void k_edge(const float* __restrict__ bm)
{
    int idx = blockIdx.x*blockDim.x + threadIdx.x;
    const int total = NN*EE*EE*DD;
    if (idx >= total) return;
    int d = idx % DD;
    int v = (idx / DD) % EE;
    int u = (idx / (DD*EE)) % EE;
    int n = idx / (DD*EE*EE);
    float val = g_A[((size_t)n*EE+u)*DD+d] + g_B[((size_t)n*EE+v)*DD+d] + bm[d];
    g_edge[idx] = fmaxf(val, 0.f);
}

// ---------------- K4: pair attention ----------------
__global__ void k_pair(const int* __restrict__ hts, const int* __restrict__ ms)
{
    int r = blockIdx.x;
    int n = r / PP;
    int h = hts[r*2 + 0];
    int t = hts[r*2 + 1];
    __shared__ int   s_ph[MMENT], s_pt[MMENT];
    __shared__ float s_phatt[MMENT], s_ptatt[MMENT];
    __shared__ float s_red[256];
    int tid = threadIdx.x;
    if (tid < MMENT) {
        s_ph[tid] = ms[((size_t)n*EE+h)*MMENT + tid] + 1;
        s_pt[tid] = ms[((size_t)n*EE+t)*MMENT + tid] + 1;
    }
    __syncthreads();
    if (tid < 2*MMENT) {
        int m2 = tid & (MMENT-1);
        float s = 0.f;
        if (tid < MMENT) {
            for (int m1 = 0; m1 < MMENT; m1++)
                s += g_eatt[((size_t)(n*EE+h)*MMENT+m1)*CC + s_pt[m2]];
            s_phatt[m2] = s * (1.f/MMENT);
        } else {
            for (int m1 = 0; m1 < MMENT; m1++)
                s += g_eatt[((size_t)(n*EE+t)*MMENT+m1)*CC + s_ph[m2]];
            s_ptatt[m2] = s * (1.f/MMENT);
        }
    }
    __syncthreads();
    if (tid == 0) {
        float sh = 1e-5f, st = 1e-5f;
        for (int m = 0; m < MMENT; m++) { sh += s_phatt[m]; st += s_ptatt[m]; }
        float ih = 1.f/sh, it = 1.f/st;
        for (int m = 0; m < MMENT; m++) { s_phatt[m] *= ih; s_ptatt[m] *= it; }
    }
    __syncthreads();
    for (int d = tid; d < DD; d += blockDim.x) {
        float nh = 0.f, nt = 0.f;
        #pragma unroll
        for (int m = 0; m < MMENT; m++) {
            nh += s_ptatt[m]*g_eemb[((size_t)(n*EE+h)*MMENT+m)*DD + d];
            nt += s_phatt[m]*g_eemb[((size_t)(n*EE+t)*MMENT+m)*DD + d];
        }
        uint32_t nh32 = f2tf32(nh), nt32 = f2tf32(nt);
        g_hcat32[(size_t)r*DIM3 + d] = nh32;
        g_tcat32[(size_t)r*DIM3 + d] = nt32;
        g_q32[(size_t)r*DIM2 + d]      = nh32;
        g_q32[(size_t)r*DIM2 + DD + d] = nt32;
    }
    float local = 0.f;
    for (int c = tid; c < CC; c += blockDim.x) {
        float na = 0.f, ta = 0.f;
        #pragma unroll
        for (int m = 0; m < MMENT; m++) {
            na += s_ptatt[m]*g_eatt[((size_t)(n*EE+h)*MMENT+m)*CC + c];
            ta += s_phatt[m]*g_eatt[((size_t)(n*EE+t)*MMENT+m)*CC + c];
        }
        float v = na*ta;
        g_pa[(size_t)r*CC + c] = v;
        local += v;
    }
    s_red[tid] = local;
    __syncthreads();
    for (int off = 128; off > 0; off >>= 1) {
        if (tid < off) s_red[tid] += s_red[tid+off];
        __syncthreads();
    }
    float inv = 1.f/(s_red[0] + 1e-5f);
    for (int c = tid; c < CC; c += blockDim.x)
        g_pa32[(size_t)r*CC + c] = f2tf32(g_pa[(size_t)r*CC + c]*inv);
}

// ---------------- fp32 SGEMM (Wm1+Wm2 merged: z = b*S+s, b selects B/B2) ----------------
__global__ void __launch_bounds__(256) sgemm(
    int M, int Nn, int Kc, int S,
    const float* __restrict__ A, int lda,
    const float* __restrict__ B, const float* __restrict__ B2, int ldb,
    float* __restrict__ part)
{
    int z = blockIdx.z;
    int s = z % S, b = z / S;
    const float* Ab = A + (size_t)s*Kc;
    const float* Bb = ((b && B2) ? B2 : B) + (size_t)s*Kc*ldb;
    int m0 = blockIdx.y*128, n0 = blockIdx.x*128;
    __shared__ float As[8][128];
    __shared__ float Bs[8][128];
    int tid = threadIdx.x;
    int arow = tid >> 1, ak = (tid & 1)*4;
    int bk = tid >> 5,  bn = (tid & 31)*4;
    int tx = tid & 15,  ty = tid >> 4;
    float acc[8][8];
    #pragma unroll
    for (int i = 0; i < 8; i++)
        #pragma unroll
        for (int j = 0; j < 8; j++) acc[i][j] = 0.f;
    for (int k0 = 0; k0 < Kc; k0 += 8) {
        float4 av = make_float4(0.f,0.f,0.f,0.f);
        if (m0 + arow < M)
            av = *(const float4*)(Ab + (size_t)(m0+arow)*lda + k0 + ak);
        float4 bvv = *(const float4*)(Bb + (size_t)(k0+bk)*ldb + n0 + bn);
        __syncthreads();
        As[ak+0][arow] = av.x; As[ak+1][arow] = av.y;
        As[ak+2][arow] = av.z; As[ak+3][arow] = av.w;
        *(float4*)&Bs[bk][bn] = bvv;
        __syncthreads();
        #pragma unroll
        for (int kk = 0; kk < 8; kk++) {
            float a[8], bb[8];
            *(float4*)(a)    = *(const float4*)&As[kk][ty*8];
            *(float4*)(a+4)  = *(const float4*)&As[kk][ty*8+4];
            *(float4*)(bb)   = *(const float4*)&Bs[kk][tx*8];
            *(float4*)(bb+4) = *(const float4*)&Bs[kk][tx*8+4];
            #pragma unroll
            for (int i = 0; i < 8; i++)
                #pragma unroll
                for (int j = 0; j < 8; j++)
                    acc[i][j] += a[i]*bb[j];
        }
    }
    float* pbase = part + ((size_t)z*M)*Nn;
    #pragma unroll
    for (int i = 0; i < 8; i++) {
        int r = m0 + ty*8 + i;
        if (r < M) {
            float* prow = pbase + (size_t)r*Nn + n0 + tx*8;
            *(float4*)(prow)   = make_float4(acc[i][0],acc[i][1],acc[i][2],acc[i][3]);
            *(float4*)(prow+4) = make_float4(acc[i][4],acc[i][5],acc[i][6],acc[i][7]);
        }
    }
}

// reduce + bias + relu; tf32out: dst pointers are uint32_t* (tf32)
__global__ void reduce_ep(const float* __restrict__ part, int S, int Mtot, int Nn,
                          const float* __restrict__ bias, int dorelu, int tf32out,
                          float* __restrict__ dst1, int ld1,
                          float* __restrict__ dst2, int ld2)
{
    int idx = blockIdx.x*blockDim.x + threadIdx.x;
    if (idx >= Mtot*Nn) return;
    int r = idx / Nn, c = idx % Nn;
    float v = 0.f;
    for (int s = 0; s < S; s++)
        v += part[((size_t)s*Mtot + r)*Nn + c];
    if (bias) v += bias[c];
    if (dorelu) v = fmaxf(v, 0.f);
    if (tf32out) {
        uint32_t u = f2tf32(v);
        ((uint32_t*)dst1)[(size_t)r*ld1 + c] = u;
        if (dst2) ((uint32_t*)dst2)[(size_t)r*ld2 + c] = u;
    } else {
        dst1[(size_t)r*ld1 + c] = v;
        if (dst2) dst2[(size_t)r*ld2 + c] = v;
    }
}

// ---------------- K7: score + masked softmax + path ----------------
__global__ void k_scorepath(const int* __restrict__ hts, const float* __restrict__ battp)
{
    int r = blockIdx.x;
    int n = r / PP;
    int h = hts[r*2 + 0];
    int t = hts[r*2 + 1];
    __shared__ float s_q[DIM4];
    __shared__ float s_score[EE];
    __shared__ float s_aw[EE];
    int tid = threadIdx.x;
    for (int i = tid; i < DIM4; i += blockDim.x)
        s_q[i] = g_qW[(size_t)r*DIM4 + i];
    __syncthreads();
    int warp = tid >> 5, lane = tid & 31;
    float batt = battp[0];
    for (int v = warp; v < EE; v += 8) {
        const float* e1 = g_edge + ((size_t)((n*EE+h)*EE + v))*DD;
        const float* e2 = g_edge + ((size_t)((n*EE+v)*EE + t))*DD;
        const float* e3 = g_edge + ((size_t)((n*EE+t)*EE + v))*DD;
        const float* e4 = g_edge + ((size_t)((n*EE+v)*EE + h))*DD;
        float s = 0.f;
        for (int d = lane; d < DD; d += 32)
            s += s_q[d]*e1[d] + s_q[DD+d]*e2[d] + s_q[2*DD+d]*e3[d] + s_q[3*DD+d]*e4[d];
        #pragma unroll
        for (int off = 16; off; off >>= 1)
            s += __shfl_down_sync(0xffffffffu, s, off);
        if (lane == 0) s_score[v] = s + batt;
    }
    __syncthreads();
    if (tid == 0) {
        float mx = -1e38f;
        for (int v = 0; v < EE; v++) {
            float sc = (v == h || v == t) ? NEGV : s_score[v];
            s_score[v] = sc;
            mx = fmaxf(mx, sc);
        }
        float sum = 0.f;
        for (int v = 0; v < EE; v++) {
            float e = expf(s_score[v] - mx);
            s_aw[v] = e;
            sum += e;
        }
        float inv = 1.f/sum;
        for (int v = 0; v < EE; v++) s_aw[v] *= inv;
    }
    __syncthreads();
    for (int idx = tid; idx < DIM4; idx += blockDim.x) {
        int kk = idx / DD, d = idx % DD;
        const float* ep;
        size_t strideV;
        if (kk == 0)      { ep = g_edge + ((size_t)((n*EE+h)*EE))*DD + d;   strideV = DD; }
        else if (kk == 1) { ep = g_edge + ((size_t)(n*EE)*EE + t)*DD + d;   strideV = (size_t)EE*DD; }
        else if (kk == 2) { ep = g_edge + ((size_t)((n*EE+t)*EE))*DD + d;   strideV = DD; }
        else              { ep = g_edge + ((size_t)(n*EE)*EE + h)*DD + d;   strideV = (size_t)EE*DD; }
        float acc = 0.f;
        #pragma unroll 4
        for (int v = 0; v < EE; v++)
            acc += s_aw[v]*ep[(size_t)v*strideV];
        g_praw32[(size_t)r*DIM4 + idx] = f2tf32(acc);
    }
}

__global__ void k_bilred(const float* __restrict__ bbil, float* __restrict__ out)
{
    int idx = blockIdx.x*blockDim.x + threadIdx.x;
    if (idx >= NP*LL) return;
    int r = idx / LL, l = idx % LL;
    float v = bbil[l];
    #pragma unroll
    for (int k = 0; k < 12; k++)
        v += g_part[((size_t)k*NP + r)*LL + l];
    out[idx] = v;
}

// ---------------- launcher ----------------
static void* symaddr(const void* sym)
{
    void* p = nullptr;
    cudaGetSymbolAddress(&p, sym);
    return p;
}

extern "C" void kernel_launch(void* const* d_in, const int* in_sizes, int n_in,
                              void* d_out, int out_size)
{
    const float* seq   = (const float*)d_in[0];
    const float* att   = (const float*)d_in[1];
    const int*   ms    = (const int*)  d_in[2];
    const int*   hts   = (const int*)  d_in[3];
    const float* Wm1   = (const float*)d_in[4];
    const float* Wm2   = (const float*)d_in[5];
    const float* bm    = (const float*)d_in[6];
    const float* Watt  = (const float*)d_in[7];
    const float* batt  = (const float*)d_in[8];
    const float* Wpath = (const float*)d_in[9];
    const float* bpath = (const float*)d_in[10];
    const float* Whead = (const float*)d_in[11];
    const float* bhead = (const float*)d_in[12];
    const float* Wtail = (const float*)d_in[13];
    const float* btail = (const float*)d_in[14];
    const float* Wbil  = (const float*)d_in[15];
    const float* bbil  = (const float*)d_in[16];
    float* out = (float*)d_out;

    float*    glob   = (float*)symaddr(g_glob);
    float*    gA     = (float*)symaddr(g_A);
    float*    gB     = (float*)symaddr(g_B);
    float*    qW     = (float*)symaddr(g_qW);
    float*    hs     = (float*)symaddr(g_hs);
    float*    ts     = (float*)symaddr(g_ts);
    float*    part   = (float*)symaddr(g_part);
    uint32_t* pa32   = (uint32_t*)symaddr(g_pa32);
    uint32_t* seqT32 = (uint32_t*)symaddr(g_seqT32);
    uint32_t* q32    = (uint32_t*)symaddr(g_q32);
    uint32_t* hcat32 = (uint32_t*)symaddr(g_hcat32);
    uint32_t* tcat32 = (uint32_t*)symaddr(g_tcat32);
    uint32_t* praw32 = (uint32_t*)symaddr(g_praw32);
    uint32_t* wTatt  = (uint32_t*)symaddr(g_wT_att32);
    uint32_t* wTpath = (uint32_t*)symaddr(g_wT_path32);
    uint32_t* wThead = (uint32_t*)symaddr(g_wT_head32);
    uint32_t* wTtail = (uint32_t*)symaddr(g_wT_tail32);
    uint32_t* wTbil  = (uint32_t*)symaddr(g_wT_bil32);

    const int SMEM_WG = 65536;
    const int SMEM_WB = 131072;
    cudaFuncSetAttribute(wgemm, cudaFuncAttributeMaxDynamicSharedMemorySize, SMEM_WG);
    cudaFuncSetAttribute(wbil,  cudaFuncAttributeMaxDynamicSharedMemorySize, SMEM_WB);

    // --- ordered so launch index 3 (ncu capture slot) is the qW wgemm ---
    k_gather<<<NN*EE, 256>>>(seq, att, ms);                                        // 0
    k_pair<<<NP, 256>>>(hts, ms);                                                  // 1
    ktrans<<<dim3(DIM4/32, DIM2/32), dim3(32,8)>>>(Watt, DIM2, DIM4, DIM4, wTatt); // 2
    // 3: qW = q @ Watt (tf32 mma + cp.async) <-- ncu profiles this
    wgemm<<<dim3(24,12,1), 256, SMEM_WG>>>(NP, 48, 1,
        q32, DIM2, 0, wTatt, DIM2, 0, nullptr, nullptr,
        qW, DIM4, 0, nullptr, nullptr, 0, 0,
        nullptr, nullptr, 0, 0, nullptr, 0, 0);

    // Wm1+Wm2 merged (fp32, split-K 12 each, z = b*12+s)
    sgemm<<<dim3(6,1,24), 256>>>(NN*EE, DD, 64, 12, glob, DD, Wm1, Wm2, DD, part);
    reduce_ep<<<(NN*EE*DD+255)/256, 256>>>(part, 12, NN*EE, DD, nullptr, 0, 0,
                                           gA, DD, nullptr, 0);
    reduce_ep<<<(NN*EE*DD+255)/256, 256>>>(part + (size_t)12*NN*EE*DD, 12, NN*EE, DD,
                                           nullptr, 0, 0, gB, DD, nullptr, 0);
    k_edge<<<(NN*EE*EE*DD+255)/256, 256>>>(bm);

    // rs = pa @ seq (tf32 mma, per-doc batch, direct dual tf32 epilogue)
    ktransB<<<dim3(DD/32, CC/32, NN), dim3(32,8)>>>(seq, seqT32);
    wgemm<<<dim3(6,3,NN), 256, SMEM_WG>>>(PP, 16, 1,
        pa32, CC, (long long)PP*CC, seqT32, CC, (long long)DD*CC, nullptr, nullptr,
        (float*)(hcat32 + DD), DIM3, (long long)PP*DIM3, nullptr,
        (float*)(tcat32 + DD), DIM3, (long long)PP*DIM3,
        nullptr, nullptr, 0, 1, nullptr, 0, 0);

    // score/softmax/path (writes praw32 tf32)
    k_scorepath<<<NP, 256>>>(hts, batt);

    // path = relu(pathraw @ Wpath + bpath) -> tf32 into hcat32/tcat32 [2D,3D)
    ktrans<<<dim3(DD/32, DIM4/32), dim3(32,8)>>>(Wpath, DIM4, DD, DD, wTpath);
    wgemm<<<dim3(6,12,2), 256, SMEM_WG>>>(NP, 48, 2,
        praw32, DIM4, 0, wTpath, DIM4, 0, nullptr, nullptr,
        nullptr, 0, 0, nullptr, nullptr, 0, 0,
        nullptr, nullptr, 0, 0, part, NP, DD);
    reduce_ep<<<(NP*DD+255)/256, 256>>>(part, 2, NP, DD, bpath, 1, 1,
                                        (float*)(hcat32 + 2*DD), DIM3,
                                        (float*)(tcat32 + 2*DD), DIM3);

    // hs / ts projections — merged, Sr=1, direct epilogue (per-b bias/dst)
    ktrans<<<dim3(DD/32, DIM3/32), dim3(32,8)>>>(Whead, DIM3, DD, DD, wThead);
    ktrans<<<dim3(DD/32, DIM3/32), dim3(32,8)>>>(Wtail, DIM3, DD, DD, wTtail);
    wgemm<<<dim3(6,12,2), 256, SMEM_WG>>>(NP, 72, 1,
        hcat32, DIM3, 0, wThead, DIM3, 0, tcat32, wTtail,
        hs, DD, 0, ts, nullptr, 0, 0,
        bhead, btail, 1, 0, nullptr, 0, 0);

    // bilinear head (tf32 mma, cp.async B, fused outer-product A)
    ktrans<<<dim3(4, KBIL/32), dim3(32,8)>>>(Wbil, KBIL, LL, 128, wTbil);
    wbil<<<dim3(12,12), 256, SMEM_WB>>>(wTbil);
    k_bilred<<<(NP*LL+255)/256, 256>>>(bbil, out);
}

// round 13
// speedup vs baseline: 2.6898x; 1.0342x over previous
#include <cuda_runtime.h>
#include <cstdint>
#include <math.h>

#define NN 4
#define CC 512
#define DD 768
#define HH 12
#define EE 20
#define MMENT 4
#define PP 380
#define NP 1520
#define LL 97
#define DIM2 1536
#define DIM3 2304
#define DIM4 3072
#define KBIL 49152
#define NEGV (-1e30f)

// ---------------- static device scratch ----------------
__device__ float g_eemb[NN*EE*MMENT*DD];
__device__ float g_eatt[NN*EE*MMENT*CC];
__device__ float g_glob[NN*EE*DD];
__device__ float g_A[NN*EE*DD];
__device__ float g_B[NN*EE*DD];
__device__ float g_edge[NN*EE*EE*DD];
__device__ float g_pa[NP*CC];
__device__ float g_qW[NP*DIM4];
__device__ float g_hs[NP*DD];
__device__ float g_ts[NP*DD];
__device__ float g_part[4*NP*DD];
// tf32 (u32 bit pattern) GEMM operands
__device__ uint32_t g_pa32[NP*CC];
__device__ uint32_t g_seqT32[NN*DD*CC];
__device__ uint32_t g_q32[NP*DIM2];
__device__ uint32_t g_hcat32[NP*DIM3];
__device__ uint32_t g_tcat32[NP*DIM3];
__device__ uint32_t g_praw32[NP*DIM4];
__device__ uint32_t g_wT_att32[DIM4*DIM2];
__device__ uint32_t g_wT_path32[DD*DIM4];
__device__ uint32_t g_wT_head32[DD*DIM3];
__device__ uint32_t g_wT_tail32[DD*DIM3];
__device__ uint32_t g_wT_bil32[128*KBIL];   // rows 97..127 zero

// ---------------- helpers ----------------
__device__ __forceinline__ uint32_t f2tf32(float f) {
    uint32_t r;
    asm("cvt.rna.tf32.f32 %0, %1;" : "=r"(r) : "f"(f));
    return r;
}
__device__ __forceinline__ void mma_tf32(float* d, uint32_t a0, uint32_t a1,
                                         uint32_t a2, uint32_t a3,
                                         uint32_t b0, uint32_t b1)
{
    asm volatile(
        "mma.sync.aligned.m16n8k8.row.col.f32.tf32.tf32.f32 "
        "{%0,%1,%2,%3}, {%4,%5,%6,%7}, {%8,%9}, {%0,%1,%2,%3};"
        : "+f"(d[0]), "+f"(d[1]), "+f"(d[2]), "+f"(d[3])
        : "r"(a0), "r"(a1), "r"(a2), "r"(a3), "r"(b0), "r"(b1));
}
__device__ __forceinline__ void ldsm4(uint32_t addr, uint32_t& a, uint32_t& b,
                                      uint32_t& c, uint32_t& d)
{
    asm volatile("ldmatrix.sync.aligned.m8n8.x4.shared.b16 {%0,%1,%2,%3}, [%4];"
                 : "=r"(a), "=r"(b), "=r"(c), "=r"(d) : "r"(addr));
}
__device__ __forceinline__ void sts128(uint32_t addr, uint32_t x, uint32_t y,
                                       uint32_t z, uint32_t w)
{
    asm volatile("st.shared.v4.b32 [%0], {%1,%2,%3,%4};"
                 :: "r"(addr), "r"(x), "r"(y), "r"(z), "r"(w) : "memory");
}
__device__ __forceinline__ void cpa16(uint32_t dst, const void* src, uint32_t sz)
{
    asm volatile("cp.async.cg.shared.global [%0], [%1], 16, %2;"
                 :: "r"(dst), "l"(src), "r"(sz) : "memory");
}
#define CP_COMMIT() asm volatile("cp.async.commit_group;" ::: "memory")
#define CP_WAIT0()  asm volatile("cp.async.wait_group 0;" ::: "memory")

// ================ tf32 warp-mma GEMM: cp.async staging + ldmatrix ================
// CTA 128x128, K-chunk 32, double buffer. Swizzle: byte = row*128 + ((col16 ^ (row&7))<<4).
// grid: (N/128, ceil(M/128), Sr*nbatch). z: s=z%Sr, b=z/Sr.
// Batch select: if A2!=null -> pointer swap; else strided offsets.
__global__ void __launch_bounds__(256,2) wgemm(
    int M, int nchunks, int Sr,
    const uint32_t* __restrict__ A, int lda, long long sAb,
    const uint32_t* __restrict__ BT, int ldbt, long long sBTb,
    const uint32_t* __restrict__ A2, const uint32_t* __restrict__ BT2,
    float* __restrict__ dst1, int ld1, long long d1b, float* __restrict__ dst1b,
    float* __restrict__ dst2, int ld2, long long d2b,
    const float* __restrict__ bias, const float* __restrict__ bias2,
    int relu, int tf32out,
    float* __restrict__ part, int Mtot, int Nn)
{
    extern __shared__ float smf[];
    uint32_t sbase = (uint32_t)__cvta_generic_to_shared(smf);
    int tid = threadIdx.x;
    int lane = tid & 31, wid = tid >> 5;
    int wm = wid >> 2, wn = wid & 3;
    int m0 = blockIdx.y*128, n0 = blockIdx.x*128;
    int z = blockIdx.z;
    int s = z % Sr, b = z / Sr;
    const uint32_t* Ause;
    const uint32_t* BTuse;
    float* d1; float* d2;
    const float* biasu;
    if (A2) {
        Ause  = b ? A2  : A;
        BTuse = b ? BT2 : BT;
        d1 = b ? dst1b : dst1;
        d2 = dst2;
        biasu = (b && bias2) ? bias2 : bias;
    } else {
        Ause  = A + (size_t)b*sAb;
        BTuse = BT + (size_t)b*sBTb;
        d1 = dst1 ? dst1 + (size_t)b*d1b : nullptr;
        d2 = dst2 ? dst2 + (size_t)b*d2b : nullptr;
        biasu = bias;
    }
    int kbase = s*nchunks*32;

    int r0g = tid >> 3;
    int qf  = tid & 7;
    uint32_t dstoff[4];
    const uint32_t* aS[4]; uint32_t aSz[4];
    const uint32_t* bS[4];
    #pragma unroll
    for (int t = 0; t < 4; t++) {
        int r = r0g + t*32;
        dstoff[t] = (uint32_t)(r*128) + (uint32_t)((qf ^ (r & 7)) << 4);
        int rm = m0 + r;
        int rcl = rm < M ? rm : (M-1);
        aS[t]  = Ause + (size_t)rcl*lda + kbase + qf*4;
        aSz[t] = (rm < M) ? 16u : 0u;
        bS[t]  = BTuse + (size_t)(n0 + r)*ldbt + kbase + qf*4;
    }

    int lg = lane >> 3, l7 = lane & 7;
    int arow = wm*64 + ((lg & 1) << 3) + l7;
    int brow = wn*32 + ((lg >> 1) << 3) + l7;
    uint32_t acol[4], bcol[4];
    #pragma unroll
    for (int ks = 0; ks < 4; ks++) {
        acol[ks] = (uint32_t)(((((ks<<1) + (lg>>1)) ^ (arow & 7))) << 4);
        bcol[ks] = (uint32_t)(((((ks<<1) + (lg&1))  ^ (brow & 7))) << 4);
    }
    uint32_t aBase = sbase + (uint32_t)(arow*128);
    uint32_t bBase = sbase + 16384u + (uint32_t)(brow*128);

    float acc[4][4][4];
    #pragma unroll
    for (int i = 0; i < 4; i++)
        #pragma unroll
        for (int j = 0; j < 4; j++)
            #pragma unroll
            for (int k = 0; k < 4; k++) acc[i][j][k] = 0.f;

    auto issue = [&](int kc, int buf) {
        uint32_t off = sbase + (uint32_t)(buf*32768);
        int ko = kc*32;
        #pragma unroll
        for (int t = 0; t < 4; t++) {
            cpa16(off + dstoff[t], aS[t] + ko, aSz[t]);
            cpa16(off + 16384u + dstoff[t], bS[t] + ko, 16u);
        }
        CP_COMMIT();
    };
    auto compute = [&](int buf) {
        uint32_t ab = aBase + (uint32_t)(buf*32768);
        uint32_t bb = bBase + (uint32_t)(buf*32768);
        #pragma unroll
        for (int ks = 0; ks < 4; ks++) {
            uint32_t bfr[4][2];
            #pragma unroll
            for (int ntp = 0; ntp < 2; ntp++)
                ldsm4(bb + (uint32_t)(ntp*2048) + bcol[ks],
                      bfr[2*ntp][0], bfr[2*ntp][1], bfr[2*ntp+1][0], bfr[2*ntp+1][1]);
            #pragma unroll
            for (int mt = 0; mt < 4; mt++) {
                uint32_t a0, a1, a2, a3;
                ldsm4(ab + (uint32_t)(mt*2048) + acol[ks], a0, a1, a2, a3);
                #pragma unroll
                for (int nt = 0; nt < 4; nt++)
                    mma_tf32(acc[mt][nt], a0, a1, a2, a3, bfr[nt][0], bfr[nt][1]);
            }
        }
    };

    issue(0, 0);
    for (int kc = 0; kc < nchunks; kc++) {
        CP_WAIT0();
        __syncthreads();
        if (kc + 1 < nchunks) issue(kc + 1, (kc + 1) & 1);
        compute(kc & 1);
    }

    int eg = lane >> 2, ec = lane & 3;
    #pragma unroll
    for (int mt = 0; mt < 4; mt++) {
        int r0 = m0 + wm*64 + mt*16 + eg;
        int r1 = r0 + 8;
        #pragma unroll
        for (int nt = 0; nt < 4; nt++) {
            int c0 = n0 + wn*32 + nt*8 + 2*ec;
            if (part) {
                float* p0 = part + ((size_t)z*Mtot + r0)*Nn + c0;
                float* p1 = part + ((size_t)z*Mtot + r1)*Nn + c0;
                if (r0 < M) { p0[0] = acc[mt][nt][0]; p0[1] = acc[mt][nt][1]; }
                if (r1 < M) { p1[0] = acc[mt][nt][2]; p1[1] = acc[mt][nt][3]; }
            } else {
                float b0 = biasu ? biasu[c0] : 0.f;
                float b1 = biasu ? biasu[c0+1] : 0.f;
                float v0 = acc[mt][nt][0] + b0, v1 = acc[mt][nt][1] + b1;
                float v2 = acc[mt][nt][2] + b0, v3 = acc[mt][nt][3] + b1;
                if (relu) { v0=fmaxf(v0,0.f); v1=fmaxf(v1,0.f); v2=fmaxf(v2,0.f); v3=fmaxf(v3,0.f); }
                if (tf32out) {
                    uint32_t u0 = f2tf32(v0), u1 = f2tf32(v1), u2 = f2tf32(v2), u3 = f2tf32(v3);
                    if (r0 < M) {
                        ((uint32_t*)d1)[(size_t)r0*ld1 + c0] = u0;
                        ((uint32_t*)d1)[(size_t)r0*ld1 + c0+1] = u1;
                        if (d2) { ((uint32_t*)d2)[(size_t)r0*ld2 + c0] = u0;
                                  ((uint32_t*)d2)[(size_t)r0*ld2 + c0+1] = u1; }
                    }
                    if (r1 < M) {
                        ((uint32_t*)d1)[(size_t)r1*ld1 + c0] = u2;
                        ((uint32_t*)d1)[(size_t)r1*ld1 + c0+1] = u3;
                        if (d2) { ((uint32_t*)d2)[(size_t)r1*ld2 + c0] = u2;
                                  ((uint32_t*)d2)[(size_t)r1*ld2 + c0+1] = u3; }
                    }
                } else {
                    if (r0 < M) {
                        d1[(size_t)r0*ld1 + c0] = v0; d1[(size_t)r0*ld1 + c0+1] = v1;
                        if (d2) { d2[(size_t)r0*ld2 + c0] = v0; d2[(size_t)r0*ld2 + c0+1] = v1; }
                    }
                    if (r1 < M) {
                        d1[(size_t)r1*ld1 + c0] = v2; d1[(size_t)r1*ld1 + c0+1] = v3;
                        if (d2) { d2[(size_t)r1*ld2 + c0] = v2; d2[(size_t)r1*ld2 + c0+1] = v3; }
                    }
                }
            }
        }
    }
}

// ===== bilinear v2: grid (12 m-tiles, 24 slots). slot = kb*2 + half; 64 chunks each. =====
// part[slot] = (hs ⊗ ts)[:, K-half] @ WbilT[K-half].  smem: A/B dbl buf 64KB + ts 32KB = 96KB.
// hs read from gmem (L2-resident), one scalar per row per chunk-pair.
__global__ void __launch_bounds__(256,2) wbil(const uint32_t* __restrict__ BT)
{
    extern __shared__ float smf[];
    uint32_t sbase = (uint32_t)__cvta_generic_to_shared(smf);
    float* ts_s = smf + 16384;           // byte 65536: [128][64]
    int tid = threadIdx.x;
    int lane = tid & 31, wid = tid >> 5;
    int wm = wid >> 2, wn = wid & 3;
    int m0 = blockIdx.x*128;
    int slot = blockIdx.y;
    int kb = slot >> 1, half = slot & 1;

    // stage ts rows (fp32), cols kb*64..+64
    #pragma unroll
    for (int t = 0; t < 8; t++) {
        int idx = tid + t*256;
        int r = idx >> 4, qi = idx & 15;
        int rg = m0 + r;
        float4 v = make_float4(0.f,0.f,0.f,0.f);
        if (rg < NP)
            v = *(const float4*)(g_ts + (size_t)rg*DD + kb*64 + qi*4);
        *(float4*)(ts_s + r*64 + qi*4) = v;
    }
    __syncthreads();

    int r0g = tid >> 3;
    int qf  = tid & 7;
    uint32_t dstoff[4];
    const uint32_t* bS[4];
    int hrow[4]; int hvalid[4];
    #pragma unroll
    for (int t = 0; t < 4; t++) {
        int r = r0g + t*32;
        dstoff[t] = (uint32_t)(r*128) + (uint32_t)((qf ^ (r & 7)) << 4);
        bS[t] = BT + (size_t)r*KBIL + kb*4096 + half*2048 + qf*4;
        hrow[t] = m0 + r;
        hvalid[t] = (m0 + r) < NP;
    }
    const float* hsbase = g_hs + (size_t)0;
    int icol0 = kb*64 + half*32;

    int lg = lane >> 3, l7 = lane & 7;
    int arow = wm*64 + ((lg & 1) << 3) + l7;
    int brow = wn*32 + ((lg >> 1) << 3) + l7;
    uint32_t acol[4], bcol[4];
    #pragma unroll
    for (int ks = 0; ks < 4; ks++) {
        acol[ks] = (uint32_t)(((((ks<<1) + (lg>>1)) ^ (arow & 7))) << 4);
        bcol[ks] = (uint32_t)(((((ks<<1) + (lg&1))  ^ (brow & 7))) << 4);
    }
    uint32_t aBase = sbase + (uint32_t)(arow*128);
    uint32_t bBase = sbase + 16384u + (uint32_t)(brow*128);

    float acc[4][4][4];
    #pragma unroll
    for (int i = 0; i < 4; i++)
        #pragma unroll
        for (int j = 0; j < 4; j++)
            #pragma unroll
            for (int k = 0; k < 4; k++) acc[i][j][k] = 0.f;

    float hv[4];
    float4 av[4];
    auto issueB = [&](int kc, int buf) {
        uint32_t off = sbase + (uint32_t)(buf*32768) + 16384u;
        int ko = kc*32;
        #pragma unroll
        for (int t = 0; t < 4; t++)
            cpa16(off + dstoff[t], bS[t] + ko, 16u);
        CP_COMMIT();
    };
    auto gatherA = [&](int kc) {
        if ((kc & 1) == 0) {
            int icol = icol0 + (kc >> 1);
            #pragma unroll
            for (int t = 0; t < 4; t++)
                hv[t] = hvalid[t] ? hsbase[(size_t)hrow[t]*DD + icol] : 0.f;
        }
        int j0 = ((kc & 1) << 5) + qf*4;
        #pragma unroll
        for (int t = 0; t < 4; t++) {
            int r = r0g + t*32;
            float4 tv = *(const float4*)(ts_s + r*64 + j0);
            av[t] = make_float4(hv[t]*tv.x, hv[t]*tv.y, hv[t]*tv.z, hv[t]*tv.w);
        }
    };
    auto storeA = [&](int buf) {
        uint32_t off = sbase + (uint32_t)(buf*32768);
        #pragma unroll
        for (int t = 0; t < 4; t++)
            sts128(off + dstoff[t],
                   f2tf32(av[t].x), f2tf32(av[t].y), f2tf32(av[t].z), f2tf32(av[t].w));
    };
    auto compute = [&](int buf) {
        uint32_t ab = aBase + (uint32_t)(buf*32768);
        uint32_t bb = bBase + (uint32_t)(buf*32768);
        #pragma unroll
        for (int ks = 0; ks < 4; ks++) {
            uint32_t bfr[4][2];
            #pragma unroll
            for (int ntp = 0; ntp < 2; ntp++)
                ldsm4(bb + (uint32_t)(ntp*2048) + bcol[ks],
                      bfr[2*ntp][0], bfr[2*ntp][1], bfr[2*ntp+1][0], bfr[2*ntp+1][1]);
            #pragma unroll
            for (int mt = 0; mt < 4; mt++) {
                uint32_t a0, a1, a2, a3;
                ldsm4(ab + (uint32_t)(mt*2048) + acol[ks], a0, a1, a2, a3);
                #pragma unroll
                for (int nt = 0; nt < 4; nt++)
                    mma_tf32(acc[mt][nt], a0, a1, a2, a3, bfr[nt][0], bfr[nt][1]);
            }
        }
    };

    issueB(0, 0);
    gatherA(0);
    for (int kc = 0; kc < 64; kc++) {
        int buf = kc & 1;
        storeA(buf);
        CP_WAIT0();
        __syncthreads();
        if (kc + 1 < 64) { issueB(kc + 1, buf ^ 1); gatherA(kc + 1); }
        compute(buf);
    }

    int eg = lane >> 2, ec = lane & 3;
    #pragma unroll
    for (int mt = 0; mt < 4; mt++) {
        int r0 = m0 + wm*64 + mt*16 + eg;
        int r1 = r0 + 8;
        #pragma unroll
        for (int nt = 0; nt < 4; nt++) {
            int c0 = wn*32 + nt*8 + 2*ec;
            #pragma unroll
            for (int u = 0; u < 2; u++) {
                int col = c0 + u;
                if (col < LL) {
                    if (r0 < NP) g_part[((size_t)slot*NP + r0)*LL + col] = acc[mt][nt][u];
                    if (r1 < NP) g_part[((size_t)slot*NP + r1)*LL + col] = acc[mt][nt][2+u];
                }
            }
        }
    }
}

// ================= transpose -> tf32 =================
__global__ void ktrans(const float* __restrict__ in, int R, int C, int Cout,
                       uint32_t* __restrict__ out)
{
    __shared__ float t[32][33];
    int c0 = blockIdx.x*32, r0 = blockIdx.y*32;
    int tx = threadIdx.x, ty = threadIdx.y;
    #pragma unroll
    for (int j = 0; j < 32; j += 8) {
        int r = r0 + ty + j, c = c0 + tx;
        t[ty+j][tx] = (r < R && c < C) ? in[(size_t)r*C + c] : 0.f;
    }
    __syncthreads();
    #pragma unroll
    for (int j = 0; j < 32; j += 8) {
        int c = c0 + ty + j, r = r0 + tx;
        if (c < Cout && r < R) out[(size_t)c*R + r] = f2tf32(t[tx][ty+j]);
    }
}

// batched seq transpose: out[n][d][c] = tf32(seq[n][c][d])
__global__ void ktransB(const float* __restrict__ in, uint32_t* __restrict__ out)
{
    __shared__ float t[32][33];
    int d0 = blockIdx.x*32, c0 = blockIdx.y*32, n = blockIdx.z;
    int tx = threadIdx.x, ty = threadIdx.y;
    const float* inb = in + (size_t)n*CC*DD;
    uint32_t* outb = out + (size_t)n*DD*CC;
    #pragma unroll
    for (int j = 0; j < 32; j += 8)
        t[ty+j][tx] = inb[(size_t)(c0+ty+j)*DD + d0 + tx];
    __syncthreads();
    #pragma unroll
    for (int j = 0; j < 32; j += 8)
        outb[(size_t)(d0+ty+j)*CC + c0 + tx] = f2tf32(t[tx][ty+j]);
}

// ---------------- K1: gather ----------------
__global__ void k_gather(const float* __restrict__ seq, const float* __restrict__ att,
                         const int* __restrict__ ms)
{
    int ne = blockIdx.x;
    int n  = ne / EE;
    int tid = threadIdx.x;
    for (int m = 0; m < MMENT; m++) {
        int pos = ms[ne*MMENT + m] + 1;
        const float* srow = seq + ((size_t)n*CC + pos)*DD;
        float* erow = g_eemb + ((size_t)ne*MMENT + m)*DD;
        for (int d = tid; d < DD; d += blockDim.x) erow[d] = srow[d];
        float* arow = g_eatt + ((size_t)ne*MMENT + m)*CC;
        for (int c = tid; c < CC; c += blockDim.x) {
            float s = 0.f;
            #pragma unroll
            for (int h = 0; h < HH; h++)
                s += att[(((size_t)n*HH + h)*CC + pos)*CC + c];
            arow[c] = s * (1.0f/HH);
        }
    }
    __syncthreads();
    for (int d = tid; d < DD; d += blockDim.x) {
        float x0 = g_eemb[((size_t)ne*MMENT+0)*DD+d];
        float x1 = g_eemb[((size_t)ne*MMENT+1)*DD+d];
        float x2 = g_eemb[((size_t)ne*MMENT+2)*DD+d];
        float x3 = g_eemb[((size_t)ne*MMENT+3)*DD+d];
        float mx = fmaxf(fmaxf(x0,x1), fmaxf(x2,x3));
        float s = expf(x0-mx)+expf(x1-mx)+expf(x2-mx)+expf(x3-mx);
        g_glob[(size_t)ne*DD + d] = mx + logf(s);
    }
}

// ---------------- K3: edge ----------------
__global__ void k_edge(const float* __restrict__ bm)
{
    int idx = blockIdx.x*blockDim.x + threadIdx.x;
    const int total = NN*EE*EE*DD;
    if (idx >= total) return;
    int d = idx % DD;
    int v = (idx / DD) % EE;
    int u = (idx / (DD*EE)) % EE;
    int n = idx / (DD*EE*EE);
    float val = g_A[((size_t)n*EE+u)*DD+d] + g_B[((size_t)n*EE+v)*DD+d] + bm[d];
    g_edge[idx] = fmaxf(val, 0.f);
}

// ---------------- K4: pair attention ----------------
__global__ void k_pair(const int* __restrict__ hts, const int* __restrict__ ms)
{
    int r = blockIdx.x;
    int n = r / PP;
    int h = hts[r*2 + 0];
    int t = hts[r*2 + 1];
    __shared__ int   s_ph[MMENT], s_pt[MMENT];
    __shared__ float s_phatt[MMENT], s_ptatt[MMENT];
    __shared__ float s_red[256];
    int tid = threadIdx.x;
    if (tid < MMENT) {
        s_ph[tid] = ms[((size_t)n*EE+h)*MMENT + tid] + 1;
        s_pt[tid] = ms[((size_t)n*EE+t)*MMENT + tid] + 1;
    }
    __syncthreads();
    if (tid < 2*MMENT) {
        int m2 = tid & (MMENT-1);
        float s = 0.f;
        if (tid < MMENT) {
            for (int m1 = 0; m1 < MMENT; m1++)
                s += g_eatt[((size_t)(n*EE+h)*MMENT+m1)*CC + s_pt[m2]];
            s_phatt[m2] = s * (1.f/MMENT);
        } else {
            for (int m1 = 0; m1 < MMENT; m1++)
                s += g_eatt[((size_t)(n*EE+t)*MMENT+m1)*CC + s_ph[m2]];
            s_ptatt[m2] = s * (1.f/MMENT);
        }
    }
    __syncthreads();
    if (tid == 0) {
        float sh = 1e-5f, st = 1e-5f;
        for (int m = 0; m < MMENT; m++) { sh += s_phatt[m]; st += s_ptatt[m]; }
        float ih = 1.f/sh, it = 1.f/st;
        for (int m = 0; m < MMENT; m++) { s_phatt[m] *= ih; s_ptatt[m] *= it; }
    }
    __syncthreads();
    for (int d = tid; d < DD; d += blockDim.x) {
        float nh = 0.f, nt = 0.f;
        #pragma unroll
        for (int m = 0; m < MMENT; m++) {
            nh += s_ptatt[m]*g_eemb[((size_t)(n*EE+h)*MMENT+m)*DD + d];
            nt += s_phatt[m]*g_eemb[((size_t)(n*EE+t)*MMENT+m)*DD + d];
        }
        uint32_t nh32 = f2tf32(nh), nt32 = f2tf32(nt);
        g_hcat32[(size_t)r*DIM3 + d] = nh32;
        g_tcat32[(size_t)r*DIM3 + d] = nt32;
        g_q32[(size_t)r*DIM2 + d]      = nh32;
        g_q32[(size_t)r*DIM2 + DD + d] = nt32;
    }
    float local = 0.f;
    for (int c = tid; c < CC; c += blockDim.x) {
        float na = 0.f, ta = 0.f;
        #pragma unroll
        for (int m = 0; m < MMENT; m++) {
            na += s_ptatt[m]*g_eatt[((size_t)(n*EE+h)*MMENT+m)*CC + c];
            ta += s_phatt[m]*g_eatt[((size_t)(n*EE+t)*MMENT+m)*CC + c];
        }
        float v = na*ta;
        g_pa[(size_t)r*CC + c] = v;
        local += v;
    }
    s_red[tid] = local;
    __syncthreads();
    for (int off = 128; off > 0; off >>= 1) {
        if (tid < off) s_red[tid] += s_red[tid+off];
        __syncthreads();
    }
    float inv = 1.f/(s_red[0] + 1e-5f);
    for (int c = tid; c < CC; c += blockDim.x)
        g_pa32[(size_t)r*CC + c] = f2tf32(g_pa[(size_t)r*CC + c]*inv);
}

// ---------------- fp32 SGEMM (Wm1+Wm2 merged: z = b*S+s, b selects B/B2) ----------------
__global__ void __launch_bounds__(256) sgemm(
    int M, int Nn, int Kc, int S,
    const float* __restrict__ A, int lda,
    const float* __restrict__ B, const float* __restrict__ B2, int ldb,
    float* __restrict__ part)
{
    int z = blockIdx.z;
    int s = z % S, b = z / S;
    const float* Ab = A + (size_t)s*Kc;
    const float* Bb = ((b && B2) ? B2 : B) + (size_t)s*Kc*ldb;
    int m0 = blockIdx.y*128, n0 = blockIdx.x*128;
    __shared__ float As[8][128];
    __shared__ float Bs[8][128];
    int tid = threadIdx.x;
    int arow = tid >> 1, ak = (tid & 1)*4;
    int bk = tid >> 5,  bn = (tid & 31)*4;
    int tx = tid & 15,  ty = tid >> 4;
    float acc[8][8];
    #pragma unroll
    for (int i = 0; i < 8; i++)
        #pragma unroll
        for (int j = 0; j < 8; j++) acc[i][j] = 0.f;
    for (int k0 = 0; k0 < Kc; k0 += 8) {
        float4 av = make_float4(0.f,0.f,0.f,0.f);
        if (m0 + arow < M)
            av = *(const float4*)(Ab + (size_t)(m0+arow)*lda + k0 + ak);
        float4 bvv = *(const float4*)(Bb + (size_t)(k0+bk)*ldb + n0 + bn);
        __syncthreads();
        As[ak+0][arow] = av.x; As[ak+1][arow] = av.y;
        As[ak+2][arow] = av.z; As[ak+3][arow] = av.w;
        *(float4*)&Bs[bk][bn] = bvv;
        __syncthreads();
        #pragma unroll
        for (int kk = 0; kk < 8; kk++) {
            float a[8], bb[8];
            *(float4*)(a)    = *(const float4*)&As[kk][ty*8];
            *(float4*)(a+4)  = *(const float4*)&As[kk][ty*8+4];
            *(float4*)(bb)   = *(const float4*)&Bs[kk][tx*8];
            *(float4*)(bb+4) = *(const float4*)&Bs[kk][tx*8+4];
            #pragma unroll
            for (int i = 0; i < 8; i++)
                #pragma unroll
                for (int j = 0; j < 8; j++)
                    acc[i][j] += a[i]*bb[j];
        }
    }
    float* pbase = part + ((size_t)z*M)*Nn;
    #pragma unroll
    for (int i = 0; i < 8; i++) {
        int r = m0 + ty*8 + i;
        if (r < M) {
            float* prow = pbase + (size_t)r*Nn + n0 + tx*8;
            *(float4*)(prow)   = make_float4(acc[i][0],acc[i][1],acc[i][2],acc[i][3]);
            *(float4*)(prow+4) = make_float4(acc[i][4],acc[i][5],acc[i][6],acc[i][7]);
        }
    }
}

// reduce + bias + relu; tf32out: dst pointers are uint32_t* (tf32)
__global__ void reduce_ep(const float* __restrict__ part, int S, int Mtot, int Nn,
                          const float* __restrict__ bias, int dorelu, int tf32out,
                          float* __restrict__ dst1, int ld1,
                          float* __restrict__ dst2, int ld2)
{
    int idx = blockIdx.x*blockDim.x + threadIdx.x;
    if (idx >= Mtot*Nn) return;
    int r = idx / Nn, c = idx % Nn;
    float v = 0.f;
    for (int s = 0; s < S; s++)
        v += part[((size_t)s*Mtot + r)*Nn + c];
    if (bias) v += bias[c];
    if (dorelu) v = fmaxf(v, 0.f);
    if (tf32out) {
        uint32_t u = f2tf32(v);
        ((uint32_t*)dst1)[(size_t)r*ld1 + c] = u;
        if (dst2) ((uint32_t*)dst2)[(size_t)r*ld2 + c] = u;
    } else {
        dst1[(size_t)r*ld1 + c] = v;
        if (dst2) dst2[(size_t)r*ld2 + c] = v;
    }
}

// ---------------- K7: score + masked softmax + path ----------------
__global__ void k_scorepath(const int* __restrict__ hts, const float* __restrict__ battp)
{
    int r = blockIdx.x;
    int n = r / PP;
    int h = hts[r*2 + 0];
    int t = hts[r*2 + 1];
    __shared__ float s_q[DIM4];
    __shared__ float s_score[EE];
    __shared__ float s_aw[EE];
    int tid = threadIdx.x;
    for (int i = tid; i < DIM4; i += blockDim.x)
        s_q[i] = g_qW[(size_t)r*DIM4 + i];
    __syncthreads();
    int warp = tid >> 5, lane = tid & 31;
    float batt = battp[0];
    for (int v = warp; v < EE; v += 8) {
        const float* e1 = g_edge + ((size_t)((n*EE+h)*EE + v))*DD;
        const float* e2 = g_edge + ((size_t)((n*EE+v)*EE + t))*DD;
        const float* e3 = g_edge + ((size_t)((n*EE+t)*EE + v))*DD;
        const float* e4 = g_edge + ((size_t)((n*EE+v)*EE + h))*DD;
        float s = 0.f;
        for (int d = lane; d < DD; d += 32)
            s += s_q[d]*e1[d] + s_q[DD+d]*e2[d] + s_q[2*DD+d]*e3[d] + s_q[3*DD+d]*e4[d];
        #pragma unroll
        for (int off = 16; off; off >>= 1)
            s += __shfl_down_sync(0xffffffffu, s, off);
        if (lane == 0) s_score[v] = s + batt;
    }
    __syncthreads();
    if (tid == 0) {
        float mx = -1e38f;
        for (int v = 0; v < EE; v++) {
            float sc = (v == h || v == t) ? NEGV : s_score[v];
            s_score[v] = sc;
            mx = fmaxf(mx, sc);
        }
        float sum = 0.f;
        for (int v = 0; v < EE; v++) {
            float e = expf(s_score[v] - mx);
            s_aw[v] = e;
            sum += e;
        }
        float inv = 1.f/sum;
        for (int v = 0; v < EE; v++) s_aw[v] *= inv;
    }
    __syncthreads();
    for (int idx = tid; idx < DIM4; idx += blockDim.x) {
        int kk = idx / DD, d = idx % DD;
        const float* ep;
        size_t strideV;
        if (kk == 0)      { ep = g_edge + ((size_t)((n*EE+h)*EE))*DD + d;   strideV = DD; }
        else if (kk == 1) { ep = g_edge + ((size_t)(n*EE)*EE + t)*DD + d;   strideV = (size_t)EE*DD; }
        else if (kk == 2) { ep = g_edge + ((size_t)((n*EE+t)*EE))*DD + d;   strideV = DD; }
        else              { ep = g_edge + ((size_t)(n*EE)*EE + h)*DD + d;   strideV = (size_t)EE*DD; }
        float acc = 0.f;
        #pragma unroll 4
        for (int v = 0; v < EE; v++)
            acc += s_aw[v]*ep[(size_t)v*strideV];
        g_praw32[(size_t)r*DIM4 + idx] = f2tf32(acc);
    }
}

__global__ void k_bilred(const float* __restrict__ bbil, float* __restrict__ out)
{
    int idx = blockIdx.x*blockDim.x + threadIdx.x;
    if (idx >= NP*LL) return;
    int r = idx / LL, l = idx % LL;
    float v = bbil[l];
    #pragma unroll
    for (int k = 0; k < 24; k++)
        v += g_part[((size_t)k*NP + r)*LL + l];
    out[idx] = v;
}

// ---------------- launcher ----------------
static void* symaddr(const void* sym)
{
    void* p = nullptr;
    cudaGetSymbolAddress(&p, sym);
    return p;
}

extern "C" void kernel_launch(void* const* d_in, const int* in_sizes, int n_in,
                              void* d_out, int out_size)
{
    const float* seq   = (const float*)d_in[0];
    const float* att   = (const float*)d_in[1];
    const int*   ms    = (const int*)  d_in[2];
    const int*   hts   = (const int*)  d_in[3];
    const float* Wm1   = (const float*)d_in[4];
    const float* Wm2   = (const float*)d_in[5];
    const float* bm    = (const float*)d_in[6];
    const float* Watt  = (const float*)d_in[7];
    const float* batt  = (const float*)d_in[8];
    const float* Wpath = (const float*)d_in[9];
    const float* bpath = (const float*)d_in[10];
    const float* Whead = (const float*)d_in[11];
    const float* bhead = (const float*)d_in[12];
    const float* Wtail = (const float*)d_in[13];
    const float* btail = (const float*)d_in[14];
    const float* Wbil  = (const float*)d_in[15];
    const float* bbil  = (const float*)d_in[16];
    float* out = (float*)d_out;

    float*    glob   = (float*)symaddr(g_glob);
    float*    gA     = (float*)symaddr(g_A);
    float*    gB     = (float*)symaddr(g_B);
    float*    qW     = (float*)symaddr(g_qW);
    float*    hs     = (float*)symaddr(g_hs);
    float*    ts     = (float*)symaddr(g_ts);
    float*    part   = (float*)symaddr(g_part);
    uint32_t* pa32   = (uint32_t*)symaddr(g_pa32);
    uint32_t* seqT32 = (uint32_t*)symaddr(g_seqT32);
    uint32_t* q32    = (uint32_t*)symaddr(g_q32);
    uint32_t* hcat32 = (uint32_t*)symaddr(g_hcat32);
    uint32_t* tcat32 = (uint32_t*)symaddr(g_tcat32);
    uint32_t* praw32 = (uint32_t*)symaddr(g_praw32);
    uint32_t* wTatt  = (uint32_t*)symaddr(g_wT_att32);
    uint32_t* wTpath = (uint32_t*)symaddr(g_wT_path32);
    uint32_t* wThead = (uint32_t*)symaddr(g_wT_head32);
    uint32_t* wTtail = (uint32_t*)symaddr(g_wT_tail32);
    uint32_t* wTbil  = (uint32_t*)symaddr(g_wT_bil32);

    const int SMEM_WG = 65536;
    const int SMEM_WB = 98304;
    cudaFuncSetAttribute(wgemm, cudaFuncAttributeMaxDynamicSharedMemorySize, SMEM_WG);
    cudaFuncSetAttribute(wbil,  cudaFuncAttributeMaxDynamicSharedMemorySize, SMEM_WB);

    // --- ordered so launch index 3 (ncu capture slot) is the qW wgemm ---
    k_gather<<<NN*EE, 256>>>(seq, att, ms);                                        // 0
    k_pair<<<NP, 256>>>(hts, ms);                                                  // 1
    ktrans<<<dim3(DIM4/32, DIM2/32), dim3(32,8)>>>(Watt, DIM2, DIM4, DIM4, wTatt); // 2
    // 3: qW = q @ Watt (tf32 mma + cp.async) <-- ncu profiles this
    wgemm<<<dim3(24,12,1), 256, SMEM_WG>>>(NP, 48, 1,
        q32, DIM2, 0, wTatt, DIM2, 0, nullptr, nullptr,
        qW, DIM4, 0, nullptr, nullptr, 0, 0,
        nullptr, nullptr, 0, 0, nullptr, 0, 0);

    // Wm1+Wm2 merged (fp32, split-K 12 each, z = b*12+s)
    sgemm<<<dim3(6,1,24), 256>>>(NN*EE, DD, 64, 12, glob, DD, Wm1, Wm2, DD, part);
    reduce_ep<<<(NN*EE*DD+255)/256, 256>>>(part, 12, NN*EE, DD, nullptr, 0, 0,
                                           gA, DD, nullptr, 0);
    reduce_ep<<<(NN*EE*DD+255)/256, 256>>>(part + (size_t)12*NN*EE*DD, 12, NN*EE, DD,
                                           nullptr, 0, 0, gB, DD, nullptr, 0);
    k_edge<<<(NN*EE*EE*DD+255)/256, 256>>>(bm);

    // rs = pa @ seq (tf32 mma, per-doc batch, direct dual tf32 epilogue)
    ktransB<<<dim3(DD/32, CC/32, NN), dim3(32,8)>>>(seq, seqT32);
    wgemm<<<dim3(6,3,NN), 256, SMEM_WG>>>(PP, 16, 1,
        pa32, CC, (long long)PP*CC, seqT32, CC, (long long)DD*CC, nullptr, nullptr,
        (float*)(hcat32 + DD), DIM3, (long long)PP*DIM3, nullptr,
        (float*)(tcat32 + DD), DIM3, (long long)PP*DIM3,
        nullptr, nullptr, 0, 1, nullptr, 0, 0);

    // score/softmax/path (writes praw32 tf32)
    k_scorepath<<<NP, 256>>>(hts, batt);

    // path = relu(pathraw @ Wpath + bpath) -> tf32 into hcat32/tcat32 [2D,3D)
    ktrans<<<dim3(DD/32, DIM4/32), dim3(32,8)>>>(Wpath, DIM4, DD, DD, wTpath);
    wgemm<<<dim3(6,12,2), 256, SMEM_WG>>>(NP, 48, 2,
        praw32, DIM4, 0, wTpath, DIM4, 0, nullptr, nullptr,
        nullptr, 0, 0, nullptr, nullptr, 0, 0,
        nullptr, nullptr, 0, 0, part, NP, DD);
    reduce_ep<<<(NP*DD+255)/256, 256>>>(part, 2, NP, DD, bpath, 1, 1,
                                        (float*)(hcat32 + 2*DD), DIM3,
                                        (float*)(tcat32 + 2*DD), DIM3);

    // hs / ts projections — merged, Sr=1, direct epilogue (per-b bias/dst)
    ktrans<<<dim3(DD/32, DIM3/32), dim3(32,8)>>>(Whead, DIM3, DD, DD, wThead);
    ktrans<<<dim3(DD/32, DIM3/32), dim3(32,8)>>>(Wtail, DIM3, DD, DD, wTtail);
    wgemm<<<dim3(6,12,2), 256, SMEM_WG>>>(NP, 72, 1,
        hcat32, DIM3, 0, wThead, DIM3, 0, tcat32, wTtail,
        hs, DD, 0, ts, nullptr, 0, 0,
        bhead, btail, 1, 0, nullptr, 0, 0);

    // bilinear head v2: grid (12, 24), 2 CTAs/SM, partial slots 0..23
    ktrans<<<dim3(4, KBIL/32), dim3(32,8)>>>(Wbil, KBIL, LL, 128, wTbil);
    wbil<<<dim3(12,24), 256, SMEM_WB>>>(wTbil);
    k_bilred<<<(NP*LL+255)/256, 256>>>(bbil, out);
}